// round 9
// baseline (speedup 1.0000x reference)
#include <cuda_runtime.h>
#include <cuda_bf16.h>
#include <cuda_fp16.h>
#include <cstdint>
#include <cstddef>

#define BATCH 8
#define TENC 2048
#define TDEC 512
#define DIM  1024
#define NEG_BIG 1e20f

// ---------------------------------------------------------------------------
// Scratch (static device arrays — no allocation allowed)
// ---------------------------------------------------------------------------
__device__ __nv_bfloat16 g_eh[(size_t)BATCH * TENC * DIM];   // enc hi bf16 [b][t][d]
__device__ __nv_bfloat16 g_el[(size_t)BATCH * TENC * DIM];   // enc lo bf16
__device__ __half        g_ef[(size_t)BATCH * TENC * DIM];   // enc fp16 (gemm2)
__device__ __nv_bfloat16 g_dh[(size_t)BATCH * TDEC * DIM];   // dec hi bf16 [b][u][d]
__device__ __nv_bfloat16 g_dl[(size_t)BATCH * TDEC * DIM];   // dec lo bf16
__device__ __half        g_ph[(size_t)BATCH * TENC * TDEC];  // scores hi fp16 [b][t][u]
__device__ __half        g_pl[(size_t)BATCH * TENC * TDEC];  // scores lo fp16
// softmax partials
__device__ float g_cm[BATCH * 8 * TDEC];
__device__ float g_cs[BATCH * 8 * TDEC];

// ---------------------------------------------------------------------------
// helpers
// ---------------------------------------------------------------------------
__device__ __forceinline__ uint32_t smem_u32(const void* p) {
    return (uint32_t)__cvta_generic_to_shared(p);
}
__device__ __forceinline__ void cpa16(uint32_t s, const void* g) {
    asm volatile("cp.async.cg.shared.global [%0], [%1], 16;\n" :: "r"(s), "l"(g));
}
__device__ __forceinline__ void cpa_commit() {
    asm volatile("cp.async.commit_group;\n");
}
__device__ __forceinline__ void cpa_wait2() { asm volatile("cp.async.wait_group 2;\n"); }
__device__ __forceinline__ void cpa_wait1() { asm volatile("cp.async.wait_group 1;\n"); }
__device__ __forceinline__ void cpa_wait0() { asm volatile("cp.async.wait_group 0;\n"); }
__device__ __forceinline__ void ldsm4(uint32_t* r, uint32_t a) {
    asm volatile("ldmatrix.sync.aligned.m8n8.x4.shared.b16 {%0,%1,%2,%3}, [%4];\n"
                 : "=r"(r[0]), "=r"(r[1]), "=r"(r[2]), "=r"(r[3]) : "r"(a));
}
__device__ __forceinline__ void ldsm4t(uint32_t* r, uint32_t a) {
    asm volatile("ldmatrix.sync.aligned.m8n8.x4.trans.shared.b16 {%0,%1,%2,%3}, [%4];\n"
                 : "=r"(r[0]), "=r"(r[1]), "=r"(r[2]), "=r"(r[3]) : "r"(a));
}
__device__ __forceinline__ void mma_bf16(float* c, const uint32_t* a, uint32_t b0, uint32_t b1) {
    asm volatile(
        "mma.sync.aligned.m16n8k16.row.col.f32.bf16.bf16.f32 "
        "{%0,%1,%2,%3},{%4,%5,%6,%7},{%8,%9},{%0,%1,%2,%3};\n"
        : "+f"(c[0]), "+f"(c[1]), "+f"(c[2]), "+f"(c[3])
        : "r"(a[0]), "r"(a[1]), "r"(a[2]), "r"(a[3]), "r"(b0), "r"(b1));
}
__device__ __forceinline__ void mma_fp16(float* c, const uint32_t* a, uint32_t b0, uint32_t b1) {
    asm volatile(
        "mma.sync.aligned.m16n8k16.row.col.f32.f16.f16.f32 "
        "{%0,%1,%2,%3},{%4,%5,%6,%7},{%8,%9},{%0,%1,%2,%3};\n"
        : "+f"(c[0]), "+f"(c[1]), "+f"(c[2]), "+f"(c[3])
        : "r"(a[0]), "r"(a[1]), "r"(a[2]), "r"(a[3]), "r"(b0), "r"(b1));
}

// ---------------------------------------------------------------------------
// enc split: f32 -> bf16 hi/lo + fp16 copy
// ---------------------------------------------------------------------------
__global__ void split_enc_kernel(const float* __restrict__ x)
{
    const int n4 = (int)((size_t)BATCH * TENC * DIM / 4);
    int stride = gridDim.x * blockDim.x;
    for (int i = blockIdx.x * blockDim.x + threadIdx.x; i < n4; i += stride) {
        float4 v = ((const float4*)x)[i];
        __nv_bfloat16 h0 = __float2bfloat16(v.x), h1 = __float2bfloat16(v.y);
        __nv_bfloat16 h2 = __float2bfloat16(v.z), h3 = __float2bfloat16(v.w);
        __nv_bfloat16 l0 = __float2bfloat16(v.x - __bfloat162float(h0));
        __nv_bfloat16 l1 = __float2bfloat16(v.y - __bfloat162float(h1));
        __nv_bfloat16 l2 = __float2bfloat16(v.z - __bfloat162float(h2));
        __nv_bfloat16 l3 = __float2bfloat16(v.w - __bfloat162float(h3));
        __nv_bfloat162 hA = {h0, h1}, hB = {h2, h3}, lA = {l0, l1}, lB = {l2, l3};
        uint2 hv = {*(uint32_t*)&hA, *(uint32_t*)&hB};
        uint2 lv = {*(uint32_t*)&lA, *(uint32_t*)&lB};
        ((uint2*)g_eh)[i] = hv;
        ((uint2*)g_el)[i] = lv;
        __half2 fA = {__float2half(v.x), __float2half(v.y)};
        __half2 fB = {__float2half(v.z), __float2half(v.w)};
        uint2 fv = {*(uint32_t*)&fA, *(uint32_t*)&fB};
        ((uint2*)g_ef)[i] = fv;
    }
}

// dec split: bf16 hi/lo only
__global__ void split_dec_kernel(const float* __restrict__ x)
{
    const int n4 = (int)((size_t)BATCH * TDEC * DIM / 4);
    int stride = gridDim.x * blockDim.x;
    for (int i = blockIdx.x * blockDim.x + threadIdx.x; i < n4; i += stride) {
        float4 v = ((const float4*)x)[i];
        __nv_bfloat16 h0 = __float2bfloat16(v.x), h1 = __float2bfloat16(v.y);
        __nv_bfloat16 h2 = __float2bfloat16(v.z), h3 = __float2bfloat16(v.w);
        __nv_bfloat16 l0 = __float2bfloat16(v.x - __bfloat162float(h0));
        __nv_bfloat16 l1 = __float2bfloat16(v.y - __bfloat162float(h1));
        __nv_bfloat16 l2 = __float2bfloat16(v.z - __bfloat162float(h2));
        __nv_bfloat16 l3 = __float2bfloat16(v.w - __bfloat162float(h3));
        __nv_bfloat162 hA = {h0, h1}, hB = {h2, h3}, lA = {l0, l1}, lB = {l2, l3};
        uint2 hv = {*(uint32_t*)&hA, *(uint32_t*)&hB};
        uint2 lv = {*(uint32_t*)&lA, *(uint32_t*)&lB};
        ((uint2*)g_dh)[i] = hv;
        ((uint2*)g_dl)[i] = lv;
    }
}

// ---------------------------------------------------------------------------
// GEMM1: S[b,t,u] = sum_d enc[t,d]*dec[u,d] - (1-mask[t])*NEG_BIG
// bf16x3 mma.sync. BM=128(t), BN=64(u), BK=32. 8 warps (2m x 4n), 64x16/warp.
// 1024 CTAs -> 6.92 waves (98.9% tail efficiency). 4-deep cp.async ring.
// ---------------------------------------------------------------------------
#define G1_AB    10240            // A array: 128 rows * 80 B
#define G1_BB    5120             // B array:  64 rows * 80 B
#define G1_STAGE (2 * G1_AB + 2 * G1_BB)   // Ah, Al, Bh, Bl = 30720
#define G1_DYN   (4 * G1_STAGE + 1024)

__global__ __launch_bounds__(256, 1) void gemm1_kernel(
    const int* __restrict__ enc_mask, float* __restrict__ S)
{
    extern __shared__ __align__(16) uint8_t dynsm[];
    const uint32_t dynb = (smem_u32(dynsm) + 1023u) & ~1023u;

    const int b  = blockIdx.z;
    const int m0 = blockIdx.y * 128;   // t
    const int n0 = blockIdx.x * 64;    // u

    const __nv_bfloat16* Ah = g_eh + (size_t)b * TENC * DIM;
    const __nv_bfloat16* Al = g_el + (size_t)b * TENC * DIM;
    const __nv_bfloat16* Bh = g_dh + (size_t)b * TDEC * DIM;
    const __nv_bfloat16* Bl = g_dl + (size_t)b * TDEC * DIM;
    const int* mk = enc_mask + b * TENC;
    float* Sp = S + (size_t)b * TENC * TDEC;

    const int tid  = threadIdx.x;
    const int lane = tid & 31;
    const int wid  = tid >> 5;
    const int m_off = (wid & 1) * 64;
    const int n_off = (wid >> 1) * 16;

    const int lrow = tid >> 2;        // 0..63
    const int lc   = tid & 3;

    const uint32_t aBase = (uint32_t)((m_off + (lane & 15)) * 80 + (lane >> 4) * 16);
    const uint32_t bBase = (uint32_t)((n_off + (lane & 7) + ((lane >> 4) << 3)) * 80
                                      + ((lane >> 3) & 1) * 16);

    float acc[4][2][4];
    #pragma unroll
    for (int i = 0; i < 4; i++)
        #pragma unroll
        for (int j = 0; j < 2; j++)
            #pragma unroll
            for (int k = 0; k < 4; k++) acc[i][j][k] = 0.f;

    const int NST = DIM / 32;

    auto load_stage = [&](int s) {
        const int k0 = s * 32;
        const uint32_t sb = dynb + (uint32_t)(s & 3) * G1_STAGE;
        #pragma unroll
        for (int j = 0; j < 2; j++) {
            int row = lrow + j * 64;
            uint32_t so = (uint32_t)(row * 80 + lc * 16);
            size_t goA = (size_t)(m0 + row) * DIM + k0 + lc * 8;
            cpa16(sb + so,         Ah + goA);
            cpa16(sb + G1_AB + so, Al + goA);
        }
        {
            uint32_t so = (uint32_t)(lrow * 80 + lc * 16);
            size_t goB = (size_t)(n0 + lrow) * DIM + k0 + lc * 8;
            cpa16(sb + 2 * G1_AB + so,         Bh + goB);
            cpa16(sb + 2 * G1_AB + G1_BB + so, Bl + goB);
        }
        cpa_commit();
    };

    load_stage(0);
    load_stage(1);
    load_stage(2);

    for (int s = 0; s < NST; s++) {
        if (s < NST - 2) cpa_wait2();
        else if (s == NST - 2) cpa_wait1();
        else cpa_wait0();
        __syncthreads();

        const uint32_t bAh = dynb + (uint32_t)(s & 3) * G1_STAGE;
        const uint32_t bAl = bAh + G1_AB;
        const uint32_t bBh = bAh + 2 * G1_AB;
        const uint32_t bBl = bBh + G1_BB;

        #pragma unroll
        for (int ks = 0; ks < 2; ks++) {
            uint32_t koff = (uint32_t)(ks * 32);
            uint32_t ah[4][4], bh[4];
            #pragma unroll
            for (int im = 0; im < 4; im++) ldsm4(ah[im], bAh + aBase + im * 1280 + koff);
            ldsm4(bh, bBh + bBase + koff);
            #pragma unroll
            for (int im = 0; im < 4; im++)
                #pragma unroll
                for (int in = 0; in < 2; in++)
                    mma_bf16(acc[im][in], ah[im], bh[in * 2], bh[in * 2 + 1]);

            uint32_t bl[4];
            ldsm4(bl, bBl + bBase + koff);
            #pragma unroll
            for (int im = 0; im < 4; im++)
                #pragma unroll
                for (int in = 0; in < 2; in++)
                    mma_bf16(acc[im][in], ah[im], bl[in * 2], bl[in * 2 + 1]);

            uint32_t al[4][4];
            #pragma unroll
            for (int im = 0; im < 4; im++) ldsm4(al[im], bAl + aBase + im * 1280 + koff);
            #pragma unroll
            for (int im = 0; im < 4; im++)
                #pragma unroll
                for (int in = 0; in < 2; in++)
                    mma_bf16(acc[im][in], al[im], bh[in * 2], bh[in * 2 + 1]);
        }
        if (s + 3 < NST) load_stage(s + 3);
    }

    #pragma unroll
    for (int im = 0; im < 4; im++) {
        int tr = m0 + m_off + im * 16 + (lane >> 2);
        float bias0 = (1.0f - (float)mk[tr])     * NEG_BIG;
        float bias1 = (1.0f - (float)mk[tr + 8]) * NEG_BIG;
        #pragma unroll
        for (int in = 0; in < 2; in++) {
            int col = n0 + n_off + in * 8 + (lane & 3) * 2;
            float2 v0 = {acc[im][in][0] - bias0, acc[im][in][1] - bias0};
            float2 v1 = {acc[im][in][2] - bias1, acc[im][in][3] - bias1};
            *(float2*)&Sp[(size_t)tr * TDEC + col]       = v0;
            *(float2*)&Sp[(size_t)(tr + 8) * TDEC + col] = v1;
        }
    }
}

// ---------------------------------------------------------------------------
// Softmax, 2 kernels.
// ---------------------------------------------------------------------------
__global__ __launch_bounds__(256) void softmaxA_kernel(const float* __restrict__ S)
{
    const int b  = blockIdx.z;
    const int c  = blockIdx.y;            // 0..7
    const int u0 = blockIdx.x * 16;
    const int ux = threadIdx.x;           // 0..15
    const int tz = threadIdx.y;           // 0..15
    const int t0 = c * 256;
    const float* col = S + (size_t)b * TENC * TDEC + u0 + ux;

    float x[16];
    #pragma unroll
    for (int i = 0; i < 16; i++)
        x[i] = col[(size_t)(t0 + tz + i * 16) * TDEC];

    float m = x[0];
    #pragma unroll
    for (int i = 1; i < 16; i++) m = fmaxf(m, x[i]);

    __shared__ float red[16][17];
    red[tz][ux] = m;
    __syncthreads();
    #pragma unroll
    for (int s = 8; s > 0; s >>= 1) {
        if (tz < s) red[tz][ux] = fmaxf(red[tz][ux], red[tz + s][ux]);
        __syncthreads();
    }
    m = red[0][ux];
    __syncthreads();

    float sum = 0.f;
    #pragma unroll
    for (int i = 0; i < 16; i++) sum += __expf(x[i] - m);
    red[tz][ux] = sum;
    __syncthreads();
    #pragma unroll
    for (int s = 8; s > 0; s >>= 1) {
        if (tz < s) red[tz][ux] += red[tz + s][ux];
        __syncthreads();
    }
    if (tz == 0) {
        g_cm[(b * 8 + c) * TDEC + u0 + ux] = m;
        g_cs[(b * 8 + c) * TDEC + u0 + ux] = red[0][ux];
    }
}

__global__ __launch_bounds__(256) void softmaxC_kernel(float* __restrict__ S)
{
    const int b  = blockIdx.z;
    const int c  = blockIdx.y;
    const int u0 = blockIdx.x * 16;
    const int ux = threadIdx.x;
    const int tz = threadIdx.y;
    const int t0 = c * 256;
    const int u  = u0 + ux;

    float M = -3.4e38f;
    #pragma unroll
    for (int cc = 0; cc < 8; cc++) M = fmaxf(M, g_cm[(b * 8 + cc) * TDEC + u]);
    float Ssum = 0.f;
    #pragma unroll
    for (int cc = 0; cc < 8; cc++)
        Ssum += g_cs[(b * 8 + cc) * TDEC + u] * __expf(g_cm[(b * 8 + cc) * TDEC + u] - M);
    const float inv = 1.0f / Ssum;

    size_t base = (size_t)b * TENC * TDEC + u;
    float* Sp = S + base;
    __half* ph = g_ph + base;
    __half* pl = g_pl + base;

    #pragma unroll
    for (int i = 0; i < 16; i++) {
        size_t idx = (size_t)(t0 + tz + i * 16) * TDEC;
        float p = __expf(Sp[idx] - M) * inv;
        Sp[idx] = p;
        __half h = __float2half(p);
        ph[idx] = h;
        pl[idx] = __float2half(p - __half2float(h));
    }
}

// ---------------------------------------------------------------------------
// GEMM2 (fp16, 2 passes): ctx[b,u,d] = sum_t p[t,u] * enc[t,d]
// BM=64(u), BN=64(d), BK=32(t). 128 threads (4 warps 2x2, 32x32/warp).
// 1024 CTAs -> 6.92 waves. smem row stride 144 B (conflict-free trans ldsm).
// ---------------------------------------------------------------------------
#define G2_BUF   4608             // 32 rows * 144 B
#define G2_STAGE (3 * G2_BUF)     // Ph, Pl, Ef
#define G2_DYN   (4 * G2_STAGE + 1024)

__global__ __launch_bounds__(128, 1) void gemm2_kernel(float* __restrict__ ctx)
{
    extern __shared__ __align__(16) uint8_t dynsm[];
    const uint32_t dynb = (smem_u32(dynsm) + 1023u) & ~1023u;

    const int b  = blockIdx.z;
    const int u0 = blockIdx.y * 64;
    const int d0 = blockIdx.x * 64;

    const __half* Ph = g_ph + (size_t)b * TENC * TDEC;
    const __half* Pl = g_pl + (size_t)b * TENC * TDEC;
    const __half* Ef = g_ef + (size_t)b * TENC * DIM;
    float* C = ctx + (size_t)b * TDEC * DIM;

    const int tid  = threadIdx.x;
    const int lane = tid & 31;
    const int wid  = tid >> 5;
    const int m_off = (wid & 1) * 32;   // u
    const int n_off = (wid >> 1) * 32;  // d

    const int lrow = tid >> 3;   // 0..15 (+16)
    const int lc   = tid & 7;

    const uint32_t aBase = (uint32_t)(((lane & 7) + ((lane >> 4) << 3)) * 144
                                      + (m_off + ((lane >> 3) & 1) * 8) * 2);
    const uint32_t bBase = (uint32_t)(((lane & 7) + (((lane >> 3) & 1) << 3)) * 144
                                      + (n_off + (lane >> 4) * 8) * 2);

    float acc[2][4][4];
    #pragma unroll
    for (int i = 0; i < 2; i++)
        #pragma unroll
        for (int j = 0; j < 4; j++)
            #pragma unroll
            for (int k = 0; k < 4; k++) acc[i][j][k] = 0.f;

    const int NST = TENC / 32;

    auto load_stage = [&](int s) {
        const int k0 = s * 32;
        const uint32_t sb = dynb + (uint32_t)(s & 3) * G2_STAGE;
        #pragma unroll
        for (int j = 0; j < 2; j++) {
            int row = lrow + j * 16;
            uint32_t so = (uint32_t)(row * 144 + lc * 16);
            size_t goP = (size_t)(k0 + row) * TDEC + u0 + lc * 8;
            size_t goE = (size_t)(k0 + row) * DIM + d0 + lc * 8;
            cpa16(sb + so,              Ph + goP);
            cpa16(sb + G2_BUF + so,     Pl + goP);
            cpa16(sb + 2 * G2_BUF + so, Ef + goE);
        }
        cpa_commit();
    };

    load_stage(0);
    load_stage(1);
    load_stage(2);

    for (int s = 0; s < NST; s++) {
        if (s < NST - 2) cpa_wait2();
        else if (s == NST - 2) cpa_wait1();
        else cpa_wait0();
        __syncthreads();

        const uint32_t bPh = dynb + (uint32_t)(s & 3) * G2_STAGE;
        const uint32_t bPl = bPh + G2_BUF;
        const uint32_t bEf = bPh + 2 * G2_BUF;

        #pragma unroll
        for (int ks = 0; ks < 2; ks++) {
            uint32_t koff = (uint32_t)(ks * 16 * 144);
            uint32_t ah[2][4], bh[2][4];
            #pragma unroll
            for (int im = 0; im < 2; im++) ldsm4t(ah[im], bPh + aBase + im * 32 + koff);
            #pragma unroll
            for (int p = 0; p < 2; p++)   ldsm4t(bh[p], bEf + bBase + p * 32 + koff);
            #pragma unroll
            for (int im = 0; im < 2; im++)
                #pragma unroll
                for (int in = 0; in < 4; in++)
                    mma_fp16(acc[im][in], ah[im], bh[in >> 1][(in & 1) * 2], bh[in >> 1][(in & 1) * 2 + 1]);

            uint32_t al[2][4];
            #pragma unroll
            for (int im = 0; im < 2; im++) ldsm4t(al[im], bPl + aBase + im * 32 + koff);
            #pragma unroll
            for (int im = 0; im < 2; im++)
                #pragma unroll
                for (int in = 0; in < 4; in++)
                    mma_fp16(acc[im][in], al[im], bh[in >> 1][(in & 1) * 2], bh[in >> 1][(in & 1) * 2 + 1]);
        }
        if (s + 3 < NST) load_stage(s + 3);
    }

    #pragma unroll
    for (int im = 0; im < 2; im++) {
        int ur = u0 + m_off + im * 16 + (lane >> 2);
        #pragma unroll
        for (int in = 0; in < 4; in++) {
            int col = d0 + n_off + in * 8 + (lane & 3) * 2;
            float2 v0 = {acc[im][in][0], acc[im][in][1]};
            float2 v1 = {acc[im][in][2], acc[im][in][3]};
            *(float2*)&C[(size_t)ur * DIM + col]       = v0;
            *(float2*)&C[(size_t)(ur + 8) * DIM + col] = v1;
        }
    }
}

// ---------------------------------------------------------------------------
extern "C" void kernel_launch(void* const* d_in, const int* in_sizes, int n_in,
                              void* d_out, int out_size)
{
    const float* enc      = (const float*)d_in[0];
    const int*   enc_mask = (const int*)  d_in[1];
    const float* dec      = (const float*)d_in[2];

    float* ctx = (float*)d_out;                      // [B, TDEC, DIM]
    float* S   = ctx + (size_t)BATCH * TDEC * DIM;   // [B, TENC, TDEC]

    cudaFuncSetAttribute(gemm1_kernel, cudaFuncAttributeMaxDynamicSharedMemorySize, G1_DYN);
    cudaFuncSetAttribute(gemm2_kernel, cudaFuncAttributeMaxDynamicSharedMemorySize, G2_DYN);

    split_enc_kernel<<<1024, 256>>>(enc);
    split_dec_kernel<<<512, 256>>>(dec);

    gemm1_kernel<<<dim3(TDEC / 64, TENC / 128, BATCH), 256, G1_DYN>>>(enc_mask, S);

    softmaxA_kernel<<<dim3(TDEC / 16, 8, BATCH), dim3(16, 16)>>>(S);
    softmaxC_kernel<<<dim3(TDEC / 16, 8, BATCH), dim3(16, 16)>>>(S);

    gemm2_kernel<<<dim3(DIM / 64, TDEC / 64, BATCH), 128, G2_DYN>>>(ctx);
}

// round 10
// speedup vs baseline: 1.2036x; 1.2036x over previous
#include <cuda_runtime.h>
#include <cuda_bf16.h>
#include <cuda_fp16.h>
#include <cstdint>
#include <cstddef>

#define BATCH 8
#define TENC 2048
#define TDEC 512
#define DIM  1024
#define NEG_BIG 1e20f

// ---------------------------------------------------------------------------
// Scratch (static device arrays — no allocation allowed)
// ---------------------------------------------------------------------------
__device__ __nv_bfloat16 g_eh[(size_t)BATCH * TENC * DIM];   // enc hi bf16 [b][t][d]
__device__ __nv_bfloat16 g_el[(size_t)BATCH * TENC * DIM];   // enc lo bf16
__device__ __half        g_ef[(size_t)BATCH * TENC * DIM];   // enc fp16 (gemm2)
__device__ __nv_bfloat16 g_dh[(size_t)BATCH * TDEC * DIM];   // dec hi bf16 [b][u][d]
__device__ __nv_bfloat16 g_dl[(size_t)BATCH * TDEC * DIM];   // dec lo bf16
__device__ __half        g_ph[(size_t)BATCH * TENC * TDEC];  // scores fp16 [b][t][u]
// softmax partials
__device__ float g_cm[BATCH * 8 * TDEC];
__device__ float g_cs[BATCH * 8 * TDEC];

// ---------------------------------------------------------------------------
// helpers
// ---------------------------------------------------------------------------
__device__ __forceinline__ uint32_t smem_u32(const void* p) {
    return (uint32_t)__cvta_generic_to_shared(p);
}
__device__ __forceinline__ void cpa16(uint32_t s, const void* g) {
    asm volatile("cp.async.cg.shared.global [%0], [%1], 16;\n" :: "r"(s), "l"(g));
}
__device__ __forceinline__ void cpa_commit() {
    asm volatile("cp.async.commit_group;\n");
}
__device__ __forceinline__ void cpa_wait2() { asm volatile("cp.async.wait_group 2;\n"); }
__device__ __forceinline__ void cpa_wait1() { asm volatile("cp.async.wait_group 1;\n"); }
__device__ __forceinline__ void cpa_wait0() { asm volatile("cp.async.wait_group 0;\n"); }
__device__ __forceinline__ void ldsm4(uint32_t* r, uint32_t a) {
    asm volatile("ldmatrix.sync.aligned.m8n8.x4.shared.b16 {%0,%1,%2,%3}, [%4];\n"
                 : "=r"(r[0]), "=r"(r[1]), "=r"(r[2]), "=r"(r[3]) : "r"(a));
}
__device__ __forceinline__ void ldsm4t(uint32_t* r, uint32_t a) {
    asm volatile("ldmatrix.sync.aligned.m8n8.x4.trans.shared.b16 {%0,%1,%2,%3}, [%4];\n"
                 : "=r"(r[0]), "=r"(r[1]), "=r"(r[2]), "=r"(r[3]) : "r"(a));
}
__device__ __forceinline__ void mma_bf16(float* c, const uint32_t* a, uint32_t b0, uint32_t b1) {
    asm volatile(
        "mma.sync.aligned.m16n8k16.row.col.f32.bf16.bf16.f32 "
        "{%0,%1,%2,%3},{%4,%5,%6,%7},{%8,%9},{%0,%1,%2,%3};\n"
        : "+f"(c[0]), "+f"(c[1]), "+f"(c[2]), "+f"(c[3])
        : "r"(a[0]), "r"(a[1]), "r"(a[2]), "r"(a[3]), "r"(b0), "r"(b1));
}
__device__ __forceinline__ void mma_fp16(float* c, const uint32_t* a, uint32_t b0, uint32_t b1) {
    asm volatile(
        "mma.sync.aligned.m16n8k16.row.col.f32.f16.f16.f32 "
        "{%0,%1,%2,%3},{%4,%5,%6,%7},{%8,%9},{%0,%1,%2,%3};\n"
        : "+f"(c[0]), "+f"(c[1]), "+f"(c[2]), "+f"(c[3])
        : "r"(a[0]), "r"(a[1]), "r"(a[2]), "r"(a[3]), "r"(b0), "r"(b1));
}

// ---------------------------------------------------------------------------
// enc split: f32 -> bf16 hi/lo + fp16 copy
// ---------------------------------------------------------------------------
__global__ void split_enc_kernel(const float* __restrict__ x)
{
    const int n4 = (int)((size_t)BATCH * TENC * DIM / 4);
    int stride = gridDim.x * blockDim.x;
    for (int i = blockIdx.x * blockDim.x + threadIdx.x; i < n4; i += stride) {
        float4 v = ((const float4*)x)[i];
        __nv_bfloat16 h0 = __float2bfloat16(v.x), h1 = __float2bfloat16(v.y);
        __nv_bfloat16 h2 = __float2bfloat16(v.z), h3 = __float2bfloat16(v.w);
        __nv_bfloat16 l0 = __float2bfloat16(v.x - __bfloat162float(h0));
        __nv_bfloat16 l1 = __float2bfloat16(v.y - __bfloat162float(h1));
        __nv_bfloat16 l2 = __float2bfloat16(v.z - __bfloat162float(h2));
        __nv_bfloat16 l3 = __float2bfloat16(v.w - __bfloat162float(h3));
        __nv_bfloat162 hA = {h0, h1}, hB = {h2, h3}, lA = {l0, l1}, lB = {l2, l3};
        uint2 hv = {*(uint32_t*)&hA, *(uint32_t*)&hB};
        uint2 lv = {*(uint32_t*)&lA, *(uint32_t*)&lB};
        ((uint2*)g_eh)[i] = hv;
        ((uint2*)g_el)[i] = lv;
        __half2 fA = {__float2half(v.x), __float2half(v.y)};
        __half2 fB = {__float2half(v.z), __float2half(v.w)};
        uint2 fv = {*(uint32_t*)&fA, *(uint32_t*)&fB};
        ((uint2*)g_ef)[i] = fv;
    }
}

// dec split: bf16 hi/lo only
__global__ void split_dec_kernel(const float* __restrict__ x)
{
    const int n4 = (int)((size_t)BATCH * TDEC * DIM / 4);
    int stride = gridDim.x * blockDim.x;
    for (int i = blockIdx.x * blockDim.x + threadIdx.x; i < n4; i += stride) {
        float4 v = ((const float4*)x)[i];
        __nv_bfloat16 h0 = __float2bfloat16(v.x), h1 = __float2bfloat16(v.y);
        __nv_bfloat16 h2 = __float2bfloat16(v.z), h3 = __float2bfloat16(v.w);
        __nv_bfloat16 l0 = __float2bfloat16(v.x - __bfloat162float(h0));
        __nv_bfloat16 l1 = __float2bfloat16(v.y - __bfloat162float(h1));
        __nv_bfloat16 l2 = __float2bfloat16(v.z - __bfloat162float(h2));
        __nv_bfloat16 l3 = __float2bfloat16(v.w - __bfloat162float(h3));
        __nv_bfloat162 hA = {h0, h1}, hB = {h2, h3}, lA = {l0, l1}, lB = {l2, l3};
        uint2 hv = {*(uint32_t*)&hA, *(uint32_t*)&hB};
        uint2 lv = {*(uint32_t*)&lA, *(uint32_t*)&lB};
        ((uint2*)g_dh)[i] = hv;
        ((uint2*)g_dl)[i] = lv;
    }
}

// ---------------------------------------------------------------------------
// GEMM1: S[b,t,u] = sum_d enc[t,d]*dec[u,d] - (1-mask[t])*NEG_BIG
// bf16x3 mma.sync. BM=BN=128, BK=32, 8 warps, 4-deep cp.async ring, 1 CTA/SM.
// ---------------------------------------------------------------------------
#define G1_BUF   10240
#define G1_STAGE (4 * G1_BUF)
#define G1_DYN   (4 * G1_STAGE + 1024)

__global__ __launch_bounds__(256, 1) void gemm1_kernel(
    const int* __restrict__ enc_mask, float* __restrict__ S)
{
    extern __shared__ __align__(16) uint8_t dynsm[];
    const uint32_t dynb = (smem_u32(dynsm) + 1023u) & ~1023u;

    const int b  = blockIdx.z;
    const int m0 = blockIdx.y * 128;   // t
    const int n0 = blockIdx.x * 128;   // u

    const __nv_bfloat16* Ah = g_eh + (size_t)b * TENC * DIM;
    const __nv_bfloat16* Al = g_el + (size_t)b * TENC * DIM;
    const __nv_bfloat16* Bh = g_dh + (size_t)b * TDEC * DIM;
    const __nv_bfloat16* Bl = g_dl + (size_t)b * TDEC * DIM;
    const int* mk = enc_mask + b * TENC;
    float* Sp = S + (size_t)b * TENC * TDEC;

    const int tid  = threadIdx.x;
    const int lane = tid & 31;
    const int wid  = tid >> 5;
    const int m_off = (wid & 1) * 64;
    const int n_off = (wid >> 1) * 32;

    const int lrow = tid >> 2;
    const int lc   = tid & 3;

    const uint32_t aBase = (uint32_t)((m_off + (lane & 15)) * 80 + (lane >> 4) * 16);
    const uint32_t bBase = (uint32_t)((n_off + (lane & 7) + ((lane >> 4) << 3)) * 80
                                      + ((lane >> 3) & 1) * 16);

    float acc[4][4][4];
    #pragma unroll
    for (int i = 0; i < 4; i++)
        #pragma unroll
        for (int j = 0; j < 4; j++)
            #pragma unroll
            for (int k = 0; k < 4; k++) acc[i][j][k] = 0.f;

    const int NST = DIM / 32;

    auto load_stage = [&](int s) {
        const int k0 = s * 32;
        const uint32_t sb = dynb + (uint32_t)(s & 3) * G1_STAGE;
        #pragma unroll
        for (int j = 0; j < 2; j++) {
            int row = lrow + j * 64;
            uint32_t so = (uint32_t)(row * 80 + lc * 16);
            size_t goA = (size_t)(m0 + row) * DIM + k0 + lc * 8;
            size_t goB = (size_t)(n0 + row) * DIM + k0 + lc * 8;
            cpa16(sb + so,              Ah + goA);
            cpa16(sb + G1_BUF + so,     Al + goA);
            cpa16(sb + 2 * G1_BUF + so, Bh + goB);
            cpa16(sb + 3 * G1_BUF + so, Bl + goB);
        }
        cpa_commit();
    };

    load_stage(0);
    load_stage(1);
    load_stage(2);

    for (int s = 0; s < NST; s++) {
        if (s < NST - 2) cpa_wait2();
        else if (s == NST - 2) cpa_wait1();
        else cpa_wait0();
        __syncthreads();

        const uint32_t bAh = dynb + (uint32_t)(s & 3) * G1_STAGE;
        const uint32_t bAl = bAh + G1_BUF;
        const uint32_t bBh = bAh + 2 * G1_BUF;
        const uint32_t bBl = bAh + 3 * G1_BUF;

        #pragma unroll
        for (int ks = 0; ks < 2; ks++) {
            uint32_t koff = (uint32_t)(ks * 32);
            uint32_t ah[4][4], bh[2][4];
            #pragma unroll
            for (int im = 0; im < 4; im++) ldsm4(ah[im], bAh + aBase + im * 1280 + koff);
            #pragma unroll
            for (int p = 0; p < 2; p++)   ldsm4(bh[p], bBh + bBase + p * 1280 + koff);
            #pragma unroll
            for (int im = 0; im < 4; im++)
                #pragma unroll
                for (int in = 0; in < 4; in++)
                    mma_bf16(acc[im][in], ah[im], bh[in >> 1][(in & 1) * 2], bh[in >> 1][(in & 1) * 2 + 1]);

            uint32_t bl[2][4];
            #pragma unroll
            for (int p = 0; p < 2; p++) ldsm4(bl[p], bBl + bBase + p * 1280 + koff);
            #pragma unroll
            for (int im = 0; im < 4; im++)
                #pragma unroll
                for (int in = 0; in < 4; in++)
                    mma_bf16(acc[im][in], ah[im], bl[in >> 1][(in & 1) * 2], bl[in >> 1][(in & 1) * 2 + 1]);

            uint32_t al[4][4];
            #pragma unroll
            for (int im = 0; im < 4; im++) ldsm4(al[im], bAl + aBase + im * 1280 + koff);
            #pragma unroll
            for (int im = 0; im < 4; im++)
                #pragma unroll
                for (int in = 0; in < 4; in++)
                    mma_bf16(acc[im][in], al[im], bh[in >> 1][(in & 1) * 2], bh[in >> 1][(in & 1) * 2 + 1]);
        }
        if (s + 3 < NST) load_stage(s + 3);
    }

    #pragma unroll
    for (int im = 0; im < 4; im++) {
        int tr = m0 + m_off + im * 16 + (lane >> 2);
        float bias0 = (1.0f - (float)mk[tr])     * NEG_BIG;
        float bias1 = (1.0f - (float)mk[tr + 8]) * NEG_BIG;
        #pragma unroll
        for (int in = 0; in < 4; in++) {
            int col = n0 + n_off + in * 8 + (lane & 3) * 2;
            float2 v0 = {acc[im][in][0] - bias0, acc[im][in][1] - bias0};
            float2 v1 = {acc[im][in][2] - bias1, acc[im][in][3] - bias1};
            *(float2*)&Sp[(size_t)tr * TDEC + col]       = v0;
            *(float2*)&Sp[(size_t)(tr + 8) * TDEC + col] = v1;
        }
    }
}

// ---------------------------------------------------------------------------
// Softmax, 2 kernels.
// ---------------------------------------------------------------------------
__global__ __launch_bounds__(256) void softmaxA_kernel(const float* __restrict__ S)
{
    const int b  = blockIdx.z;
    const int c  = blockIdx.y;            // 0..7
    const int u0 = blockIdx.x * 16;
    const int ux = threadIdx.x;           // 0..15
    const int tz = threadIdx.y;           // 0..15
    const int t0 = c * 256;
    const float* col = S + (size_t)b * TENC * TDEC + u0 + ux;

    float x[16];
    #pragma unroll
    for (int i = 0; i < 16; i++)
        x[i] = col[(size_t)(t0 + tz + i * 16) * TDEC];

    float m = x[0];
    #pragma unroll
    for (int i = 1; i < 16; i++) m = fmaxf(m, x[i]);

    __shared__ float red[16][17];
    red[tz][ux] = m;
    __syncthreads();
    #pragma unroll
    for (int s = 8; s > 0; s >>= 1) {
        if (tz < s) red[tz][ux] = fmaxf(red[tz][ux], red[tz + s][ux]);
        __syncthreads();
    }
    m = red[0][ux];
    __syncthreads();

    float sum = 0.f;
    #pragma unroll
    for (int i = 0; i < 16; i++) sum += __expf(x[i] - m);
    red[tz][ux] = sum;
    __syncthreads();
    #pragma unroll
    for (int s = 8; s > 0; s >>= 1) {
        if (tz < s) red[tz][ux] += red[tz + s][ux];
        __syncthreads();
    }
    if (tz == 0) {
        g_cm[(b * 8 + c) * TDEC + u0 + ux] = m;
        g_cs[(b * 8 + c) * TDEC + u0 + ux] = red[0][ux];
    }
}

// combine partials, normalize, write f32 scores + fp16 scores
__global__ __launch_bounds__(256) void softmaxC_kernel(float* __restrict__ S)
{
    const int b  = blockIdx.z;
    const int c  = blockIdx.y;
    const int u0 = blockIdx.x * 16;
    const int ux = threadIdx.x;
    const int tz = threadIdx.y;
    const int t0 = c * 256;
    const int u  = u0 + ux;

    float M = -3.4e38f;
    #pragma unroll
    for (int cc = 0; cc < 8; cc++) M = fmaxf(M, g_cm[(b * 8 + cc) * TDEC + u]);
    float Ssum = 0.f;
    #pragma unroll
    for (int cc = 0; cc < 8; cc++)
        Ssum += g_cs[(b * 8 + cc) * TDEC + u] * __expf(g_cm[(b * 8 + cc) * TDEC + u] - M);
    const float inv = 1.0f / Ssum;

    size_t base = (size_t)b * TENC * TDEC + u;
    float* Sp = S + base;
    __half* ph = g_ph + base;

    #pragma unroll
    for (int i = 0; i < 16; i++) {
        size_t idx = (size_t)(t0 + tz + i * 16) * TDEC;
        float p = __expf(Sp[idx] - M) * inv;
        Sp[idx] = p;
        ph[idx] = __float2half(p);
    }
}

// ---------------------------------------------------------------------------
// GEMM2 (fp16, SINGLE pass): ctx[b,u,d] = sum_t p[t,u] * enc[t,d]
// A = p fp16 [t][u] -> ldmatrix.trans ; B = enc fp16 [t][d] -> trans
// BM=128(u), BN=128(d), BK=32(t). 4-deep ring, 1 CTA/SM.
// ---------------------------------------------------------------------------
#define G2_BUF   8704             // 32 rows * 272 B
#define G2_STAGE (2 * G2_BUF)     // Ph, Ef
#define G2_DYN   (4 * G2_STAGE + 1024)

__global__ __launch_bounds__(256, 1) void gemm2_kernel(float* __restrict__ ctx)
{
    extern __shared__ __align__(16) uint8_t dynsm[];
    const uint32_t dynb = (smem_u32(dynsm) + 1023u) & ~1023u;

    const int b  = blockIdx.z;
    const int u0 = blockIdx.y * 128;
    const int d0 = blockIdx.x * 128;

    const __half* Ph = g_ph + (size_t)b * TENC * TDEC;
    const __half* Ef = g_ef + (size_t)b * TENC * DIM;
    float* C = ctx + (size_t)b * TDEC * DIM;

    const int tid  = threadIdx.x;
    const int lane = tid & 31;
    const int wid  = tid >> 5;
    const int m_off = (wid & 1) * 64;   // u
    const int n_off = (wid >> 1) * 32;  // d

    const int lrow = tid >> 4;   // 0..15 (+16)
    const int lc   = tid & 15;

    const uint32_t aBase = (uint32_t)(((lane & 7) + ((lane >> 4) << 3)) * 272
                                      + (m_off + ((lane >> 3) & 1) * 8) * 2);
    const uint32_t bBase = (uint32_t)(((lane & 7) + (((lane >> 3) & 1) << 3)) * 272
                                      + (n_off + (lane >> 4) * 8) * 2);

    float acc[4][4][4];
    #pragma unroll
    for (int i = 0; i < 4; i++)
        #pragma unroll
        for (int j = 0; j < 4; j++)
            #pragma unroll
            for (int k = 0; k < 4; k++) acc[i][j][k] = 0.f;

    const int NST = TENC / 32;

    auto load_stage = [&](int s) {
        const int k0 = s * 32;
        const uint32_t sb = dynb + (uint32_t)(s & 3) * G2_STAGE;
        #pragma unroll
        for (int j = 0; j < 2; j++) {
            int row = lrow + j * 16;
            uint32_t so = (uint32_t)(row * 272 + lc * 16);
            size_t goP = (size_t)(k0 + row) * TDEC + u0 + lc * 8;
            size_t goE = (size_t)(k0 + row) * DIM + d0 + lc * 8;
            cpa16(sb + so,          Ph + goP);
            cpa16(sb + G2_BUF + so, Ef + goE);
        }
        cpa_commit();
    };

    load_stage(0);
    load_stage(1);
    load_stage(2);

    for (int s = 0; s < NST; s++) {
        if (s < NST - 2) cpa_wait2();
        else if (s == NST - 2) cpa_wait1();
        else cpa_wait0();
        __syncthreads();

        const uint32_t bPh = dynb + (uint32_t)(s & 3) * G2_STAGE;
        const uint32_t bEf = bPh + G2_BUF;

        #pragma unroll
        for (int ks = 0; ks < 2; ks++) {
            uint32_t koff = (uint32_t)(ks * 16 * 272);
            uint32_t ah[4][4], bh[2][4];
            #pragma unroll
            for (int im = 0; im < 4; im++) ldsm4t(ah[im], bPh + aBase + im * 32 + koff);
            #pragma unroll
            for (int p = 0; p < 2; p++)   ldsm4t(bh[p], bEf + bBase + p * 32 + koff);
            #pragma unroll
            for (int im = 0; im < 4; im++)
                #pragma unroll
                for (int in = 0; in < 4; in++)
                    mma_fp16(acc[im][in], ah[im], bh[in >> 1][(in & 1) * 2], bh[in >> 1][(in & 1) * 2 + 1]);
        }
        if (s + 3 < NST) load_stage(s + 3);
    }

    #pragma unroll
    for (int im = 0; im < 4; im++) {
        int ur = u0 + m_off + im * 16 + (lane >> 2);
        #pragma unroll
        for (int in = 0; in < 4; in++) {
            int col = d0 + n_off + in * 8 + (lane & 3) * 2;
            float2 v0 = {acc[im][in][0], acc[im][in][1]};
            float2 v1 = {acc[im][in][2], acc[im][in][3]};
            *(float2*)&C[(size_t)ur * DIM + col]       = v0;
            *(float2*)&C[(size_t)(ur + 8) * DIM + col] = v1;
        }
    }
}

// ---------------------------------------------------------------------------
extern "C" void kernel_launch(void* const* d_in, const int* in_sizes, int n_in,
                              void* d_out, int out_size)
{
    const float* enc      = (const float*)d_in[0];
    const int*   enc_mask = (const int*)  d_in[1];
    const float* dec      = (const float*)d_in[2];

    float* ctx = (float*)d_out;                      // [B, TDEC, DIM]
    float* S   = ctx + (size_t)BATCH * TDEC * DIM;   // [B, TENC, TDEC]

    cudaFuncSetAttribute(gemm1_kernel, cudaFuncAttributeMaxDynamicSharedMemorySize, G1_DYN);
    cudaFuncSetAttribute(gemm2_kernel, cudaFuncAttributeMaxDynamicSharedMemorySize, G2_DYN);

    split_enc_kernel<<<1024, 256>>>(enc);
    split_dec_kernel<<<512, 256>>>(dec);

    gemm1_kernel<<<dim3(TDEC / 128, TENC / 128, BATCH), 256, G1_DYN>>>(enc_mask, S);

    softmaxA_kernel<<<dim3(TDEC / 16, 8, BATCH), dim3(16, 16)>>>(S);
    softmaxC_kernel<<<dim3(TDEC / 16, 8, BATCH), dim3(16, 16)>>>(S);

    gemm2_kernel<<<dim3(DIM / 128, TDEC / 128, BATCH), 256, G2_DYN>>>(ctx);
}

// round 11
// speedup vs baseline: 1.2332x; 1.0246x over previous
#include <cuda_runtime.h>
#include <cuda_bf16.h>
#include <cuda_fp16.h>
#include <cstdint>
#include <cstddef>

#define BATCH 8
#define TENC 2048
#define TDEC 512
#define DIM  1024
#define NEG_BIG 1e20f

// ---------------------------------------------------------------------------
// Scratch (static device arrays — no allocation allowed)
// ---------------------------------------------------------------------------
__device__ __nv_bfloat16 g_eh[(size_t)BATCH * TENC * DIM];   // enc hi bf16 [b][t][d]
__device__ __nv_bfloat16 g_el[(size_t)BATCH * TENC * DIM];   // enc lo bf16
__device__ __half        g_ef[(size_t)BATCH * TENC * DIM];   // enc fp16 (gemm2)
__device__ __nv_bfloat16 g_dh[(size_t)BATCH * TDEC * DIM];   // dec hi bf16 [b][u][d]
__device__ __nv_bfloat16 g_dl[(size_t)BATCH * TDEC * DIM];   // dec lo bf16
__device__ __half        g_ph[(size_t)BATCH * TENC * TDEC];  // scores fp16 [b][t][u]
// softmax partials: 16 t-chunks of 128 (one per gemm1 m-tile)
__device__ float g_cm[BATCH * 16 * TDEC];
__device__ float g_cs[BATCH * 16 * TDEC];

// ---------------------------------------------------------------------------
// helpers
// ---------------------------------------------------------------------------
__device__ __forceinline__ uint32_t smem_u32(const void* p) {
    return (uint32_t)__cvta_generic_to_shared(p);
}
__device__ __forceinline__ void cpa16(uint32_t s, const void* g) {
    asm volatile("cp.async.cg.shared.global [%0], [%1], 16;\n" :: "r"(s), "l"(g));
}
__device__ __forceinline__ void cpa_commit() {
    asm volatile("cp.async.commit_group;\n");
}
__device__ __forceinline__ void cpa_wait2() { asm volatile("cp.async.wait_group 2;\n"); }
__device__ __forceinline__ void cpa_wait1() { asm volatile("cp.async.wait_group 1;\n"); }
__device__ __forceinline__ void cpa_wait0() { asm volatile("cp.async.wait_group 0;\n"); }
__device__ __forceinline__ void ldsm4(uint32_t* r, uint32_t a) {
    asm volatile("ldmatrix.sync.aligned.m8n8.x4.shared.b16 {%0,%1,%2,%3}, [%4];\n"
                 : "=r"(r[0]), "=r"(r[1]), "=r"(r[2]), "=r"(r[3]) : "r"(a));
}
__device__ __forceinline__ void ldsm4t(uint32_t* r, uint32_t a) {
    asm volatile("ldmatrix.sync.aligned.m8n8.x4.trans.shared.b16 {%0,%1,%2,%3}, [%4];\n"
                 : "=r"(r[0]), "=r"(r[1]), "=r"(r[2]), "=r"(r[3]) : "r"(a));
}
__device__ __forceinline__ void mma_bf16(float* c, const uint32_t* a, uint32_t b0, uint32_t b1) {
    asm volatile(
        "mma.sync.aligned.m16n8k16.row.col.f32.bf16.bf16.f32 "
        "{%0,%1,%2,%3},{%4,%5,%6,%7},{%8,%9},{%0,%1,%2,%3};\n"
        : "+f"(c[0]), "+f"(c[1]), "+f"(c[2]), "+f"(c[3])
        : "r"(a[0]), "r"(a[1]), "r"(a[2]), "r"(a[3]), "r"(b0), "r"(b1));
}
__device__ __forceinline__ void mma_fp16(float* c, const uint32_t* a, uint32_t b0, uint32_t b1) {
    asm volatile(
        "mma.sync.aligned.m16n8k16.row.col.f32.f16.f16.f32 "
        "{%0,%1,%2,%3},{%4,%5,%6,%7},{%8,%9},{%0,%1,%2,%3};\n"
        : "+f"(c[0]), "+f"(c[1]), "+f"(c[2]), "+f"(c[3])
        : "r"(a[0]), "r"(a[1]), "r"(a[2]), "r"(a[3]), "r"(b0), "r"(b1));
}

// ---------------------------------------------------------------------------
// enc split: f32 -> bf16 hi/lo + fp16 copy
// ---------------------------------------------------------------------------
__global__ void split_enc_kernel(const float* __restrict__ x)
{
    const int n4 = (int)((size_t)BATCH * TENC * DIM / 4);
    int stride = gridDim.x * blockDim.x;
    for (int i = blockIdx.x * blockDim.x + threadIdx.x; i < n4; i += stride) {
        float4 v = ((const float4*)x)[i];
        __nv_bfloat16 h0 = __float2bfloat16(v.x), h1 = __float2bfloat16(v.y);
        __nv_bfloat16 h2 = __float2bfloat16(v.z), h3 = __float2bfloat16(v.w);
        __nv_bfloat16 l0 = __float2bfloat16(v.x - __bfloat162float(h0));
        __nv_bfloat16 l1 = __float2bfloat16(v.y - __bfloat162float(h1));
        __nv_bfloat16 l2 = __float2bfloat16(v.z - __bfloat162float(h2));
        __nv_bfloat16 l3 = __float2bfloat16(v.w - __bfloat162float(h3));
        __nv_bfloat162 hA = {h0, h1}, hB = {h2, h3}, lA = {l0, l1}, lB = {l2, l3};
        uint2 hv = {*(uint32_t*)&hA, *(uint32_t*)&hB};
        uint2 lv = {*(uint32_t*)&lA, *(uint32_t*)&lB};
        ((uint2*)g_eh)[i] = hv;
        ((uint2*)g_el)[i] = lv;
        __half2 fA = {__float2half(v.x), __float2half(v.y)};
        __half2 fB = {__float2half(v.z), __float2half(v.w)};
        uint2 fv = {*(uint32_t*)&fA, *(uint32_t*)&fB};
        ((uint2*)g_ef)[i] = fv;
    }
}

// dec split: bf16 hi/lo only
__global__ void split_dec_kernel(const float* __restrict__ x)
{
    const int n4 = (int)((size_t)BATCH * TDEC * DIM / 4);
    int stride = gridDim.x * blockDim.x;
    for (int i = blockIdx.x * blockDim.x + threadIdx.x; i < n4; i += stride) {
        float4 v = ((const float4*)x)[i];
        __nv_bfloat16 h0 = __float2bfloat16(v.x), h1 = __float2bfloat16(v.y);
        __nv_bfloat16 h2 = __float2bfloat16(v.z), h3 = __float2bfloat16(v.w);
        __nv_bfloat16 l0 = __float2bfloat16(v.x - __bfloat162float(h0));
        __nv_bfloat16 l1 = __float2bfloat16(v.y - __bfloat162float(h1));
        __nv_bfloat16 l2 = __float2bfloat16(v.z - __bfloat162float(h2));
        __nv_bfloat16 l3 = __float2bfloat16(v.w - __bfloat162float(h3));
        __nv_bfloat162 hA = {h0, h1}, hB = {h2, h3}, lA = {l0, l1}, lB = {l2, l3};
        uint2 hv = {*(uint32_t*)&hA, *(uint32_t*)&hB};
        uint2 lv = {*(uint32_t*)&lA, *(uint32_t*)&lB};
        ((uint2*)g_dh)[i] = hv;
        ((uint2*)g_dl)[i] = lv;
    }
}

// ---------------------------------------------------------------------------
// GEMM1 + fused softmax partials.
// S[b,t,u] = sum_d enc[t,d]*dec[u,d] - (1-mask[t])*NEG_BIG
// Epilogue also emits per-(128-t-chunk, u) max and sumexp to g_cm/g_cs.
// bf16x3 mma.sync. BM=BN=128, BK=32, 8 warps, 4-deep cp.async ring, 1 CTA/SM.
// ---------------------------------------------------------------------------
#define G1_BUF   10240
#define G1_STAGE (4 * G1_BUF)
#define G1_DYN   (4 * G1_STAGE + 1024)

__global__ __launch_bounds__(256, 1) void gemm1_kernel(
    const int* __restrict__ enc_mask, float* __restrict__ S)
{
    extern __shared__ __align__(16) uint8_t dynsm[];
    const uint32_t dynb = (smem_u32(dynsm) + 1023u) & ~1023u;
    __shared__ float smax[2][128];
    __shared__ float ssum[2][128];

    const int b  = blockIdx.z;
    const int m0 = blockIdx.y * 128;   // t
    const int n0 = blockIdx.x * 128;   // u

    const __nv_bfloat16* Ah = g_eh + (size_t)b * TENC * DIM;
    const __nv_bfloat16* Al = g_el + (size_t)b * TENC * DIM;
    const __nv_bfloat16* Bh = g_dh + (size_t)b * TDEC * DIM;
    const __nv_bfloat16* Bl = g_dl + (size_t)b * TDEC * DIM;
    const int* mk = enc_mask + b * TENC;
    float* Sp = S + (size_t)b * TENC * TDEC;

    const int tid  = threadIdx.x;
    const int lane = tid & 31;
    const int wid  = tid >> 5;
    const int m_off = (wid & 1) * 64;
    const int n_off = (wid >> 1) * 32;

    const int lrow = tid >> 2;
    const int lc   = tid & 3;

    const uint32_t aBase = (uint32_t)((m_off + (lane & 15)) * 80 + (lane >> 4) * 16);
    const uint32_t bBase = (uint32_t)((n_off + (lane & 7) + ((lane >> 4) << 3)) * 80
                                      + ((lane >> 3) & 1) * 16);

    float acc[4][4][4];
    #pragma unroll
    for (int i = 0; i < 4; i++)
        #pragma unroll
        for (int j = 0; j < 4; j++)
            #pragma unroll
            for (int k = 0; k < 4; k++) acc[i][j][k] = 0.f;

    const int NST = DIM / 32;

    auto load_stage = [&](int s) {
        const int k0 = s * 32;
        const uint32_t sb = dynb + (uint32_t)(s & 3) * G1_STAGE;
        #pragma unroll
        for (int j = 0; j < 2; j++) {
            int row = lrow + j * 64;
            uint32_t so = (uint32_t)(row * 80 + lc * 16);
            size_t goA = (size_t)(m0 + row) * DIM + k0 + lc * 8;
            size_t goB = (size_t)(n0 + row) * DIM + k0 + lc * 8;
            cpa16(sb + so,              Ah + goA);
            cpa16(sb + G1_BUF + so,     Al + goA);
            cpa16(sb + 2 * G1_BUF + so, Bh + goB);
            cpa16(sb + 3 * G1_BUF + so, Bl + goB);
        }
        cpa_commit();
    };

    load_stage(0);
    load_stage(1);
    load_stage(2);

    for (int s = 0; s < NST; s++) {
        if (s < NST - 2) cpa_wait2();
        else if (s == NST - 2) cpa_wait1();
        else cpa_wait0();
        __syncthreads();

        const uint32_t bAh = dynb + (uint32_t)(s & 3) * G1_STAGE;
        const uint32_t bAl = bAh + G1_BUF;
        const uint32_t bBh = bAh + 2 * G1_BUF;
        const uint32_t bBl = bAh + 3 * G1_BUF;

        #pragma unroll
        for (int ks = 0; ks < 2; ks++) {
            uint32_t koff = (uint32_t)(ks * 32);
            uint32_t ah[4][4], bh[2][4];
            #pragma unroll
            for (int im = 0; im < 4; im++) ldsm4(ah[im], bAh + aBase + im * 1280 + koff);
            #pragma unroll
            for (int p = 0; p < 2; p++)   ldsm4(bh[p], bBh + bBase + p * 1280 + koff);
            #pragma unroll
            for (int im = 0; im < 4; im++)
                #pragma unroll
                for (int in = 0; in < 4; in++)
                    mma_bf16(acc[im][in], ah[im], bh[in >> 1][(in & 1) * 2], bh[in >> 1][(in & 1) * 2 + 1]);

            uint32_t bl[2][4];
            #pragma unroll
            for (int p = 0; p < 2; p++) ldsm4(bl[p], bBl + bBase + p * 1280 + koff);
            #pragma unroll
            for (int im = 0; im < 4; im++)
                #pragma unroll
                for (int in = 0; in < 4; in++)
                    mma_bf16(acc[im][in], ah[im], bl[in >> 1][(in & 1) * 2], bl[in >> 1][(in & 1) * 2 + 1]);

            uint32_t al[4][4];
            #pragma unroll
            for (int im = 0; im < 4; im++) ldsm4(al[im], bAl + aBase + im * 1280 + koff);
            #pragma unroll
            for (int im = 0; im < 4; im++)
                #pragma unroll
                for (int in = 0; in < 4; in++)
                    mma_bf16(acc[im][in], al[im], bh[in >> 1][(in & 1) * 2], bh[in >> 1][(in & 1) * 2 + 1]);
        }
        if (s + 3 < NST) load_stage(s + 3);
    }

    // ---- epilogue: apply bias in-register, write S, fold in softmax partials
    float bias[4][2];
    #pragma unroll
    for (int im = 0; im < 4; im++) {
        int tr = m0 + m_off + im * 16 + (lane >> 2);
        bias[im][0] = (1.0f - (float)mk[tr])     * NEG_BIG;
        bias[im][1] = (1.0f - (float)mk[tr + 8]) * NEG_BIG;
    }
    // biased values back into acc; write S
    #pragma unroll
    for (int im = 0; im < 4; im++) {
        int tr = m0 + m_off + im * 16 + (lane >> 2);
        #pragma unroll
        for (int in = 0; in < 4; in++) {
            acc[im][in][0] -= bias[im][0];
            acc[im][in][1] -= bias[im][0];
            acc[im][in][2] -= bias[im][1];
            acc[im][in][3] -= bias[im][1];
            int col = n0 + n_off + in * 8 + (lane & 3) * 2;
            *(float2*)&Sp[(size_t)tr * TDEC + col]       = *(float2*)&acc[im][in][0];
            *(float2*)&Sp[(size_t)(tr + 8) * TDEC + col] = *(float2*)&acc[im][in][2];
        }
    }
    // per-u max over this thread's 8 t rows (u index within thread: in*2+j)
    float umax[8];
    #pragma unroll
    for (int q = 0; q < 8; q++) umax[q] = -3.4e38f;
    #pragma unroll
    for (int im = 0; im < 4; im++)
        #pragma unroll
        for (int in = 0; in < 4; in++)
            #pragma unroll
            for (int j = 0; j < 2; j++) {
                umax[in * 2 + j] = fmaxf(umax[in * 2 + j], acc[im][in][j]);
                umax[in * 2 + j] = fmaxf(umax[in * 2 + j], acc[im][in][2 + j]);
            }
    // reduce across lanes sharing same (lane&3): xor over bits 2,3,4
    #pragma unroll
    for (int msk = 4; msk <= 16; msk <<= 1)
        #pragma unroll
        for (int q = 0; q < 8; q++)
            umax[q] = fmaxf(umax[q], __shfl_xor_sync(0xffffffffu, umax[q], msk));
    // per-u sumexp
    float usum[8];
    #pragma unroll
    for (int q = 0; q < 8; q++) usum[q] = 0.f;
    #pragma unroll
    for (int im = 0; im < 4; im++)
        #pragma unroll
        for (int in = 0; in < 4; in++)
            #pragma unroll
            for (int j = 0; j < 2; j++) {
                usum[in * 2 + j] += __expf(acc[im][in][j]     - umax[in * 2 + j]);
                usum[in * 2 + j] += __expf(acc[im][in][2 + j] - umax[in * 2 + j]);
            }
    #pragma unroll
    for (int msk = 4; msk <= 16; msk <<= 1)
        #pragma unroll
        for (int q = 0; q < 8; q++)
            usum[q] += __shfl_xor_sync(0xffffffffu, usum[q], msk);
    // lanes 0..3 publish per-u warp partials (64 t rows each)
    if (lane < 4) {
        #pragma unroll
        for (int in = 0; in < 4; in++)
            #pragma unroll
            for (int j = 0; j < 2; j++) {
                int u = n_off + in * 8 + lane * 2 + j;
                smax[wid & 1][u] = umax[in * 2 + j];
                ssum[wid & 1][u] = usum[in * 2 + j];
            }
    }
    __syncthreads();
    // combine the two m-halves, write chunk partials (chunk index = blockIdx.y)
    if (tid < 128) {
        float m0v = smax[0][tid], m1v = smax[1][tid];
        float M = fmaxf(m0v, m1v);
        float Ssum = ssum[0][tid] * __expf(m0v - M) + ssum[1][tid] * __expf(m1v - M);
        int idx = (b * 16 + blockIdx.y) * TDEC + n0 + tid;
        g_cm[idx] = M;
        g_cs[idx] = Ssum;
    }
}

// ---------------------------------------------------------------------------
// softmaxC: combine 16 chunk partials, normalize, write f32 + fp16 scores
// ---------------------------------------------------------------------------
__global__ __launch_bounds__(256) void softmaxC_kernel(float* __restrict__ S)
{
    const int b  = blockIdx.z;
    const int c  = blockIdx.y;
    const int u0 = blockIdx.x * 16;
    const int ux = threadIdx.x;
    const int tz = threadIdx.y;
    const int t0 = c * 256;
    const int u  = u0 + ux;

    float M = -3.4e38f;
    #pragma unroll
    for (int cc = 0; cc < 16; cc++) M = fmaxf(M, g_cm[(b * 16 + cc) * TDEC + u]);
    float Ssum = 0.f;
    #pragma unroll
    for (int cc = 0; cc < 16; cc++)
        Ssum += g_cs[(b * 16 + cc) * TDEC + u] * __expf(g_cm[(b * 16 + cc) * TDEC + u] - M);
    const float inv = 1.0f / Ssum;

    size_t base = (size_t)b * TENC * TDEC + u;
    float* Sp = S + base;
    __half* ph = g_ph + base;

    #pragma unroll
    for (int i = 0; i < 16; i++) {
        size_t idx = (size_t)(t0 + tz + i * 16) * TDEC;
        float p = __expf(Sp[idx] - M) * inv;
        Sp[idx] = p;
        ph[idx] = __float2half(p);
    }
}

// ---------------------------------------------------------------------------
// GEMM2 (fp16, single pass): ctx[b,u,d] = sum_t p[t,u] * enc[t,d]
// BM=128(u), BN=128(d), BK=32(t). 4-deep ring, 2 CTAs/SM (no tail wave).
// ---------------------------------------------------------------------------
#define G2_BUF   8704             // 32 rows * 272 B
#define G2_STAGE (2 * G2_BUF)     // Ph, Ef
#define G2_DYN   (4 * G2_STAGE + 1024)

__global__ __launch_bounds__(256, 2) void gemm2_kernel(float* __restrict__ ctx)
{
    extern __shared__ __align__(16) uint8_t dynsm[];
    const uint32_t dynb = (smem_u32(dynsm) + 1023u) & ~1023u;

    const int b  = blockIdx.z;
    const int u0 = blockIdx.y * 128;
    const int d0 = blockIdx.x * 128;

    const __half* Ph = g_ph + (size_t)b * TENC * TDEC;
    const __half* Ef = g_ef + (size_t)b * TENC * DIM;
    float* C = ctx + (size_t)b * TDEC * DIM;

    const int tid  = threadIdx.x;
    const int lane = tid & 31;
    const int wid  = tid >> 5;
    const int m_off = (wid & 1) * 64;   // u
    const int n_off = (wid >> 1) * 32;  // d

    const int lrow = tid >> 4;   // 0..15 (+16)
    const int lc   = tid & 15;

    const uint32_t aBase = (uint32_t)(((lane & 7) + ((lane >> 4) << 3)) * 272
                                      + (m_off + ((lane >> 3) & 1) * 8) * 2);
    const uint32_t bBase = (uint32_t)(((lane & 7) + (((lane >> 3) & 1) << 3)) * 272
                                      + (n_off + (lane >> 4) * 8) * 2);

    float acc[4][4][4];
    #pragma unroll
    for (int i = 0; i < 4; i++)
        #pragma unroll
        for (int j = 0; j < 4; j++)
            #pragma unroll
            for (int k = 0; k < 4; k++) acc[i][j][k] = 0.f;

    const int NST = TENC / 32;

    auto load_stage = [&](int s) {
        const int k0 = s * 32;
        const uint32_t sb = dynb + (uint32_t)(s & 3) * G2_STAGE;
        #pragma unroll
        for (int j = 0; j < 2; j++) {
            int row = lrow + j * 16;
            uint32_t so = (uint32_t)(row * 272 + lc * 16);
            size_t goP = (size_t)(k0 + row) * TDEC + u0 + lc * 8;
            size_t goE = (size_t)(k0 + row) * DIM + d0 + lc * 8;
            cpa16(sb + so,          Ph + goP);
            cpa16(sb + G2_BUF + so, Ef + goE);
        }
        cpa_commit();
    };

    load_stage(0);
    load_stage(1);
    load_stage(2);

    for (int s = 0; s < NST; s++) {
        if (s < NST - 2) cpa_wait2();
        else if (s == NST - 2) cpa_wait1();
        else cpa_wait0();
        __syncthreads();

        const uint32_t bPh = dynb + (uint32_t)(s & 3) * G2_STAGE;
        const uint32_t bEf = bPh + G2_BUF;

        #pragma unroll
        for (int ks = 0; ks < 2; ks++) {
            uint32_t koff = (uint32_t)(ks * 16 * 272);
            uint32_t ah[4][4], bh[2][4];
            #pragma unroll
            for (int im = 0; im < 4; im++) ldsm4t(ah[im], bPh + aBase + im * 32 + koff);
            #pragma unroll
            for (int p = 0; p < 2; p++)   ldsm4t(bh[p], bEf + bBase + p * 32 + koff);
            #pragma unroll
            for (int im = 0; im < 4; im++)
                #pragma unroll
                for (int in = 0; in < 4; in++)
                    mma_fp16(acc[im][in], ah[im], bh[in >> 1][(in & 1) * 2], bh[in >> 1][(in & 1) * 2 + 1]);
        }
        if (s + 3 < NST) load_stage(s + 3);
    }

    #pragma unroll
    for (int im = 0; im < 4; im++) {
        int ur = u0 + m_off + im * 16 + (lane >> 2);
        #pragma unroll
        for (int in = 0; in < 4; in++) {
            int col = d0 + n_off + in * 8 + (lane & 3) * 2;
            float2 v0 = {acc[im][in][0], acc[im][in][1]};
            float2 v1 = {acc[im][in][2], acc[im][in][3]};
            *(float2*)&C[(size_t)ur * DIM + col]       = v0;
            *(float2*)&C[(size_t)(ur + 8) * DIM + col] = v1;
        }
    }
}

// ---------------------------------------------------------------------------
extern "C" void kernel_launch(void* const* d_in, const int* in_sizes, int n_in,
                              void* d_out, int out_size)
{
    const float* enc      = (const float*)d_in[0];
    const int*   enc_mask = (const int*)  d_in[1];
    const float* dec      = (const float*)d_in[2];

    float* ctx = (float*)d_out;                      // [B, TDEC, DIM]
    float* S   = ctx + (size_t)BATCH * TDEC * DIM;   // [B, TENC, TDEC]

    cudaFuncSetAttribute(gemm1_kernel, cudaFuncAttributeMaxDynamicSharedMemorySize, G1_DYN);
    cudaFuncSetAttribute(gemm2_kernel, cudaFuncAttributeMaxDynamicSharedMemorySize, G2_DYN);

    split_enc_kernel<<<1024, 256>>>(enc);
    split_dec_kernel<<<512, 256>>>(dec);

    gemm1_kernel<<<dim3(TDEC / 128, TENC / 128, BATCH), 256, G1_DYN>>>(enc_mask, S);

    softmaxC_kernel<<<dim3(TDEC / 16, 8, BATCH), dim3(16, 16)>>>(S);

    gemm2_kernel<<<dim3(DIM / 128, TDEC / 128, BATCH), 256, G2_DYN>>>(ctx);
}

// round 12
// speedup vs baseline: 1.2593x; 1.0212x over previous
#include <cuda_runtime.h>
#include <cuda_bf16.h>
#include <cuda_fp16.h>
#include <cstdint>
#include <cstddef>

#define BATCH 8
#define TENC 2048
#define TDEC 512
#define DIM  1024
#define NEG_BIG 1e20f

// ---------------------------------------------------------------------------
// Scratch (static device arrays — no allocation allowed)
// ---------------------------------------------------------------------------
__device__ __nv_bfloat16 g_eh[(size_t)BATCH * TENC * DIM];   // enc hi bf16 [b][t][d]
__device__ __nv_bfloat16 g_el[(size_t)BATCH * TENC * DIM];   // enc lo bf16
__device__ __half        g_ef[(size_t)BATCH * TENC * DIM];   // enc fp16 (gemm2)
__device__ __nv_bfloat16 g_dh[(size_t)BATCH * TDEC * DIM];   // dec hi bf16 [b][u][d]
__device__ __nv_bfloat16 g_dl[(size_t)BATCH * TDEC * DIM];   // dec lo bf16
__device__ __half        g_ph[(size_t)BATCH * TENC * TDEC];  // scores fp16 [b][t][u]
// softmax partials: 16 t-chunks of 128 (one per gemm1 m-tile)
__device__ float g_cm[BATCH * 16 * TDEC];
__device__ float g_cs[BATCH * 16 * TDEC];
__device__ float g_Mx[BATCH * TDEC];
__device__ float g_Iv[BATCH * TDEC];

// ---------------------------------------------------------------------------
// helpers
// ---------------------------------------------------------------------------
__device__ __forceinline__ uint32_t smem_u32(const void* p) {
    return (uint32_t)__cvta_generic_to_shared(p);
}
__device__ __forceinline__ void cpa16(uint32_t s, const void* g) {
    asm volatile("cp.async.cg.shared.global [%0], [%1], 16;\n" :: "r"(s), "l"(g));
}
__device__ __forceinline__ void cpa_commit() {
    asm volatile("cp.async.commit_group;\n");
}
__device__ __forceinline__ void cpa_wait2() { asm volatile("cp.async.wait_group 2;\n"); }
__device__ __forceinline__ void cpa_wait1() { asm volatile("cp.async.wait_group 1;\n"); }
__device__ __forceinline__ void cpa_wait0() { asm volatile("cp.async.wait_group 0;\n"); }
__device__ __forceinline__ void ldsm4(uint32_t* r, uint32_t a) {
    asm volatile("ldmatrix.sync.aligned.m8n8.x4.shared.b16 {%0,%1,%2,%3}, [%4];\n"
                 : "=r"(r[0]), "=r"(r[1]), "=r"(r[2]), "=r"(r[3]) : "r"(a));
}
__device__ __forceinline__ void ldsm4t(uint32_t* r, uint32_t a) {
    asm volatile("ldmatrix.sync.aligned.m8n8.x4.trans.shared.b16 {%0,%1,%2,%3}, [%4];\n"
                 : "=r"(r[0]), "=r"(r[1]), "=r"(r[2]), "=r"(r[3]) : "r"(a));
}
__device__ __forceinline__ void mma_bf16(float* c, const uint32_t* a, uint32_t b0, uint32_t b1) {
    asm volatile(
        "mma.sync.aligned.m16n8k16.row.col.f32.bf16.bf16.f32 "
        "{%0,%1,%2,%3},{%4,%5,%6,%7},{%8,%9},{%0,%1,%2,%3};\n"
        : "+f"(c[0]), "+f"(c[1]), "+f"(c[2]), "+f"(c[3])
        : "r"(a[0]), "r"(a[1]), "r"(a[2]), "r"(a[3]), "r"(b0), "r"(b1));
}
__device__ __forceinline__ void mma_fp16(float* c, const uint32_t* a, uint32_t b0, uint32_t b1) {
    asm volatile(
        "mma.sync.aligned.m16n8k16.row.col.f32.f16.f16.f32 "
        "{%0,%1,%2,%3},{%4,%5,%6,%7},{%8,%9},{%0,%1,%2,%3};\n"
        : "+f"(c[0]), "+f"(c[1]), "+f"(c[2]), "+f"(c[3])
        : "r"(a[0]), "r"(a[1]), "r"(a[2]), "r"(a[3]), "r"(b0), "r"(b1));
}

// ---------------------------------------------------------------------------
// enc split: f32 -> bf16 hi/lo + fp16 copy
// ---------------------------------------------------------------------------
__global__ void split_enc_kernel(const float* __restrict__ x)
{
    const int n4 = (int)((size_t)BATCH * TENC * DIM / 4);
    int stride = gridDim.x * blockDim.x;
    for (int i = blockIdx.x * blockDim.x + threadIdx.x; i < n4; i += stride) {
        float4 v = ((const float4*)x)[i];
        __nv_bfloat16 h0 = __float2bfloat16(v.x), h1 = __float2bfloat16(v.y);
        __nv_bfloat16 h2 = __float2bfloat16(v.z), h3 = __float2bfloat16(v.w);
        __nv_bfloat16 l0 = __float2bfloat16(v.x - __bfloat162float(h0));
        __nv_bfloat16 l1 = __float2bfloat16(v.y - __bfloat162float(h1));
        __nv_bfloat16 l2 = __float2bfloat16(v.z - __bfloat162float(h2));
        __nv_bfloat16 l3 = __float2bfloat16(v.w - __bfloat162float(h3));
        __nv_bfloat162 hA = {h0, h1}, hB = {h2, h3}, lA = {l0, l1}, lB = {l2, l3};
        uint2 hv = {*(uint32_t*)&hA, *(uint32_t*)&hB};
        uint2 lv = {*(uint32_t*)&lA, *(uint32_t*)&lB};
        ((uint2*)g_eh)[i] = hv;
        ((uint2*)g_el)[i] = lv;
        __half2 fA = {__float2half(v.x), __float2half(v.y)};
        __half2 fB = {__float2half(v.z), __float2half(v.w)};
        uint2 fv = {*(uint32_t*)&fA, *(uint32_t*)&fB};
        ((uint2*)g_ef)[i] = fv;
    }
}

// dec split: bf16 hi/lo only
__global__ void split_dec_kernel(const float* __restrict__ x)
{
    const int n4 = (int)((size_t)BATCH * TDEC * DIM / 4);
    int stride = gridDim.x * blockDim.x;
    for (int i = blockIdx.x * blockDim.x + threadIdx.x; i < n4; i += stride) {
        float4 v = ((const float4*)x)[i];
        __nv_bfloat16 h0 = __float2bfloat16(v.x), h1 = __float2bfloat16(v.y);
        __nv_bfloat16 h2 = __float2bfloat16(v.z), h3 = __float2bfloat16(v.w);
        __nv_bfloat16 l0 = __float2bfloat16(v.x - __bfloat162float(h0));
        __nv_bfloat16 l1 = __float2bfloat16(v.y - __bfloat162float(h1));
        __nv_bfloat16 l2 = __float2bfloat16(v.z - __bfloat162float(h2));
        __nv_bfloat16 l3 = __float2bfloat16(v.w - __bfloat162float(h3));
        __nv_bfloat162 hA = {h0, h1}, hB = {h2, h3}, lA = {l0, l1}, lB = {l2, l3};
        uint2 hv = {*(uint32_t*)&hA, *(uint32_t*)&hB};
        uint2 lv = {*(uint32_t*)&lA, *(uint32_t*)&lB};
        ((uint2*)g_dh)[i] = hv;
        ((uint2*)g_dl)[i] = lv;
    }
}

// ---------------------------------------------------------------------------
// GEMM1 + fused softmax chunk partials (identical to R11 winner)
// ---------------------------------------------------------------------------
#define G1_BUF   10240
#define G1_STAGE (4 * G1_BUF)
#define G1_DYN   (4 * G1_STAGE + 1024)

__global__ __launch_bounds__(256, 1) void gemm1_kernel(
    const int* __restrict__ enc_mask, float* __restrict__ S)
{
    extern __shared__ __align__(16) uint8_t dynsm[];
    const uint32_t dynb = (smem_u32(dynsm) + 1023u) & ~1023u;
    __shared__ float smax[2][128];
    __shared__ float ssum[2][128];

    const int b  = blockIdx.z;
    const int m0 = blockIdx.y * 128;   // t
    const int n0 = blockIdx.x * 128;   // u

    const __nv_bfloat16* Ah = g_eh + (size_t)b * TENC * DIM;
    const __nv_bfloat16* Al = g_el + (size_t)b * TENC * DIM;
    const __nv_bfloat16* Bh = g_dh + (size_t)b * TDEC * DIM;
    const __nv_bfloat16* Bl = g_dl + (size_t)b * TDEC * DIM;
    const int* mk = enc_mask + b * TENC;
    float* Sp = S + (size_t)b * TENC * TDEC;

    const int tid  = threadIdx.x;
    const int lane = tid & 31;
    const int wid  = tid >> 5;
    const int m_off = (wid & 1) * 64;
    const int n_off = (wid >> 1) * 32;

    const int lrow = tid >> 2;
    const int lc   = tid & 3;

    const uint32_t aBase = (uint32_t)((m_off + (lane & 15)) * 80 + (lane >> 4) * 16);
    const uint32_t bBase = (uint32_t)((n_off + (lane & 7) + ((lane >> 4) << 3)) * 80
                                      + ((lane >> 3) & 1) * 16);

    float acc[4][4][4];
    #pragma unroll
    for (int i = 0; i < 4; i++)
        #pragma unroll
        for (int j = 0; j < 4; j++)
            #pragma unroll
            for (int k = 0; k < 4; k++) acc[i][j][k] = 0.f;

    const int NST = DIM / 32;

    auto load_stage = [&](int s) {
        const int k0 = s * 32;
        const uint32_t sb = dynb + (uint32_t)(s & 3) * G1_STAGE;
        #pragma unroll
        for (int j = 0; j < 2; j++) {
            int row = lrow + j * 64;
            uint32_t so = (uint32_t)(row * 80 + lc * 16);
            size_t goA = (size_t)(m0 + row) * DIM + k0 + lc * 8;
            size_t goB = (size_t)(n0 + row) * DIM + k0 + lc * 8;
            cpa16(sb + so,              Ah + goA);
            cpa16(sb + G1_BUF + so,     Al + goA);
            cpa16(sb + 2 * G1_BUF + so, Bh + goB);
            cpa16(sb + 3 * G1_BUF + so, Bl + goB);
        }
        cpa_commit();
    };

    load_stage(0);
    load_stage(1);
    load_stage(2);

    for (int s = 0; s < NST; s++) {
        if (s < NST - 2) cpa_wait2();
        else if (s == NST - 2) cpa_wait1();
        else cpa_wait0();
        __syncthreads();

        const uint32_t bAh = dynb + (uint32_t)(s & 3) * G1_STAGE;
        const uint32_t bAl = bAh + G1_BUF;
        const uint32_t bBh = bAh + 2 * G1_BUF;
        const uint32_t bBl = bAh + 3 * G1_BUF;

        #pragma unroll
        for (int ks = 0; ks < 2; ks++) {
            uint32_t koff = (uint32_t)(ks * 32);
            uint32_t ah[4][4], bh[2][4];
            #pragma unroll
            for (int im = 0; im < 4; im++) ldsm4(ah[im], bAh + aBase + im * 1280 + koff);
            #pragma unroll
            for (int p = 0; p < 2; p++)   ldsm4(bh[p], bBh + bBase + p * 1280 + koff);
            #pragma unroll
            for (int im = 0; im < 4; im++)
                #pragma unroll
                for (int in = 0; in < 4; in++)
                    mma_bf16(acc[im][in], ah[im], bh[in >> 1][(in & 1) * 2], bh[in >> 1][(in & 1) * 2 + 1]);

            uint32_t bl[2][4];
            #pragma unroll
            for (int p = 0; p < 2; p++) ldsm4(bl[p], bBl + bBase + p * 1280 + koff);
            #pragma unroll
            for (int im = 0; im < 4; im++)
                #pragma unroll
                for (int in = 0; in < 4; in++)
                    mma_bf16(acc[im][in], ah[im], bl[in >> 1][(in & 1) * 2], bl[in >> 1][(in & 1) * 2 + 1]);

            uint32_t al[4][4];
            #pragma unroll
            for (int im = 0; im < 4; im++) ldsm4(al[im], bAl + aBase + im * 1280 + koff);
            #pragma unroll
            for (int im = 0; im < 4; im++)
                #pragma unroll
                for (int in = 0; in < 4; in++)
                    mma_bf16(acc[im][in], al[im], bh[in >> 1][(in & 1) * 2], bh[in >> 1][(in & 1) * 2 + 1]);
        }
        if (s + 3 < NST) load_stage(s + 3);
    }

    float bias[4][2];
    #pragma unroll
    for (int im = 0; im < 4; im++) {
        int tr = m0 + m_off + im * 16 + (lane >> 2);
        bias[im][0] = (1.0f - (float)mk[tr])     * NEG_BIG;
        bias[im][1] = (1.0f - (float)mk[tr + 8]) * NEG_BIG;
    }
    #pragma unroll
    for (int im = 0; im < 4; im++) {
        int tr = m0 + m_off + im * 16 + (lane >> 2);
        #pragma unroll
        for (int in = 0; in < 4; in++) {
            acc[im][in][0] -= bias[im][0];
            acc[im][in][1] -= bias[im][0];
            acc[im][in][2] -= bias[im][1];
            acc[im][in][3] -= bias[im][1];
            int col = n0 + n_off + in * 8 + (lane & 3) * 2;
            *(float2*)&Sp[(size_t)tr * TDEC + col]       = *(float2*)&acc[im][in][0];
            *(float2*)&Sp[(size_t)(tr + 8) * TDEC + col] = *(float2*)&acc[im][in][2];
        }
    }
    float umax[8];
    #pragma unroll
    for (int q = 0; q < 8; q++) umax[q] = -3.4e38f;
    #pragma unroll
    for (int im = 0; im < 4; im++)
        #pragma unroll
        for (int in = 0; in < 4; in++)
            #pragma unroll
            for (int j = 0; j < 2; j++) {
                umax[in * 2 + j] = fmaxf(umax[in * 2 + j], acc[im][in][j]);
                umax[in * 2 + j] = fmaxf(umax[in * 2 + j], acc[im][in][2 + j]);
            }
    #pragma unroll
    for (int msk = 4; msk <= 16; msk <<= 1)
        #pragma unroll
        for (int q = 0; q < 8; q++)
            umax[q] = fmaxf(umax[q], __shfl_xor_sync(0xffffffffu, umax[q], msk));
    float usum[8];
    #pragma unroll
    for (int q = 0; q < 8; q++) usum[q] = 0.f;
    #pragma unroll
    for (int im = 0; im < 4; im++)
        #pragma unroll
        for (int in = 0; in < 4; in++)
            #pragma unroll
            for (int j = 0; j < 2; j++) {
                usum[in * 2 + j] += __expf(acc[im][in][j]     - umax[in * 2 + j]);
                usum[in * 2 + j] += __expf(acc[im][in][2 + j] - umax[in * 2 + j]);
            }
    #pragma unroll
    for (int msk = 4; msk <= 16; msk <<= 1)
        #pragma unroll
        for (int q = 0; q < 8; q++)
            usum[q] += __shfl_xor_sync(0xffffffffu, usum[q], msk);
    if (lane < 4) {
        #pragma unroll
        for (int in = 0; in < 4; in++)
            #pragma unroll
            for (int j = 0; j < 2; j++) {
                int u = n_off + in * 8 + lane * 2 + j;
                smax[wid & 1][u] = umax[in * 2 + j];
                ssum[wid & 1][u] = usum[in * 2 + j];
            }
    }
    __syncthreads();
    if (tid < 128) {
        float m0v = smax[0][tid], m1v = smax[1][tid];
        float M = fmaxf(m0v, m1v);
        float Ssum = ssum[0][tid] * __expf(m0v - M) + ssum[1][tid] * __expf(m1v - M);
        int idx = (b * 16 + blockIdx.y) * TDEC + n0 + tid;
        g_cm[idx] = M;
        g_cs[idx] = Ssum;
    }
}

// ---------------------------------------------------------------------------
// softmaxB: fold 16 chunk partials -> M[b,u], 1/S[b,u]
// ---------------------------------------------------------------------------
__global__ void softmaxB_kernel()
{
    int i = blockIdx.x * 256 + threadIdx.x;
    if (i >= BATCH * TDEC) return;
    int b = i / TDEC, u = i % TDEC;
    float M = -3.4e38f;
    #pragma unroll
    for (int c = 0; c < 16; c++) M = fmaxf(M, g_cm[(b * 16 + c) * TDEC + u]);
    float Ssum = 0.f;
    #pragma unroll
    for (int c = 0; c < 16; c++)
        Ssum += g_cs[(b * 16 + c) * TDEC + u] * __expf(g_cm[(b * 16 + c) * TDEC + u] - M);
    g_Mx[i] = M;
    g_Iv[i] = 1.0f / Ssum;
}

// ---------------------------------------------------------------------------
// softmaxC (row-coalesced): each block does 8 t-rows; M/inv staged in smem.
// Streams float4 S in/out + half4 ph out, fully coalesced.
// ---------------------------------------------------------------------------
__global__ __launch_bounds__(256) void softmaxC_kernel(float* __restrict__ S)
{
    const int b  = blockIdx.y;
    const int t0 = blockIdx.x * 8;
    const int tid = threadIdx.x;

    __shared__ float sM[TDEC], sI[TDEC];
    #pragma unroll
    for (int i = tid; i < TDEC; i += 256) {
        sM[i] = g_Mx[b * TDEC + i];
        sI[i] = g_Iv[b * TDEC + i];
    }
    __syncthreads();

    // 8 rows * 128 float4 = 1024 slots, 4 per thread
    #pragma unroll
    for (int slot = tid; slot < 1024; slot += 256) {
        int row = slot >> 7;          // 0..7
        int u4  = slot & 127;         // float4 index in row
        int u   = u4 * 4;
        size_t idx = ((size_t)b * TENC + t0 + row) * TDEC + u;
        float4 v = *(float4*)&S[idx];
        v.x = __expf(v.x - sM[u + 0]) * sI[u + 0];
        v.y = __expf(v.y - sM[u + 1]) * sI[u + 1];
        v.z = __expf(v.z - sM[u + 2]) * sI[u + 2];
        v.w = __expf(v.w - sM[u + 3]) * sI[u + 3];
        *(float4*)&S[idx] = v;
        __half2 h01 = {__float2half(v.x), __float2half(v.y)};
        __half2 h23 = {__float2half(v.z), __float2half(v.w)};
        uint2 hv = {*(uint32_t*)&h01, *(uint32_t*)&h23};
        *(uint2*)&g_ph[idx] = hv;
    }
}

// ---------------------------------------------------------------------------
// GEMM2 (fp16, single pass): ctx[b,u,d] = sum_t p[t,u] * enc[t,d]
// BM=128(u), BN=128(d), BK=32(t). 4-deep ring, 2 CTAs/SM.
// ---------------------------------------------------------------------------
#define G2_BUF   8704             // 32 rows * 272 B
#define G2_STAGE (2 * G2_BUF)     // Ph, Ef
#define G2_DYN   (4 * G2_STAGE + 1024)

__global__ __launch_bounds__(256, 2) void gemm2_kernel(float* __restrict__ ctx)
{
    extern __shared__ __align__(16) uint8_t dynsm[];
    const uint32_t dynb = (smem_u32(dynsm) + 1023u) & ~1023u;

    const int b  = blockIdx.z;
    const int u0 = blockIdx.y * 128;
    const int d0 = blockIdx.x * 128;

    const __half* Ph = g_ph + (size_t)b * TENC * TDEC;
    const __half* Ef = g_ef + (size_t)b * TENC * DIM;
    float* C = ctx + (size_t)b * TDEC * DIM;

    const int tid  = threadIdx.x;
    const int lane = tid & 31;
    const int wid  = tid >> 5;
    const int m_off = (wid & 1) * 64;   // u
    const int n_off = (wid >> 1) * 32;  // d

    const int lrow = tid >> 4;   // 0..15 (+16)
    const int lc   = tid & 15;

    const uint32_t aBase = (uint32_t)(((lane & 7) + ((lane >> 4) << 3)) * 272
                                      + (m_off + ((lane >> 3) & 1) * 8) * 2);
    const uint32_t bBase = (uint32_t)(((lane & 7) + (((lane >> 3) & 1) << 3)) * 272
                                      + (n_off + (lane >> 4) * 8) * 2);

    float acc[4][4][4];
    #pragma unroll
    for (int i = 0; i < 4; i++)
        #pragma unroll
        for (int j = 0; j < 4; j++)
            #pragma unroll
            for (int k = 0; k < 4; k++) acc[i][j][k] = 0.f;

    const int NST = TENC / 32;

    auto load_stage = [&](int s) {
        const int k0 = s * 32;
        const uint32_t sb = dynb + (uint32_t)(s & 3) * G2_STAGE;
        #pragma unroll
        for (int j = 0; j < 2; j++) {
            int row = lrow + j * 16;
            uint32_t so = (uint32_t)(row * 272 + lc * 16);
            size_t goP = (size_t)(k0 + row) * TDEC + u0 + lc * 8;
            size_t goE = (size_t)(k0 + row) * DIM + d0 + lc * 8;
            cpa16(sb + so,          Ph + goP);
            cpa16(sb + G2_BUF + so, Ef + goE);
        }
        cpa_commit();
    };

    load_stage(0);
    load_stage(1);
    load_stage(2);

    for (int s = 0; s < NST; s++) {
        if (s < NST - 2) cpa_wait2();
        else if (s == NST - 2) cpa_wait1();
        else cpa_wait0();
        __syncthreads();

        const uint32_t bPh = dynb + (uint32_t)(s & 3) * G2_STAGE;
        const uint32_t bEf = bPh + G2_BUF;

        #pragma unroll
        for (int ks = 0; ks < 2; ks++) {
            uint32_t koff = (uint32_t)(ks * 16 * 272);
            uint32_t ah[4][4], bh[2][4];
            #pragma unroll
            for (int im = 0; im < 4; im++) ldsm4t(ah[im], bPh + aBase + im * 32 + koff);
            #pragma unroll
            for (int p = 0; p < 2; p++)   ldsm4t(bh[p], bEf + bBase + p * 32 + koff);
            #pragma unroll
            for (int im = 0; im < 4; im++)
                #pragma unroll
                for (int in = 0; in < 4; in++)
                    mma_fp16(acc[im][in], ah[im], bh[in >> 1][(in & 1) * 2], bh[in >> 1][(in & 1) * 2 + 1]);
        }
        if (s + 3 < NST) load_stage(s + 3);
    }

    #pragma unroll
    for (int im = 0; im < 4; im++) {
        int ur = u0 + m_off + im * 16 + (lane >> 2);
        #pragma unroll
        for (int in = 0; in < 4; in++) {
            int col = d0 + n_off + in * 8 + (lane & 3) * 2;
            float2 v0 = {acc[im][in][0], acc[im][in][1]};
            float2 v1 = {acc[im][in][2], acc[im][in][3]};
            *(float2*)&C[(size_t)ur * DIM + col]       = v0;
            *(float2*)&C[(size_t)(ur + 8) * DIM + col] = v1;
        }
    }
}

// ---------------------------------------------------------------------------
extern "C" void kernel_launch(void* const* d_in, const int* in_sizes, int n_in,
                              void* d_out, int out_size)
{
    const float* enc      = (const float*)d_in[0];
    const int*   enc_mask = (const int*)  d_in[1];
    const float* dec      = (const float*)d_in[2];

    float* ctx = (float*)d_out;                      // [B, TDEC, DIM]
    float* S   = ctx + (size_t)BATCH * TDEC * DIM;   // [B, TENC, TDEC]

    cudaFuncSetAttribute(gemm1_kernel, cudaFuncAttributeMaxDynamicSharedMemorySize, G1_DYN);
    cudaFuncSetAttribute(gemm2_kernel, cudaFuncAttributeMaxDynamicSharedMemorySize, G2_DYN);

    split_enc_kernel<<<1024, 256>>>(enc);
    split_dec_kernel<<<512, 256>>>(dec);

    gemm1_kernel<<<dim3(TDEC / 128, TENC / 128, BATCH), 256, G1_DYN>>>(enc_mask, S);

    softmaxB_kernel<<<(BATCH * TDEC + 255) / 256, 256>>>();
    softmaxC_kernel<<<dim3(TENC / 8, BATCH), 256>>>(S);

    gemm2_kernel<<<dim3(DIM / 128, TDEC / 128, BATCH), 256, G2_DYN>>>(ctx);
}

// round 13
// speedup vs baseline: 1.3555x; 1.0764x over previous
#include <cuda_runtime.h>
#include <cuda_bf16.h>
#include <cuda_fp16.h>
#include <cstdint>
#include <cstddef>

#define BATCH 8
#define TENC 2048
#define TDEC 512
#define DIM  1024

// ---------------------------------------------------------------------------
// Scratch (static device arrays — no allocation allowed)
// ---------------------------------------------------------------------------
__device__ __nv_bfloat16 g_eh[(size_t)BATCH * TENC * DIM];   // enc hi bf16 [b][t][d]
__device__ __nv_bfloat16 g_el[(size_t)BATCH * TENC * DIM];   // enc lo bf16
__device__ __half        g_ef[(size_t)BATCH * TENC * DIM];   // enc fp16 (gemm2)
__device__ __nv_bfloat16 g_dh[(size_t)BATCH * TDEC * DIM];   // dec hi bf16 [b][u][d]
__device__ __nv_bfloat16 g_dl[(size_t)BATCH * TDEC * DIM];   // dec lo bf16
__device__ __half        g_pc[(size_t)BATCH * TENC * TDEC];  // COMPACT scores fp16 [b][j][u]
// mask compaction
__device__ int g_idx[BATCH * TENC];    // compact j -> t  (0-padded past cnt)
__device__ int g_rank[BATCH * TENC];   // t -> compact j  (valid where mask=1)
__device__ int g_cnt[BATCH];
// softmax partials: 16 compact chunks of 128
__device__ float g_cm[BATCH * 16 * TDEC];
__device__ float g_cs[BATCH * 16 * TDEC];
__device__ float g_Mx[BATCH * TDEC];
__device__ float g_Iv[BATCH * TDEC];

// ---------------------------------------------------------------------------
// helpers
// ---------------------------------------------------------------------------
__device__ __forceinline__ uint32_t smem_u32(const void* p) {
    return (uint32_t)__cvta_generic_to_shared(p);
}
__device__ __forceinline__ void cpa16(uint32_t s, const void* g) {
    asm volatile("cp.async.cg.shared.global [%0], [%1], 16;\n" :: "r"(s), "l"(g));
}
__device__ __forceinline__ void cpa_commit() {
    asm volatile("cp.async.commit_group;\n");
}
__device__ __forceinline__ void cpa_wait2() { asm volatile("cp.async.wait_group 2;\n"); }
__device__ __forceinline__ void cpa_wait1() { asm volatile("cp.async.wait_group 1;\n"); }
__device__ __forceinline__ void cpa_wait0() { asm volatile("cp.async.wait_group 0;\n"); }
__device__ __forceinline__ void ldsm4(uint32_t* r, uint32_t a) {
    asm volatile("ldmatrix.sync.aligned.m8n8.x4.shared.b16 {%0,%1,%2,%3}, [%4];\n"
                 : "=r"(r[0]), "=r"(r[1]), "=r"(r[2]), "=r"(r[3]) : "r"(a));
}
__device__ __forceinline__ void ldsm4t(uint32_t* r, uint32_t a) {
    asm volatile("ldmatrix.sync.aligned.m8n8.x4.trans.shared.b16 {%0,%1,%2,%3}, [%4];\n"
                 : "=r"(r[0]), "=r"(r[1]), "=r"(r[2]), "=r"(r[3]) : "r"(a));
}
__device__ __forceinline__ void mma_bf16(float* c, const uint32_t* a, uint32_t b0, uint32_t b1) {
    asm volatile(
        "mma.sync.aligned.m16n8k16.row.col.f32.bf16.bf16.f32 "
        "{%0,%1,%2,%3},{%4,%5,%6,%7},{%8,%9},{%0,%1,%2,%3};\n"
        : "+f"(c[0]), "+f"(c[1]), "+f"(c[2]), "+f"(c[3])
        : "r"(a[0]), "r"(a[1]), "r"(a[2]), "r"(a[3]), "r"(b0), "r"(b1));
}
__device__ __forceinline__ void mma_fp16(float* c, const uint32_t* a, uint32_t b0, uint32_t b1) {
    asm volatile(
        "mma.sync.aligned.m16n8k16.row.col.f32.f16.f16.f32 "
        "{%0,%1,%2,%3},{%4,%5,%6,%7},{%8,%9},{%0,%1,%2,%3};\n"
        : "+f"(c[0]), "+f"(c[1]), "+f"(c[2]), "+f"(c[3])
        : "r"(a[0]), "r"(a[1]), "r"(a[2]), "r"(a[3]), "r"(b0), "r"(b1));
}

// ---------------------------------------------------------------------------
// compact: per batch, prefix-scan mask; init partials; zero-pad compact rows
// ---------------------------------------------------------------------------
__global__ __launch_bounds__(1024) void compact_kernel(const int* __restrict__ mask)
{
    const int b   = blockIdx.x;
    const int tid = threadIdx.x;       // 1024
    const int lane = tid & 31, wid = tid >> 5;
    const int* m = mask + b * TENC;

    int v0 = m[2 * tid], v1 = m[2 * tid + 1];
    int s = v0 + v1;
    int x = s;
    #pragma unroll
    for (int o = 1; o < 32; o <<= 1) {
        int y = __shfl_up_sync(0xffffffffu, x, o);
        if (lane >= o) x += y;
    }
    __shared__ int wsum[32], wscan[32];
    if (lane == 31) wsum[wid] = x;
    __syncthreads();
    if (wid == 0) {
        int w = wsum[lane];
        #pragma unroll
        for (int o = 1; o < 32; o <<= 1) {
            int y = __shfl_up_sync(0xffffffffu, w, o);
            if (lane >= o) w += y;
        }
        wscan[lane] = w;
    }
    __syncthreads();
    int excl = x - s + (wid > 0 ? wscan[wid - 1] : 0);
    int p = excl;
    if (v0) { g_idx[b * TENC + p] = 2 * tid;     g_rank[b * TENC + 2 * tid]     = p; p++; }
    if (v1) { g_idx[b * TENC + p] = 2 * tid + 1; g_rank[b * TENC + 2 * tid + 1] = p; }
    const int total = wscan[31];
    if (tid == 0) g_cnt[b] = total;
    __syncthreads();

    // pad idx with 0 past total
    for (int j = tid; j < TENC; j += 1024)
        if (j >= total) g_idx[b * TENC + j] = 0;
    // init chunk partials
    for (int i = tid; i < 16 * TDEC; i += 1024) {
        g_cm[b * 16 * TDEC + i] = -3.4e38f;
        g_cs[b * 16 * TDEC + i] = 0.f;
    }
    // zero-pad compact score rows [total, cnt32)
    const int cnt32 = (total + 31) & ~31;
    const int padn = (cnt32 - total) * TDEC;
    __half zh = __float2half(0.f);
    for (int i = tid; i < padn; i += 1024) {
        int r = total + i / TDEC, u = i % TDEC;
        g_pc[((size_t)b * TENC + r) * TDEC + u] = zh;
    }
}

// ---------------------------------------------------------------------------
// enc split: f32 -> bf16 hi/lo + fp16 copy
// ---------------------------------------------------------------------------
__global__ void split_enc_kernel(const float* __restrict__ x)
{
    const int n4 = (int)((size_t)BATCH * TENC * DIM / 4);
    int stride = gridDim.x * blockDim.x;
    for (int i = blockIdx.x * blockDim.x + threadIdx.x; i < n4; i += stride) {
        float4 v = ((const float4*)x)[i];
        __nv_bfloat16 h0 = __float2bfloat16(v.x), h1 = __float2bfloat16(v.y);
        __nv_bfloat16 h2 = __float2bfloat16(v.z), h3 = __float2bfloat16(v.w);
        __nv_bfloat16 l0 = __float2bfloat16(v.x - __bfloat162float(h0));
        __nv_bfloat16 l1 = __float2bfloat16(v.y - __bfloat162float(h1));
        __nv_bfloat16 l2 = __float2bfloat16(v.z - __bfloat162float(h2));
        __nv_bfloat16 l3 = __float2bfloat16(v.w - __bfloat162float(h3));
        __nv_bfloat162 hA = {h0, h1}, hB = {h2, h3}, lA = {l0, l1}, lB = {l2, l3};
        uint2 hv = {*(uint32_t*)&hA, *(uint32_t*)&hB};
        uint2 lv = {*(uint32_t*)&lA, *(uint32_t*)&lB};
        ((uint2*)g_eh)[i] = hv;
        ((uint2*)g_el)[i] = lv;
        __half2 fA = {__float2half(v.x), __float2half(v.y)};
        __half2 fB = {__float2half(v.z), __float2half(v.w)};
        uint2 fv = {*(uint32_t*)&fA, *(uint32_t*)&fB};
        ((uint2*)g_ef)[i] = fv;
    }
}

__global__ void split_dec_kernel(const float* __restrict__ x)
{
    const int n4 = (int)((size_t)BATCH * TDEC * DIM / 4);
    int stride = gridDim.x * blockDim.x;
    for (int i = blockIdx.x * blockDim.x + threadIdx.x; i < n4; i += stride) {
        float4 v = ((const float4*)x)[i];
        __nv_bfloat16 h0 = __float2bfloat16(v.x), h1 = __float2bfloat16(v.y);
        __nv_bfloat16 h2 = __float2bfloat16(v.z), h3 = __float2bfloat16(v.w);
        __nv_bfloat16 l0 = __float2bfloat16(v.x - __bfloat162float(h0));
        __nv_bfloat16 l1 = __float2bfloat16(v.y - __bfloat162float(h1));
        __nv_bfloat16 l2 = __float2bfloat16(v.z - __bfloat162float(h2));
        __nv_bfloat16 l3 = __float2bfloat16(v.w - __bfloat162float(h3));
        __nv_bfloat162 hA = {h0, h1}, hB = {h2, h3}, lA = {l0, l1}, lB = {l2, l3};
        uint2 hv = {*(uint32_t*)&hA, *(uint32_t*)&hB};
        uint2 lv = {*(uint32_t*)&lA, *(uint32_t*)&lB};
        ((uint2*)g_dh)[i] = hv;
        ((uint2*)g_dl)[i] = lv;
    }
}

// ---------------------------------------------------------------------------
// GEMM1 (compact rows only) + fused softmax chunk partials.
// Computes logits for unmasked t rows, scattered to S via idx. No bias needed.
// ---------------------------------------------------------------------------
#define G1_BUF   10240
#define G1_STAGE (4 * G1_BUF)
#define G1_DYN   (4 * G1_STAGE + 1024)

__global__ __launch_bounds__(256, 1) void gemm1_kernel(float* __restrict__ S)
{
    const int b  = blockIdx.z;
    const int m0 = blockIdx.y * 128;   // compact row tile
    const int n0 = blockIdx.x * 128;   // u
    const int cnt = g_cnt[b];
    if (m0 >= cnt) return;

    extern __shared__ __align__(16) uint8_t dynsm[];
    const uint32_t dynb = (smem_u32(dynsm) + 1023u) & ~1023u;
    __shared__ float smax[2][128];
    __shared__ float ssum[2][128];

    const int* idxp = g_idx + b * TENC;
    const __nv_bfloat16* Ah = g_eh + (size_t)b * TENC * DIM;
    const __nv_bfloat16* Al = g_el + (size_t)b * TENC * DIM;
    const __nv_bfloat16* Bh = g_dh + (size_t)b * TDEC * DIM;
    const __nv_bfloat16* Bl = g_dl + (size_t)b * TDEC * DIM;
    float* Sp = S + (size_t)b * TENC * TDEC;

    const int tid  = threadIdx.x;
    const int lane = tid & 31;
    const int wid  = tid >> 5;
    const int m_off = (wid & 1) * 64;
    const int n_off = (wid >> 1) * 32;

    const int lrow = tid >> 2;
    const int lc   = tid & 3;
    // gather source rows (hoisted; idx 0-padded so always safe)
    const int tA0 = idxp[m0 + lrow];
    const int tA1 = idxp[m0 + lrow + 64];

    const uint32_t aBase = (uint32_t)((m_off + (lane & 15)) * 80 + (lane >> 4) * 16);
    const uint32_t bBase = (uint32_t)((n_off + (lane & 7) + ((lane >> 4) << 3)) * 80
                                      + ((lane >> 3) & 1) * 16);

    float acc[4][4][4];
    #pragma unroll
    for (int i = 0; i < 4; i++)
        #pragma unroll
        for (int j = 0; j < 4; j++)
            #pragma unroll
            for (int k = 0; k < 4; k++) acc[i][j][k] = 0.f;

    const int NST = DIM / 32;

    auto load_stage = [&](int s) {
        const int k0 = s * 32;
        const uint32_t sb = dynb + (uint32_t)(s & 3) * G1_STAGE;
        #pragma unroll
        for (int j = 0; j < 2; j++) {
            int row = lrow + j * 64;
            int t = j ? tA1 : tA0;
            uint32_t so = (uint32_t)(row * 80 + lc * 16);
            size_t goA = (size_t)t * DIM + k0 + lc * 8;
            size_t goB = (size_t)(n0 + row) * DIM + k0 + lc * 8;
            cpa16(sb + so,              Ah + goA);
            cpa16(sb + G1_BUF + so,     Al + goA);
            cpa16(sb + 2 * G1_BUF + so, Bh + goB);
            cpa16(sb + 3 * G1_BUF + so, Bl + goB);
        }
        cpa_commit();
    };

    load_stage(0);
    load_stage(1);
    load_stage(2);

    for (int s = 0; s < NST; s++) {
        if (s < NST - 2) cpa_wait2();
        else if (s == NST - 2) cpa_wait1();
        else cpa_wait0();
        __syncthreads();

        const uint32_t bAh = dynb + (uint32_t)(s & 3) * G1_STAGE;
        const uint32_t bAl = bAh + G1_BUF;
        const uint32_t bBh = bAh + 2 * G1_BUF;
        const uint32_t bBl = bAh + 3 * G1_BUF;

        #pragma unroll
        for (int ks = 0; ks < 2; ks++) {
            uint32_t koff = (uint32_t)(ks * 32);
            uint32_t ah[4][4], bh[2][4];
            #pragma unroll
            for (int im = 0; im < 4; im++) ldsm4(ah[im], bAh + aBase + im * 1280 + koff);
            #pragma unroll
            for (int p = 0; p < 2; p++)   ldsm4(bh[p], bBh + bBase + p * 1280 + koff);
            #pragma unroll
            for (int im = 0; im < 4; im++)
                #pragma unroll
                for (int in = 0; in < 4; in++)
                    mma_bf16(acc[im][in], ah[im], bh[in >> 1][(in & 1) * 2], bh[in >> 1][(in & 1) * 2 + 1]);

            uint32_t bl[2][4];
            #pragma unroll
            for (int p = 0; p < 2; p++) ldsm4(bl[p], bBl + bBase + p * 1280 + koff);
            #pragma unroll
            for (int im = 0; im < 4; im++)
                #pragma unroll
                for (int in = 0; in < 4; in++)
                    mma_bf16(acc[im][in], ah[im], bl[in >> 1][(in & 1) * 2], bl[in >> 1][(in & 1) * 2 + 1]);

            uint32_t al[4][4];
            #pragma unroll
            for (int im = 0; im < 4; im++) ldsm4(al[im], bAl + aBase + im * 1280 + koff);
            #pragma unroll
            for (int im = 0; im < 4; im++)
                #pragma unroll
                for (int in = 0; in < 4; in++)
                    mma_bf16(acc[im][in], al[im], bh[in >> 1][(in & 1) * 2], bh[in >> 1][(in & 1) * 2 + 1]);
        }
        if (s + 3 < NST) load_stage(s + 3);
    }

    // ---- epilogue: scatter S rows (valid only) + softmax partials
    bool ok0[4], ok1[4];
    int to0[4], to1[4];
    #pragma unroll
    for (int im = 0; im < 4; im++) {
        int r0 = m0 + m_off + im * 16 + (lane >> 2);
        int r1 = r0 + 8;
        ok0[im] = r0 < cnt;
        ok1[im] = r1 < cnt;
        to0[im] = idxp[r0];
        to1[im] = idxp[r1];
    }
    #pragma unroll
    for (int im = 0; im < 4; im++) {
        #pragma unroll
        for (int in = 0; in < 4; in++) {
            int col = n0 + n_off + in * 8 + (lane & 3) * 2;
            if (ok0[im]) *(float2*)&Sp[(size_t)to0[im] * TDEC + col] = *(float2*)&acc[im][in][0];
            if (ok1[im]) *(float2*)&Sp[(size_t)to1[im] * TDEC + col] = *(float2*)&acc[im][in][2];
        }
    }
    float umax[8];
    #pragma unroll
    for (int q = 0; q < 8; q++) umax[q] = -3.4e38f;
    #pragma unroll
    for (int im = 0; im < 4; im++)
        #pragma unroll
        for (int in = 0; in < 4; in++)
            #pragma unroll
            for (int j = 0; j < 2; j++) {
                if (ok0[im]) umax[in * 2 + j] = fmaxf(umax[in * 2 + j], acc[im][in][j]);
                if (ok1[im]) umax[in * 2 + j] = fmaxf(umax[in * 2 + j], acc[im][in][2 + j]);
            }
    #pragma unroll
    for (int msk = 4; msk <= 16; msk <<= 1)
        #pragma unroll
        for (int q = 0; q < 8; q++)
            umax[q] = fmaxf(umax[q], __shfl_xor_sync(0xffffffffu, umax[q], msk));
    float usum[8];
    #pragma unroll
    for (int q = 0; q < 8; q++) usum[q] = 0.f;
    #pragma unroll
    for (int im = 0; im < 4; im++)
        #pragma unroll
        for (int in = 0; in < 4; in++)
            #pragma unroll
            for (int j = 0; j < 2; j++) {
                usum[in * 2 + j] += ok0[im] ? __expf(acc[im][in][j]     - umax[in * 2 + j]) : 0.f;
                usum[in * 2 + j] += ok1[im] ? __expf(acc[im][in][2 + j] - umax[in * 2 + j]) : 0.f;
            }
    #pragma unroll
    for (int msk = 4; msk <= 16; msk <<= 1)
        #pragma unroll
        for (int q = 0; q < 8; q++)
            usum[q] += __shfl_xor_sync(0xffffffffu, usum[q], msk);
    if (lane < 4) {
        #pragma unroll
        for (int in = 0; in < 4; in++)
            #pragma unroll
            for (int j = 0; j < 2; j++) {
                int u = n_off + in * 8 + lane * 2 + j;
                smax[wid & 1][u] = umax[in * 2 + j];
                ssum[wid & 1][u] = usum[in * 2 + j];
            }
    }
    __syncthreads();
    if (tid < 128) {
        float m0v = smax[0][tid], m1v = smax[1][tid];
        float M = fmaxf(m0v, m1v);
        float Ssum = (m0v > -3.4e38f ? ssum[0][tid] * __expf(m0v - M) : 0.f)
                   + (m1v > -3.4e38f ? ssum[1][tid] * __expf(m1v - M) : 0.f);
        int idx = (b * 16 + blockIdx.y) * TDEC + n0 + tid;
        g_cm[idx] = M;
        g_cs[idx] = Ssum;
    }
}

// ---------------------------------------------------------------------------
// softmaxB: fold 16 chunk partials -> M[b,u], 1/S[b,u]
// ---------------------------------------------------------------------------
__global__ void softmaxB_kernel()
{
    int i = blockIdx.x * 256 + threadIdx.x;
    if (i >= BATCH * TDEC) return;
    int b = i / TDEC, u = i % TDEC;
    float M = -3.4e38f;
    #pragma unroll
    for (int c = 0; c < 16; c++) M = fmaxf(M, g_cm[(b * 16 + c) * TDEC + u]);
    float Ssum = 0.f;
    #pragma unroll
    for (int c = 0; c < 16; c++) {
        float cm = g_cm[(b * 16 + c) * TDEC + u];
        Ssum += (cm > -3.4e38f) ? g_cs[(b * 16 + c) * TDEC + u] * __expf(cm - M) : 0.f;
    }
    g_Mx[i] = M;
    g_Iv[i] = 1.0f / Ssum;
}

// ---------------------------------------------------------------------------
// softmaxC (row-coalesced): 8 t-rows/block. Masked rows -> S=0 (exact).
// Unmasked rows -> normalize, write f32 S + compact fp16 at rank[t].
// ---------------------------------------------------------------------------
__global__ __launch_bounds__(256) void softmaxC_kernel(
    float* __restrict__ S, const int* __restrict__ mask)
{
    const int b  = blockIdx.y;
    const int t0 = blockIdx.x * 8;
    const int tid = threadIdx.x;

    __shared__ float sM[TDEC], sI[TDEC];
    __shared__ int smk[8], srk[8];
    if (tid < 8) {
        smk[tid] = mask[b * TENC + t0 + tid];
        srk[tid] = g_rank[b * TENC + t0 + tid];
    }
    for (int i = tid; i < TDEC; i += 256) {
        sM[i] = g_Mx[b * TDEC + i];
        sI[i] = g_Iv[b * TDEC + i];
    }
    __syncthreads();

    #pragma unroll
    for (int slot = tid; slot < 1024; slot += 256) {
        int row = slot >> 7;
        int u4  = slot & 127;
        int u   = u4 * 4;
        size_t idx = ((size_t)b * TENC + t0 + row) * TDEC + u;
        if (smk[row]) {
            float4 v = *(float4*)&S[idx];
            v.x = __expf(v.x - sM[u + 0]) * sI[u + 0];
            v.y = __expf(v.y - sM[u + 1]) * sI[u + 1];
            v.z = __expf(v.z - sM[u + 2]) * sI[u + 2];
            v.w = __expf(v.w - sM[u + 3]) * sI[u + 3];
            *(float4*)&S[idx] = v;
            __half2 h01 = {__float2half(v.x), __float2half(v.y)};
            __half2 h23 = {__float2half(v.z), __float2half(v.w)};
            uint2 hv = {*(uint32_t*)&h01, *(uint32_t*)&h23};
            *(uint2*)&g_pc[((size_t)b * TENC + srk[row]) * TDEC + u] = hv;
        } else {
            float4 z = {0.f, 0.f, 0.f, 0.f};
            *(float4*)&S[idx] = z;
        }
    }
}

// ---------------------------------------------------------------------------
// GEMM2 (fp16 single pass, compact K): ctx[b,u,d] = sum_j pc[j,u]*enc[idx[j],d]
// BM=128(u), BN=128(d), BK=32. K runs to cnt32 only. 4-deep ring, 2 CTAs/SM.
// ---------------------------------------------------------------------------
#define G2_BUF   8704             // 32 rows * 272 B
#define G2_STAGE (2 * G2_BUF)     // Pc, Ef
#define G2_DYN   (4 * G2_STAGE + 1024)

__global__ __launch_bounds__(256, 2) void gemm2_kernel(float* __restrict__ ctx)
{
    extern __shared__ __align__(16) uint8_t dynsm[];
    const uint32_t dynb = (smem_u32(dynsm) + 1023u) & ~1023u;

    const int b  = blockIdx.z;
    const int u0 = blockIdx.y * 128;
    const int d0 = blockIdx.x * 128;
    const int cnt = g_cnt[b];
    const int NST = (cnt + 31) >> 5;

    const int* idxp = g_idx + b * TENC;
    const __half* Pc = g_pc + (size_t)b * TENC * TDEC;
    const __half* Ef = g_ef + (size_t)b * TENC * DIM;
    float* C = ctx + (size_t)b * TDEC * DIM;

    const int tid  = threadIdx.x;
    const int lane = tid & 31;
    const int wid  = tid >> 5;
    const int m_off = (wid & 1) * 64;   // u
    const int n_off = (wid >> 1) * 32;  // d

    const int lrow = tid >> 4;   // 0..15 (+16)
    const int lc   = tid & 15;

    const uint32_t aBase = (uint32_t)(((lane & 7) + ((lane >> 4) << 3)) * 272
                                      + (m_off + ((lane >> 3) & 1) * 8) * 2);
    const uint32_t bBase = (uint32_t)(((lane & 7) + (((lane >> 3) & 1) << 3)) * 272
                                      + (n_off + (lane >> 4) * 8) * 2);

    float acc[4][4][4];
    #pragma unroll
    for (int i = 0; i < 4; i++)
        #pragma unroll
        for (int j = 0; j < 4; j++)
            #pragma unroll
            for (int k = 0; k < 4; k++) acc[i][j][k] = 0.f;

    auto load_stage = [&](int s) {
        const int k0 = s * 32;
        const uint32_t sb = dynb + (uint32_t)(s & 3) * G2_STAGE;
        #pragma unroll
        for (int j = 0; j < 2; j++) {
            int row = lrow + j * 16;
            int t = idxp[k0 + row];     // gather enc row (0-padded past cnt)
            uint32_t so = (uint32_t)(row * 272 + lc * 16);
            size_t goP = (size_t)(k0 + row) * TDEC + u0 + lc * 8;
            size_t goE = (size_t)t * DIM + d0 + lc * 8;
            cpa16(sb + so,          Pc + goP);
            cpa16(sb + G2_BUF + so, Ef + goE);
        }
        cpa_commit();
    };

    const int pre = NST < 3 ? NST : 3;
    for (int s = 0; s < pre; s++) load_stage(s);

    for (int s = 0; s < NST; s++) {
        int out = NST - s - 1; if (out > 2) out = 2;
        if (out == 2) cpa_wait2();
        else if (out == 1) cpa_wait1();
        else cpa_wait0();
        __syncthreads();

        const uint32_t bPh = dynb + (uint32_t)(s & 3) * G2_STAGE;
        const uint32_t bEf = bPh + G2_BUF;

        #pragma unroll
        for (int ks = 0; ks < 2; ks++) {
            uint32_t koff = (uint32_t)(ks * 16 * 272);
            uint32_t ah[4][4], bh[2][4];
            #pragma unroll
            for (int im = 0; im < 4; im++) ldsm4t(ah[im], bPh + aBase + im * 32 + koff);
            #pragma unroll
            for (int p = 0; p < 2; p++)   ldsm4t(bh[p], bEf + bBase + p * 32 + koff);
            #pragma unroll
            for (int im = 0; im < 4; im++)
                #pragma unroll
                for (int in = 0; in < 4; in++)
                    mma_fp16(acc[im][in], ah[im], bh[in >> 1][(in & 1) * 2], bh[in >> 1][(in & 1) * 2 + 1]);
        }
        if (s + 3 < NST) load_stage(s + 3);
    }

    #pragma unroll
    for (int im = 0; im < 4; im++) {
        int ur = u0 + m_off + im * 16 + (lane >> 2);
        #pragma unroll
        for (int in = 0; in < 4; in++) {
            int col = d0 + n_off + in * 8 + (lane & 3) * 2;
            float2 v0 = {acc[im][in][0], acc[im][in][1]};
            float2 v1 = {acc[im][in][2], acc[im][in][3]};
            *(float2*)&C[(size_t)ur * DIM + col]       = v0;
            *(float2*)&C[(size_t)(ur + 8) * DIM + col] = v1;
        }
    }
}

// ---------------------------------------------------------------------------
extern "C" void kernel_launch(void* const* d_in, const int* in_sizes, int n_in,
                              void* d_out, int out_size)
{
    const float* enc      = (const float*)d_in[0];
    const int*   enc_mask = (const int*)  d_in[1];
    const float* dec      = (const float*)d_in[2];

    float* ctx = (float*)d_out;                      // [B, TDEC, DIM]
    float* S   = ctx + (size_t)BATCH * TDEC * DIM;   // [B, TENC, TDEC]

    cudaFuncSetAttribute(gemm1_kernel, cudaFuncAttributeMaxDynamicSharedMemorySize, G1_DYN);
    cudaFuncSetAttribute(gemm2_kernel, cudaFuncAttributeMaxDynamicSharedMemorySize, G2_DYN);

    compact_kernel<<<BATCH, 1024>>>(enc_mask);
    split_enc_kernel<<<1024, 256>>>(enc);
    split_dec_kernel<<<512, 256>>>(dec);

    gemm1_kernel<<<dim3(TDEC / 128, TENC / 128, BATCH), 256, G1_DYN>>>(S);

    softmaxB_kernel<<<(BATCH * TDEC + 255) / 256, 256>>>();
    softmaxC_kernel<<<dim3(TENC / 8, BATCH), 256>>>(S, enc_mask);

    gemm2_kernel<<<dim3(DIM / 128, TDEC / 128, BATCH), 256, G2_DYN>>>(ctx);
}

// round 14
// speedup vs baseline: 1.8782x; 1.3856x over previous
#include <cuda_runtime.h>
#include <cuda_bf16.h>
#include <cuda_fp16.h>
#include <cstdint>
#include <cstddef>

#define BATCH 8
#define TENC 2048
#define TDEC 512
#define DIM  1024

// ---------------------------------------------------------------------------
// Scratch (static device arrays — no allocation allowed)
// ---------------------------------------------------------------------------
__device__ __nv_bfloat16 g_eh[(size_t)BATCH * TENC * DIM];   // enc hi bf16 [b][t][d]
__device__ __nv_bfloat16 g_el[(size_t)BATCH * TENC * DIM];   // enc lo bf16
__device__ __half        g_ef[(size_t)BATCH * TENC * DIM];   // enc fp16 (gemm2)
__device__ __nv_bfloat16 g_dh[(size_t)BATCH * TDEC * DIM];   // dec hi bf16 [b][u][d]
__device__ __nv_bfloat16 g_dl[(size_t)BATCH * TDEC * DIM];   // dec lo bf16
__device__ __half        g_pc[(size_t)BATCH * TENC * TDEC];  // COMPACT scores fp16 [b][j][u]
// mask compaction
__device__ int g_idx[BATCH * TENC];    // compact j -> t  (0-padded past cnt)
__device__ int g_rank[BATCH * TENC];   // t -> compact j  (valid where mask=1)
__device__ int g_cnt[BATCH];
// softmax partials: 16 compact chunks of 128
__device__ float g_cm[BATCH * 16 * TDEC];
__device__ float g_cs[BATCH * 16 * TDEC];
__device__ float g_Mx[BATCH * TDEC];
__device__ float g_Iv[BATCH * TDEC];

// ---------------------------------------------------------------------------
// helpers
// ---------------------------------------------------------------------------
__device__ __forceinline__ uint32_t smem_u32(const void* p) {
    return (uint32_t)__cvta_generic_to_shared(p);
}
__device__ __forceinline__ void cpa16(uint32_t s, const void* g) {
    asm volatile("cp.async.cg.shared.global [%0], [%1], 16;\n" :: "r"(s), "l"(g));
}
__device__ __forceinline__ void cpa_commit() {
    asm volatile("cp.async.commit_group;\n");
}
__device__ __forceinline__ void cpa_wait2() { asm volatile("cp.async.wait_group 2;\n"); }
__device__ __forceinline__ void cpa_wait1() { asm volatile("cp.async.wait_group 1;\n"); }
__device__ __forceinline__ void cpa_wait0() { asm volatile("cp.async.wait_group 0;\n"); }
__device__ __forceinline__ void ldsm4(uint32_t* r, uint32_t a) {
    asm volatile("ldmatrix.sync.aligned.m8n8.x4.shared.b16 {%0,%1,%2,%3}, [%4];\n"
                 : "=r"(r[0]), "=r"(r[1]), "=r"(r[2]), "=r"(r[3]) : "r"(a));
}
__device__ __forceinline__ void ldsm4t(uint32_t* r, uint32_t a) {
    asm volatile("ldmatrix.sync.aligned.m8n8.x4.trans.shared.b16 {%0,%1,%2,%3}, [%4];\n"
                 : "=r"(r[0]), "=r"(r[1]), "=r"(r[2]), "=r"(r[3]) : "r"(a));
}
__device__ __forceinline__ void mma_bf16(float* c, const uint32_t* a, uint32_t b0, uint32_t b1) {
    asm volatile(
        "mma.sync.aligned.m16n8k16.row.col.f32.bf16.bf16.f32 "
        "{%0,%1,%2,%3},{%4,%5,%6,%7},{%8,%9},{%0,%1,%2,%3};\n"
        : "+f"(c[0]), "+f"(c[1]), "+f"(c[2]), "+f"(c[3])
        : "r"(a[0]), "r"(a[1]), "r"(a[2]), "r"(a[3]), "r"(b0), "r"(b1));
}
__device__ __forceinline__ void mma_fp16(float* c, const uint32_t* a, uint32_t b0, uint32_t b1) {
    asm volatile(
        "mma.sync.aligned.m16n8k16.row.col.f32.f16.f16.f32 "
        "{%0,%1,%2,%3},{%4,%5,%6,%7},{%8,%9},{%0,%1,%2,%3};\n"
        : "+f"(c[0]), "+f"(c[1]), "+f"(c[2]), "+f"(c[3])
        : "r"(a[0]), "r"(a[1]), "r"(a[2]), "r"(a[3]), "r"(b0), "r"(b1));
}

// ---------------------------------------------------------------------------
// compact: per batch, prefix-scan mask; init partials; zero-pad compact rows
// ---------------------------------------------------------------------------
__global__ __launch_bounds__(1024) void compact_kernel(const int* __restrict__ mask)
{
    const int b   = blockIdx.x;
    const int tid = threadIdx.x;       // 1024
    const int lane = tid & 31, wid = tid >> 5;
    const int* m = mask + b * TENC;

    int v0 = m[2 * tid], v1 = m[2 * tid + 1];
    int s = v0 + v1;
    int x = s;
    #pragma unroll
    for (int o = 1; o < 32; o <<= 1) {
        int y = __shfl_up_sync(0xffffffffu, x, o);
        if (lane >= o) x += y;
    }
    __shared__ int wsum[32], wscan[32];
    if (lane == 31) wsum[wid] = x;
    __syncthreads();
    if (wid == 0) {
        int w = wsum[lane];
        #pragma unroll
        for (int o = 1; o < 32; o <<= 1) {
            int y = __shfl_up_sync(0xffffffffu, w, o);
            if (lane >= o) w += y;
        }
        wscan[lane] = w;
    }
    __syncthreads();
    int excl = x - s + (wid > 0 ? wscan[wid - 1] : 0);
    int p = excl;
    if (v0) { g_idx[b * TENC + p] = 2 * tid;     g_rank[b * TENC + 2 * tid]     = p; p++; }
    if (v1) { g_idx[b * TENC + p] = 2 * tid + 1; g_rank[b * TENC + 2 * tid + 1] = p; }
    const int total = wscan[31];
    if (tid == 0) g_cnt[b] = total;
    __syncthreads();

    for (int j = tid; j < TENC; j += 1024)
        if (j >= total) g_idx[b * TENC + j] = 0;
    for (int i = tid; i < 16 * TDEC; i += 1024) {
        g_cm[b * 16 * TDEC + i] = -3.4e38f;
        g_cs[b * 16 * TDEC + i] = 0.f;
    }
    const int cnt32 = (total + 31) & ~31;
    const int padn = (cnt32 - total) * TDEC;
    __half zh = __float2half(0.f);
    for (int i = tid; i < padn; i += 1024) {
        int r = total + i / TDEC, u = i % TDEC;
        g_pc[((size_t)b * TENC + r) * TDEC + u] = zh;
    }
}

// ---------------------------------------------------------------------------
// enc split: f32 -> bf16 hi/lo + fp16 copy
// ---------------------------------------------------------------------------
__global__ void split_enc_kernel(const float* __restrict__ x)
{
    const int n4 = (int)((size_t)BATCH * TENC * DIM / 4);
    int stride = gridDim.x * blockDim.x;
    for (int i = blockIdx.x * blockDim.x + threadIdx.x; i < n4; i += stride) {
        float4 v = ((const float4*)x)[i];
        __nv_bfloat16 h0 = __float2bfloat16(v.x), h1 = __float2bfloat16(v.y);
        __nv_bfloat16 h2 = __float2bfloat16(v.z), h3 = __float2bfloat16(v.w);
        __nv_bfloat16 l0 = __float2bfloat16(v.x - __bfloat162float(h0));
        __nv_bfloat16 l1 = __float2bfloat16(v.y - __bfloat162float(h1));
        __nv_bfloat16 l2 = __float2bfloat16(v.z - __bfloat162float(h2));
        __nv_bfloat16 l3 = __float2bfloat16(v.w - __bfloat162float(h3));
        __nv_bfloat162 hA = {h0, h1}, hB = {h2, h3}, lA = {l0, l1}, lB = {l2, l3};
        uint2 hv = {*(uint32_t*)&hA, *(uint32_t*)&hB};
        uint2 lv = {*(uint32_t*)&lA, *(uint32_t*)&lB};
        ((uint2*)g_eh)[i] = hv;
        ((uint2*)g_el)[i] = lv;
        __half2 fA = {__float2half(v.x), __float2half(v.y)};
        __half2 fB = {__float2half(v.z), __float2half(v.w)};
        uint2 fv = {*(uint32_t*)&fA, *(uint32_t*)&fB};
        ((uint2*)g_ef)[i] = fv;
    }
}

__global__ void split_dec_kernel(const float* __restrict__ x)
{
    const int n4 = (int)((size_t)BATCH * TDEC * DIM / 4);
    int stride = gridDim.x * blockDim.x;
    for (int i = blockIdx.x * blockDim.x + threadIdx.x; i < n4; i += stride) {
        float4 v = ((const float4*)x)[i];
        __nv_bfloat16 h0 = __float2bfloat16(v.x), h1 = __float2bfloat16(v.y);
        __nv_bfloat16 h2 = __float2bfloat16(v.z), h3 = __float2bfloat16(v.w);
        __nv_bfloat16 l0 = __float2bfloat16(v.x - __bfloat162float(h0));
        __nv_bfloat16 l1 = __float2bfloat16(v.y - __bfloat162float(h1));
        __nv_bfloat16 l2 = __float2bfloat16(v.z - __bfloat162float(h2));
        __nv_bfloat16 l3 = __float2bfloat16(v.w - __bfloat162float(h3));
        __nv_bfloat162 hA = {h0, h1}, hB = {h2, h3}, lA = {l0, l1}, lB = {l2, l3};
        uint2 hv = {*(uint32_t*)&hA, *(uint32_t*)&hB};
        uint2 lv = {*(uint32_t*)&lA, *(uint32_t*)&lB};
        ((uint2*)g_dh)[i] = hv;
        ((uint2*)g_dl)[i] = lv;
    }
}

// ---------------------------------------------------------------------------
// GEMM1 (compact rows only) + fused softmax chunk partials.
// 2-stage cp.async ring, 2 CTAs/SM: ~256 active CTAs fit one wave.
// ---------------------------------------------------------------------------
#define G1_BUF   10240
#define G1_STAGE (4 * G1_BUF)
#define G1_DYN   (2 * G1_STAGE + 1024)

__global__ __launch_bounds__(256, 2) void gemm1_kernel(float* __restrict__ S)
{
    const int b  = blockIdx.z;
    const int m0 = blockIdx.y * 128;   // compact row tile
    const int n0 = blockIdx.x * 128;   // u
    const int cnt = g_cnt[b];
    if (m0 >= cnt) return;

    extern __shared__ __align__(16) uint8_t dynsm[];
    const uint32_t dynb = (smem_u32(dynsm) + 1023u) & ~1023u;
    __shared__ float smax[2][128];
    __shared__ float ssum[2][128];

    const int* idxp = g_idx + b * TENC;
    const __nv_bfloat16* Ah = g_eh + (size_t)b * TENC * DIM;
    const __nv_bfloat16* Al = g_el + (size_t)b * TENC * DIM;
    const __nv_bfloat16* Bh = g_dh + (size_t)b * TDEC * DIM;
    const __nv_bfloat16* Bl = g_dl + (size_t)b * TDEC * DIM;
    float* Sp = S + (size_t)b * TENC * TDEC;

    const int tid  = threadIdx.x;
    const int lane = tid & 31;
    const int wid  = tid >> 5;
    const int m_off = (wid & 1) * 64;
    const int n_off = (wid >> 1) * 32;

    const int lrow = tid >> 2;
    const int lc   = tid & 3;
    const int tA0 = idxp[m0 + lrow];
    const int tA1 = idxp[m0 + lrow + 64];

    const uint32_t aBase = (uint32_t)((m_off + (lane & 15)) * 80 + (lane >> 4) * 16);
    const uint32_t bBase = (uint32_t)((n_off + (lane & 7) + ((lane >> 4) << 3)) * 80
                                      + ((lane >> 3) & 1) * 16);

    float acc[4][4][4];
    #pragma unroll
    for (int i = 0; i < 4; i++)
        #pragma unroll
        for (int j = 0; j < 4; j++)
            #pragma unroll
            for (int k = 0; k < 4; k++) acc[i][j][k] = 0.f;

    const int NST = DIM / 32;

    auto load_stage = [&](int s) {
        const int k0 = s * 32;
        const uint32_t sb = dynb + (uint32_t)(s & 1) * G1_STAGE;
        #pragma unroll
        for (int j = 0; j < 2; j++) {
            int row = lrow + j * 64;
            int t = j ? tA1 : tA0;
            uint32_t so = (uint32_t)(row * 80 + lc * 16);
            size_t goA = (size_t)t * DIM + k0 + lc * 8;
            size_t goB = (size_t)(n0 + row) * DIM + k0 + lc * 8;
            cpa16(sb + so,              Ah + goA);
            cpa16(sb + G1_BUF + so,     Al + goA);
            cpa16(sb + 2 * G1_BUF + so, Bh + goB);
            cpa16(sb + 3 * G1_BUF + so, Bl + goB);
        }
        cpa_commit();
    };

    load_stage(0);
    load_stage(1);

    for (int s = 0; s < NST; s++) {
        if (s < NST - 1) cpa_wait1(); else cpa_wait0();
        __syncthreads();

        const uint32_t bAh = dynb + (uint32_t)(s & 1) * G1_STAGE;
        const uint32_t bAl = bAh + G1_BUF;
        const uint32_t bBh = bAh + 2 * G1_BUF;
        const uint32_t bBl = bAh + 3 * G1_BUF;

        #pragma unroll
        for (int ks = 0; ks < 2; ks++) {
            uint32_t koff = (uint32_t)(ks * 32);
            uint32_t ah[4][4], bh[2][4];
            #pragma unroll
            for (int im = 0; im < 4; im++) ldsm4(ah[im], bAh + aBase + im * 1280 + koff);
            #pragma unroll
            for (int p = 0; p < 2; p++)   ldsm4(bh[p], bBh + bBase + p * 1280 + koff);
            #pragma unroll
            for (int im = 0; im < 4; im++)
                #pragma unroll
                for (int in = 0; in < 4; in++)
                    mma_bf16(acc[im][in], ah[im], bh[in >> 1][(in & 1) * 2], bh[in >> 1][(in & 1) * 2 + 1]);

            uint32_t bl[2][4];
            #pragma unroll
            for (int p = 0; p < 2; p++) ldsm4(bl[p], bBl + bBase + p * 1280 + koff);
            #pragma unroll
            for (int im = 0; im < 4; im++)
                #pragma unroll
                for (int in = 0; in < 4; in++)
                    mma_bf16(acc[im][in], ah[im], bl[in >> 1][(in & 1) * 2], bl[in >> 1][(in & 1) * 2 + 1]);

            uint32_t al[4][4];
            #pragma unroll
            for (int im = 0; im < 4; im++) ldsm4(al[im], bAl + aBase + im * 1280 + koff);
            #pragma unroll
            for (int im = 0; im < 4; im++)
                #pragma unroll
                for (int in = 0; in < 4; in++)
                    mma_bf16(acc[im][in], al[im], bh[in >> 1][(in & 1) * 2], bh[in >> 1][(in & 1) * 2 + 1]);
        }
        __syncthreads();
        if (s + 2 < NST) load_stage(s + 2);
    }

    // ---- epilogue: scatter S rows (valid only) + softmax partials
    bool ok0[4], ok1[4];
    int to0[4], to1[4];
    #pragma unroll
    for (int im = 0; im < 4; im++) {
        int r0 = m0 + m_off + im * 16 + (lane >> 2);
        int r1 = r0 + 8;
        ok0[im] = r0 < cnt;
        ok1[im] = r1 < cnt;
        to0[im] = idxp[r0];
        to1[im] = idxp[r1];
    }
    #pragma unroll
    for (int im = 0; im < 4; im++) {
        #pragma unroll
        for (int in = 0; in < 4; in++) {
            int col = n0 + n_off + in * 8 + (lane & 3) * 2;
            if (ok0[im]) *(float2*)&Sp[(size_t)to0[im] * TDEC + col] = *(float2*)&acc[im][in][0];
            if (ok1[im]) *(float2*)&Sp[(size_t)to1[im] * TDEC + col] = *(float2*)&acc[im][in][2];
        }
    }
    float umax[8];
    #pragma unroll
    for (int q = 0; q < 8; q++) umax[q] = -3.4e38f;
    #pragma unroll
    for (int im = 0; im < 4; im++)
        #pragma unroll
        for (int in = 0; in < 4; in++)
            #pragma unroll
            for (int j = 0; j < 2; j++) {
                if (ok0[im]) umax[in * 2 + j] = fmaxf(umax[in * 2 + j], acc[im][in][j]);
                if (ok1[im]) umax[in * 2 + j] = fmaxf(umax[in * 2 + j], acc[im][in][2 + j]);
            }
    #pragma unroll
    for (int msk = 4; msk <= 16; msk <<= 1)
        #pragma unroll
        for (int q = 0; q < 8; q++)
            umax[q] = fmaxf(umax[q], __shfl_xor_sync(0xffffffffu, umax[q], msk));
    float usum[8];
    #pragma unroll
    for (int q = 0; q < 8; q++) usum[q] = 0.f;
    #pragma unroll
    for (int im = 0; im < 4; im++)
        #pragma unroll
        for (int in = 0; in < 4; in++)
            #pragma unroll
            for (int j = 0; j < 2; j++) {
                usum[in * 2 + j] += ok0[im] ? __expf(acc[im][in][j]     - umax[in * 2 + j]) : 0.f;
                usum[in * 2 + j] += ok1[im] ? __expf(acc[im][in][2 + j] - umax[in * 2 + j]) : 0.f;
            }
    #pragma unroll
    for (int msk = 4; msk <= 16; msk <<= 1)
        #pragma unroll
        for (int q = 0; q < 8; q++)
            usum[q] += __shfl_xor_sync(0xffffffffu, usum[q], msk);
    if (lane < 4) {
        #pragma unroll
        for (int in = 0; in < 4; in++)
            #pragma unroll
            for (int j = 0; j < 2; j++) {
                int u = n_off + in * 8 + lane * 2 + j;
                smax[wid & 1][u] = umax[in * 2 + j];
                ssum[wid & 1][u] = usum[in * 2 + j];
            }
    }
    __syncthreads();
    if (tid < 128) {
        float m0v = smax[0][tid], m1v = smax[1][tid];
        float M = fmaxf(m0v, m1v);
        float Ssum = (m0v > -3.4e38f ? ssum[0][tid] * __expf(m0v - M) : 0.f)
                   + (m1v > -3.4e38f ? ssum[1][tid] * __expf(m1v - M) : 0.f);
        int idx = (b * 16 + blockIdx.y) * TDEC + n0 + tid;
        g_cm[idx] = M;
        g_cs[idx] = Ssum;
    }
}

// ---------------------------------------------------------------------------
// softmaxB: fold 16 chunk partials -> M[b,u], 1/S[b,u]
// ---------------------------------------------------------------------------
__global__ void softmaxB_kernel()
{
    int i = blockIdx.x * 256 + threadIdx.x;
    if (i >= BATCH * TDEC) return;
    int b = i / TDEC, u = i % TDEC;
    float M = -3.4e38f;
    #pragma unroll
    for (int c = 0; c < 16; c++) M = fmaxf(M, g_cm[(b * 16 + c) * TDEC + u]);
    float Ssum = 0.f;
    #pragma unroll
    for (int c = 0; c < 16; c++) {
        float cm = g_cm[(b * 16 + c) * TDEC + u];
        Ssum += (cm > -3.4e38f) ? g_cs[(b * 16 + c) * TDEC + u] * __expf(cm - M) : 0.f;
    }
    g_Mx[i] = M;
    g_Iv[i] = 1.0f / Ssum;
}

// ---------------------------------------------------------------------------
// softmaxC (row-coalesced): 8 t-rows/block. Masked rows -> S=0 (exact).
// ---------------------------------------------------------------------------
__global__ __launch_bounds__(256) void softmaxC_kernel(
    float* __restrict__ S, const int* __restrict__ mask)
{
    const int b  = blockIdx.y;
    const int t0 = blockIdx.x * 8;
    const int tid = threadIdx.x;

    __shared__ float sM[TDEC], sI[TDEC];
    __shared__ int smk[8], srk[8];
    if (tid < 8) {
        smk[tid] = mask[b * TENC + t0 + tid];
        srk[tid] = g_rank[b * TENC + t0 + tid];
    }
    for (int i = tid; i < TDEC; i += 256) {
        sM[i] = g_Mx[b * TDEC + i];
        sI[i] = g_Iv[b * TDEC + i];
    }
    __syncthreads();

    #pragma unroll
    for (int slot = tid; slot < 1024; slot += 256) {
        int row = slot >> 7;
        int u4  = slot & 127;
        int u   = u4 * 4;
        size_t idx = ((size_t)b * TENC + t0 + row) * TDEC + u;
        if (smk[row]) {
            float4 v = *(float4*)&S[idx];
            v.x = __expf(v.x - sM[u + 0]) * sI[u + 0];
            v.y = __expf(v.y - sM[u + 1]) * sI[u + 1];
            v.z = __expf(v.z - sM[u + 2]) * sI[u + 2];
            v.w = __expf(v.w - sM[u + 3]) * sI[u + 3];
            *(float4*)&S[idx] = v;
            __half2 h01 = {__float2half(v.x), __float2half(v.y)};
            __half2 h23 = {__float2half(v.z), __float2half(v.w)};
            uint2 hv = {*(uint32_t*)&h01, *(uint32_t*)&h23};
            *(uint2*)&g_pc[((size_t)b * TENC + srk[row]) * TDEC + u] = hv;
        } else {
            float4 z = {0.f, 0.f, 0.f, 0.f};
            *(float4*)&S[idx] = z;
        }
    }
}

// ---------------------------------------------------------------------------
// GEMM2 (fp16 single pass, compact K): ctx[b,u,d] = sum_j pc[j,u]*enc[idx[j],d]
// BM=128(u), BN=128(d), BK=32. K runs to cnt32 only. 4-deep ring, 2 CTAs/SM.
// ---------------------------------------------------------------------------
#define G2_BUF   8704             // 32 rows * 272 B
#define G2_STAGE (2 * G2_BUF)     // Pc, Ef
#define G2_DYN   (4 * G2_STAGE + 1024)

__global__ __launch_bounds__(256, 2) void gemm2_kernel(float* __restrict__ ctx)
{
    extern __shared__ __align__(16) uint8_t dynsm[];
    const uint32_t dynb = (smem_u32(dynsm) + 1023u) & ~1023u;

    const int b  = blockIdx.z;
    const int u0 = blockIdx.y * 128;
    const int d0 = blockIdx.x * 128;
    const int cnt = g_cnt[b];
    const int NST = (cnt + 31) >> 5;

    const int* idxp = g_idx + b * TENC;
    const __half* Pc = g_pc + (size_t)b * TENC * TDEC;
    const __half* Ef = g_ef + (size_t)b * TENC * DIM;
    float* C = ctx + (size_t)b * TDEC * DIM;

    const int tid  = threadIdx.x;
    const int lane = tid & 31;
    const int wid  = tid >> 5;
    const int m_off = (wid & 1) * 64;   // u
    const int n_off = (wid >> 1) * 32;  // d

    const int lrow = tid >> 4;   // 0..15 (+16)
    const int lc   = tid & 15;

    const uint32_t aBase = (uint32_t)(((lane & 7) + ((lane >> 4) << 3)) * 272
                                      + (m_off + ((lane >> 3) & 1) * 8) * 2);
    const uint32_t bBase = (uint32_t)(((lane & 7) + (((lane >> 3) & 1) << 3)) * 272
                                      + (n_off + (lane >> 4) * 8) * 2);

    float acc[4][4][4];
    #pragma unroll
    for (int i = 0; i < 4; i++)
        #pragma unroll
        for (int j = 0; j < 4; j++)
            #pragma unroll
            for (int k = 0; k < 4; k++) acc[i][j][k] = 0.f;

    auto load_stage = [&](int s) {
        const int k0 = s * 32;
        const uint32_t sb = dynb + (uint32_t)(s & 3) * G2_STAGE;
        #pragma unroll
        for (int j = 0; j < 2; j++) {
            int row = lrow + j * 16;
            int t = idxp[k0 + row];
            uint32_t so = (uint32_t)(row * 272 + lc * 16);
            size_t goP = (size_t)(k0 + row) * TDEC + u0 + lc * 8;
            size_t goE = (size_t)t * DIM + d0 + lc * 8;
            cpa16(sb + so,          Pc + goP);
            cpa16(sb + G2_BUF + so, Ef + goE);
        }
        cpa_commit();
    };

    const int pre = NST < 3 ? NST : 3;
    for (int s = 0; s < pre; s++) load_stage(s);

    for (int s = 0; s < NST; s++) {
        int out = NST - s - 1; if (out > 2) out = 2;
        if (out == 2) cpa_wait2();
        else if (out == 1) cpa_wait1();
        else cpa_wait0();
        __syncthreads();

        const uint32_t bPh = dynb + (uint32_t)(s & 3) * G2_STAGE;
        const uint32_t bEf = bPh + G2_BUF;

        #pragma unroll
        for (int ks = 0; ks < 2; ks++) {
            uint32_t koff = (uint32_t)(ks * 16 * 272);
            uint32_t ah[4][4], bh[2][4];
            #pragma unroll
            for (int im = 0; im < 4; im++) ldsm4t(ah[im], bPh + aBase + im * 32 + koff);
            #pragma unroll
            for (int p = 0; p < 2; p++)   ldsm4t(bh[p], bEf + bBase + p * 32 + koff);
            #pragma unroll
            for (int im = 0; im < 4; im++)
                #pragma unroll
                for (int in = 0; in < 4; in++)
                    mma_fp16(acc[im][in], ah[im], bh[in >> 1][(in & 1) * 2], bh[in >> 1][(in & 1) * 2 + 1]);
        }
        if (s + 3 < NST) load_stage(s + 3);
    }

    #pragma unroll
    for (int im = 0; im < 4; im++) {
        int ur = u0 + m_off + im * 16 + (lane >> 2);
        #pragma unroll
        for (int in = 0; in < 4; in++) {
            int col = d0 + n_off + in * 8 + (lane & 3) * 2;
            float2 v0 = {acc[im][in][0], acc[im][in][1]};
            float2 v1 = {acc[im][in][2], acc[im][in][3]};
            *(float2*)&C[(size_t)ur * DIM + col]       = v0;
            *(float2*)&C[(size_t)(ur + 8) * DIM + col] = v1;
        }
    }
}

// ---------------------------------------------------------------------------
extern "C" void kernel_launch(void* const* d_in, const int* in_sizes, int n_in,
                              void* d_out, int out_size)
{
    const float* enc      = (const float*)d_in[0];
    const int*   enc_mask = (const int*)  d_in[1];
    const float* dec      = (const float*)d_in[2];

    float* ctx = (float*)d_out;                      // [B, TDEC, DIM]
    float* S   = ctx + (size_t)BATCH * TDEC * DIM;   // [B, TENC, TDEC]

    cudaFuncSetAttribute(gemm1_kernel, cudaFuncAttributeMaxDynamicSharedMemorySize, G1_DYN);
    cudaFuncSetAttribute(gemm2_kernel, cudaFuncAttributeMaxDynamicSharedMemorySize, G2_DYN);

    compact_kernel<<<BATCH, 1024>>>(enc_mask);
    split_enc_kernel<<<1024, 256>>>(enc);
    split_dec_kernel<<<512, 256>>>(dec);

    gemm1_kernel<<<dim3(TDEC / 128, TENC / 128, BATCH), 256, G1_DYN>>>(S);

    softmaxB_kernel<<<(BATCH * TDEC + 255) / 256, 256>>>();
    softmaxC_kernel<<<dim3(TENC / 8, BATCH), 256>>>(S, enc_mask);

    gemm2_kernel<<<dim3(DIM / 128, TDEC / 128, BATCH), 256, G2_DYN>>>(ctx);
}

// round 16
// speedup vs baseline: 2.1125x; 1.1248x over previous
#include <cuda_runtime.h>
#include <cuda_bf16.h>
#include <cuda_fp16.h>
#include <cstdint>
#include <cstddef>

#define BATCH 8
#define TENC 2048
#define TDEC 512
#define DIM  1024

// ---------------------------------------------------------------------------
// Scratch (static device arrays — no allocation allowed)
// All enc-derived tensors are stored in COMPACT row order (unmasked rows only).
// ---------------------------------------------------------------------------
__device__ __nv_bfloat16 g_eh[(size_t)BATCH * TENC * DIM];   // enc hi bf16 [b][j][d] compact
__device__ __nv_bfloat16 g_el[(size_t)BATCH * TENC * DIM];   // enc lo bf16 compact
__device__ __half        g_ef[(size_t)BATCH * TENC * DIM];   // enc fp16 compact (gemm2)
__device__ __nv_bfloat16 g_dh[(size_t)BATCH * TDEC * DIM];   // dec hi bf16 [b][u][d]
__device__ __nv_bfloat16 g_dl[(size_t)BATCH * TDEC * DIM];   // dec lo bf16
__device__ __half        g_pc[(size_t)BATCH * TENC * TDEC];  // COMPACT scores fp16 [b][j][u]
// mask compaction
__device__ int g_idx[BATCH * TENC];    // compact j -> t  (0-padded past cnt)
__device__ int g_rank[BATCH * TENC];   // t -> compact j  (valid where mask=1)
__device__ int g_cnt[BATCH];
// softmax partials: 16 compact chunks of 128
__device__ float g_cm[BATCH * 16 * TDEC];
__device__ float g_cs[BATCH * 16 * TDEC];
__device__ float g_Mx[BATCH * TDEC];
__device__ float g_Iv[BATCH * TDEC];

// ---------------------------------------------------------------------------
// helpers
// ---------------------------------------------------------------------------
__device__ __forceinline__ uint32_t smem_u32(const void* p) {
    return (uint32_t)__cvta_generic_to_shared(p);
}
__device__ __forceinline__ void cpa16(uint32_t s, const void* g) {
    asm volatile("cp.async.cg.shared.global [%0], [%1], 16;\n" :: "r"(s), "l"(g));
}
__device__ __forceinline__ void cpa_commit() {
    asm volatile("cp.async.commit_group;\n");
}
__device__ __forceinline__ void cpa_wait2() { asm volatile("cp.async.wait_group 2;\n"); }
__device__ __forceinline__ void cpa_wait1() { asm volatile("cp.async.wait_group 1;\n"); }
__device__ __forceinline__ void cpa_wait0() { asm volatile("cp.async.wait_group 0;\n"); }
__device__ __forceinline__ void ldsm4(uint32_t* r, uint32_t a) {
    asm volatile("ldmatrix.sync.aligned.m8n8.x4.shared.b16 {%0,%1,%2,%3}, [%4];\n"
                 : "=r"(r[0]), "=r"(r[1]), "=r"(r[2]), "=r"(r[3]) : "r"(a));
}
__device__ __forceinline__ void ldsm4t(uint32_t* r, uint32_t a) {
    asm volatile("ldmatrix.sync.aligned.m8n8.x4.trans.shared.b16 {%0,%1,%2,%3}, [%4];\n"
                 : "=r"(r[0]), "=r"(r[1]), "=r"(r[2]), "=r"(r[3]) : "r"(a));
}
__device__ __forceinline__ void mma_bf16(float* c, const uint32_t* a, uint32_t b0, uint32_t b1) {
    asm volatile(
        "mma.sync.aligned.m16n8k16.row.col.f32.bf16.bf16.f32 "
        "{%0,%1,%2,%3},{%4,%5,%6,%7},{%8,%9},{%0,%1,%2,%3};\n"
        : "+f"(c[0]), "+f"(c[1]), "+f"(c[2]), "+f"(c[3])
        : "r"(a[0]), "r"(a[1]), "r"(a[2]), "r"(a[3]), "r"(b0), "r"(b1));
}
__device__ __forceinline__ void mma_fp16(float* c, const uint32_t* a, uint32_t b0, uint32_t b1) {
    asm volatile(
        "mma.sync.aligned.m16n8k16.row.col.f32.f16.f16.f32 "
        "{%0,%1,%2,%3},{%4,%5,%6,%7},{%8,%9},{%0,%1,%2,%3};\n"
        : "+f"(c[0]), "+f"(c[1]), "+f"(c[2]), "+f"(c[3])
        : "r"(a[0]), "r"(a[1]), "r"(a[2]), "r"(a[3]), "r"(b0), "r"(b1));
}

// ---------------------------------------------------------------------------
// compact: per batch, prefix-scan mask; init partials; zero-pad compact rows
// of pc AND ef (pad rows enter gemm2 MMAs multiplied by pc=0 — must be finite)
// ---------------------------------------------------------------------------
__global__ __launch_bounds__(1024) void compact_kernel(const int* __restrict__ mask)
{
    const int b   = blockIdx.x;
    const int tid = threadIdx.x;       // 1024
    const int lane = tid & 31, wid = tid >> 5;
    const int* m = mask + b * TENC;

    int v0 = m[2 * tid], v1 = m[2 * tid + 1];
    int s = v0 + v1;
    int x = s;
    #pragma unroll
    for (int o = 1; o < 32; o <<= 1) {
        int y = __shfl_up_sync(0xffffffffu, x, o);
        if (lane >= o) x += y;
    }
    __shared__ int wsum[32], wscan[32];
    if (lane == 31) wsum[wid] = x;
    __syncthreads();
    if (wid == 0) {
        int w = wsum[lane];
        #pragma unroll
        for (int o = 1; o < 32; o <<= 1) {
            int y = __shfl_up_sync(0xffffffffu, w, o);
            if (lane >= o) w += y;
        }
        wscan[lane] = w;
    }
    __syncthreads();
    int excl = x - s + (wid > 0 ? wscan[wid - 1] : 0);
    int p = excl;
    if (v0) { g_idx[b * TENC + p] = 2 * tid;     g_rank[b * TENC + 2 * tid]     = p; p++; }
    if (v1) { g_idx[b * TENC + p] = 2 * tid + 1; g_rank[b * TENC + 2 * tid + 1] = p; }
    const int total = wscan[31];
    if (tid == 0) g_cnt[b] = total;
    __syncthreads();

    for (int j = tid; j < TENC; j += 1024)
        if (j >= total) g_idx[b * TENC + j] = 0;
    for (int i = tid; i < 16 * TDEC; i += 1024) {
        g_cm[b * 16 * TDEC + i] = -3.4e38f;
        g_cs[b * 16 * TDEC + i] = 0.f;
    }
    const int cnt32 = (total + 31) & ~31;
    // zero-pad compact score rows [total, cnt32)
    {
        const int padn = (cnt32 - total) * TDEC;
        __half zh = __float2half(0.f);
        for (int i = tid; i < padn; i += 1024) {
            int r = total + i / TDEC, u = i % TDEC;
            g_pc[((size_t)b * TENC + r) * TDEC + u] = zh;
        }
    }
    // zero-pad compact ef rows [total, cnt32)
    {
        const int padn = (cnt32 - total) * DIM;
        __half zh = __float2half(0.f);
        for (int i = tid; i < padn; i += 1024) {
            int r = total + i / DIM, d = i % DIM;
            g_ef[((size_t)b * TENC + r) * DIM + d] = zh;
        }
    }
}

// ---------------------------------------------------------------------------
// merged split kernel:
//   blocks [0, 1024): enc -> compact eh/el/ef (skip masked rows)
//   blocks [1024, 1536): dec -> dh/dl
// ---------------------------------------------------------------------------
__global__ __launch_bounds__(256) void split_kernel(
    const float* __restrict__ enc, const float* __restrict__ dec,
    const int* __restrict__ mask)
{
    if (blockIdx.x < 1024) {
        const int n4 = (int)((size_t)BATCH * TENC * DIM / 4);   // 4M chunks
        const int stride = 1024 * 256;
        for (int i = blockIdx.x * 256 + threadIdx.x; i < n4; i += stride) {
            const int trow = i >> 8;              // b*TENC + t  (DIM/4 = 256)
            if (!mask[trow]) continue;
            const int j = g_rank[trow];
            const size_t orow = (size_t)((trow & ~(TENC - 1)) + j);
            const int col4 = i & 255;
            float4 v = ((const float4*)enc)[i];
            __nv_bfloat16 h0 = __float2bfloat16(v.x), h1 = __float2bfloat16(v.y);
            __nv_bfloat16 h2 = __float2bfloat16(v.z), h3 = __float2bfloat16(v.w);
            __nv_bfloat16 l0 = __float2bfloat16(v.x - __bfloat162float(h0));
            __nv_bfloat16 l1 = __float2bfloat16(v.y - __bfloat162float(h1));
            __nv_bfloat16 l2 = __float2bfloat16(v.z - __bfloat162float(h2));
            __nv_bfloat16 l3 = __float2bfloat16(v.w - __bfloat162float(h3));
            __nv_bfloat162 hA = {h0, h1}, hB = {h2, h3}, lA = {l0, l1}, lB = {l2, l3};
            uint2 hv = {*(uint32_t*)&hA, *(uint32_t*)&hB};
            uint2 lv = {*(uint32_t*)&lA, *(uint32_t*)&lB};
            size_t o4 = orow * 256 + col4;
            ((uint2*)g_eh)[o4] = hv;
            ((uint2*)g_el)[o4] = lv;
            __half2 fA = {__float2half(v.x), __float2half(v.y)};
            __half2 fB = {__float2half(v.z), __float2half(v.w)};
            uint2 fv = {*(uint32_t*)&fA, *(uint32_t*)&fB};
            ((uint2*)g_ef)[o4] = fv;
        }
    } else {
        const int n4 = (int)((size_t)BATCH * TDEC * DIM / 4);   // 1M chunks
        const int stride = 512 * 256;
        for (int i = (blockIdx.x - 1024) * 256 + threadIdx.x; i < n4; i += stride) {
            float4 v = ((const float4*)dec)[i];
            __nv_bfloat16 h0 = __float2bfloat16(v.x), h1 = __float2bfloat16(v.y);
            __nv_bfloat16 h2 = __float2bfloat16(v.z), h3 = __float2bfloat16(v.w);
            __nv_bfloat16 l0 = __float2bfloat16(v.x - __bfloat162float(h0));
            __nv_bfloat16 l1 = __float2bfloat16(v.y - __bfloat162float(h1));
            __nv_bfloat16 l2 = __float2bfloat16(v.z - __bfloat162float(h2));
            __nv_bfloat16 l3 = __float2bfloat16(v.w - __bfloat162float(h3));
            __nv_bfloat162 hA = {h0, h1}, hB = {h2, h3}, lA = {l0, l1}, lB = {l2, l3};
            uint2 hv = {*(uint32_t*)&hA, *(uint32_t*)&hB};
            uint2 lv = {*(uint32_t*)&lA, *(uint32_t*)&lB};
            ((uint2*)g_dh)[i] = hv;
            ((uint2*)g_dl)[i] = lv;
        }
    }
}

// ---------------------------------------------------------------------------
// GEMM1 (compact rows, contiguous A) + fused softmax chunk partials.
// 2-stage cp.async ring, 2 CTAs/SM.
// ---------------------------------------------------------------------------
#define G1_BUF   10240
#define G1_STAGE (4 * G1_BUF)
#define G1_DYN   (2 * G1_STAGE + 1024)

__global__ __launch_bounds__(256, 2) void gemm1_kernel(float* __restrict__ S)
{
    const int b  = blockIdx.z;
    const int m0 = blockIdx.y * 128;   // compact row tile
    const int n0 = blockIdx.x * 128;   // u
    const int cnt = g_cnt[b];
    if (m0 >= cnt) return;

    extern __shared__ __align__(16) uint8_t dynsm[];
    const uint32_t dynb = (smem_u32(dynsm) + 1023u) & ~1023u;
    __shared__ float smax[2][128];
    __shared__ float ssum[2][128];

    const int* idxp = g_idx + b * TENC;
    const __nv_bfloat16* Ah = g_eh + (size_t)b * TENC * DIM;
    const __nv_bfloat16* Al = g_el + (size_t)b * TENC * DIM;
    const __nv_bfloat16* Bh = g_dh + (size_t)b * TDEC * DIM;
    const __nv_bfloat16* Bl = g_dl + (size_t)b * TDEC * DIM;
    float* Sp = S + (size_t)b * TENC * TDEC;

    const int tid  = threadIdx.x;
    const int lane = tid & 31;
    const int wid  = tid >> 5;
    const int m_off = (wid & 1) * 64;
    const int n_off = (wid >> 1) * 32;

    const int lrow = tid >> 2;
    const int lc   = tid & 3;

    const uint32_t aBase = (uint32_t)((m_off + (lane & 15)) * 80 + (lane >> 4) * 16);
    const uint32_t bBase = (uint32_t)((n_off + (lane & 7) + ((lane >> 4) << 3)) * 80
                                      + ((lane >> 3) & 1) * 16);

    float acc[4][4][4];
    #pragma unroll
    for (int i = 0; i < 4; i++)
        #pragma unroll
        for (int j = 0; j < 4; j++)
            #pragma unroll
            for (int k = 0; k < 4; k++) acc[i][j][k] = 0.f;

    const int NST = DIM / 32;

    auto load_stage = [&](int s) {
        const int k0 = s * 32;
        const uint32_t sb = dynb + (uint32_t)(s & 1) * G1_STAGE;
        #pragma unroll
        for (int j = 0; j < 2; j++) {
            int row = lrow + j * 64;
            uint32_t so = (uint32_t)(row * 80 + lc * 16);
            size_t goA = (size_t)(m0 + row) * DIM + k0 + lc * 8;
            size_t goB = (size_t)(n0 + row) * DIM + k0 + lc * 8;
            cpa16(sb + so,              Ah + goA);
            cpa16(sb + G1_BUF + so,     Al + goA);
            cpa16(sb + 2 * G1_BUF + so, Bh + goB);
            cpa16(sb + 3 * G1_BUF + so, Bl + goB);
        }
        cpa_commit();
    };

    load_stage(0);
    load_stage(1);

    for (int s = 0; s < NST; s++) {
        if (s < NST - 1) cpa_wait1(); else cpa_wait0();
        __syncthreads();

        const uint32_t bAh = dynb + (uint32_t)(s & 1) * G1_STAGE;
        const uint32_t bAl = bAh + G1_BUF;
        const uint32_t bBh = bAh + 2 * G1_BUF;
        const uint32_t bBl = bAh + 3 * G1_BUF;

        #pragma unroll
        for (int ks = 0; ks < 2; ks++) {
            uint32_t koff = (uint32_t)(ks * 32);
            uint32_t ah[4][4], bh[2][4];
            #pragma unroll
            for (int im = 0; im < 4; im++) ldsm4(ah[im], bAh + aBase + im * 1280 + koff);
            #pragma unroll
            for (int p = 0; p < 2; p++)   ldsm4(bh[p], bBh + bBase + p * 1280 + koff);
            #pragma unroll
            for (int im = 0; im < 4; im++)
                #pragma unroll
                for (int in = 0; in < 4; in++)
                    mma_bf16(acc[im][in], ah[im], bh[in >> 1][(in & 1) * 2], bh[in >> 1][(in & 1) * 2 + 1]);

            uint32_t bl[2][4];
            #pragma unroll
            for (int p = 0; p < 2; p++) ldsm4(bl[p], bBl + bBase + p * 1280 + koff);
            #pragma unroll
            for (int im = 0; im < 4; im++)
                #pragma unroll
                for (int in = 0; in < 4; in++)
                    mma_bf16(acc[im][in], ah[im], bl[in >> 1][(in & 1) * 2], bl[in >> 1][(in & 1) * 2 + 1]);

            uint32_t al[4][4];
            #pragma unroll
            for (int im = 0; im < 4; im++) ldsm4(al[im], bAl + aBase + im * 1280 + koff);
            #pragma unroll
            for (int im = 0; im < 4; im++)
                #pragma unroll
                for (int in = 0; in < 4; in++)
                    mma_bf16(acc[im][in], al[im], bh[in >> 1][(in & 1) * 2], bh[in >> 1][(in & 1) * 2 + 1]);
        }
        __syncthreads();
        if (s + 2 < NST) load_stage(s + 2);
    }

    // ---- epilogue: scatter S rows (valid only) + softmax partials
    bool ok0[4], ok1[4];
    int to0[4], to1[4];
    #pragma unroll
    for (int im = 0; im < 4; im++) {
        int r0 = m0 + m_off + im * 16 + (lane >> 2);
        int r1 = r0 + 8;
        ok0[im] = r0 < cnt;
        ok1[im] = r1 < cnt;
        to0[im] = idxp[r0];
        to1[im] = idxp[r1];
    }
    #pragma unroll
    for (int im = 0; im < 4; im++) {
        #pragma unroll
        for (int in = 0; in < 4; in++) {
            int col = n0 + n_off + in * 8 + (lane & 3) * 2;
            if (ok0[im]) *(float2*)&Sp[(size_t)to0[im] * TDEC + col] = *(float2*)&acc[im][in][0];
            if (ok1[im]) *(float2*)&Sp[(size_t)to1[im] * TDEC + col] = *(float2*)&acc[im][in][2];
        }
    }
    float umax[8];
    #pragma unroll
    for (int q = 0; q < 8; q++) umax[q] = -3.4e38f;
    #pragma unroll
    for (int im = 0; im < 4; im++)
        #pragma unroll
        for (int in = 0; in < 4; in++)
            #pragma unroll
            for (int j = 0; j < 2; j++) {
                if (ok0[im]) umax[in * 2 + j] = fmaxf(umax[in * 2 + j], acc[im][in][j]);
                if (ok1[im]) umax[in * 2 + j] = fmaxf(umax[in * 2 + j], acc[im][in][2 + j]);
            }
    #pragma unroll
    for (int msk = 4; msk <= 16; msk <<= 1)
        #pragma unroll
        for (int q = 0; q < 8; q++)
            umax[q] = fmaxf(umax[q], __shfl_xor_sync(0xffffffffu, umax[q], msk));
    float usum[8];
    #pragma unroll
    for (int q = 0; q < 8; q++) usum[q] = 0.f;
    #pragma unroll
    for (int im = 0; im < 4; im++)
        #pragma unroll
        for (int in = 0; in < 4; in++)
            #pragma unroll
            for (int j = 0; j < 2; j++) {
                usum[in * 2 + j] += ok0[im] ? __expf(acc[im][in][j]     - umax[in * 2 + j]) : 0.f;
                usum[in * 2 + j] += ok1[im] ? __expf(acc[im][in][2 + j] - umax[in * 2 + j]) : 0.f;
            }
    #pragma unroll
    for (int msk = 4; msk <= 16; msk <<= 1)
        #pragma unroll
        for (int q = 0; q < 8; q++)
            usum[q] += __shfl_xor_sync(0xffffffffu, usum[q], msk);
    if (lane < 4) {
        #pragma unroll
        for (int in = 0; in < 4; in++)
            #pragma unroll
            for (int j = 0; j < 2; j++) {
                int u = n_off + in * 8 + lane * 2 + j;
                smax[wid & 1][u] = umax[in * 2 + j];
                ssum[wid & 1][u] = usum[in * 2 + j];
            }
    }
    __syncthreads();
    if (tid < 128) {
        float m0v = smax[0][tid], m1v = smax[1][tid];
        float M = fmaxf(m0v, m1v);
        float Ssum = (m0v > -3.4e38f ? ssum[0][tid] * __expf(m0v - M) : 0.f)
                   + (m1v > -3.4e38f ? ssum[1][tid] * __expf(m1v - M) : 0.f);
        int idx = (b * 16 + blockIdx.y) * TDEC + n0 + tid;
        g_cm[idx] = M;
        g_cs[idx] = Ssum;
    }
}

// ---------------------------------------------------------------------------
// softmaxB: fold 16 chunk partials -> M[b,u], 1/S[b,u]
// ---------------------------------------------------------------------------
__global__ void softmaxB_kernel()
{
    int i = blockIdx.x * 256 + threadIdx.x;
    if (i >= BATCH * TDEC) return;
    int b = i / TDEC, u = i % TDEC;
    float M = -3.4e38f;
    #pragma unroll
    for (int c = 0; c < 16; c++) M = fmaxf(M, g_cm[(b * 16 + c) * TDEC + u]);
    float Ssum = 0.f;
    #pragma unroll
    for (int c = 0; c < 16; c++) {
        float cm = g_cm[(b * 16 + c) * TDEC + u];
        Ssum += (cm > -3.4e38f) ? g_cs[(b * 16 + c) * TDEC + u] * __expf(cm - M) : 0.f;
    }
    g_Mx[i] = M;
    g_Iv[i] = 1.0f / Ssum;
}

// ---------------------------------------------------------------------------
// softmaxC (row-coalesced): 8 t-rows/block. Masked rows -> S=0 (exact).
// ---------------------------------------------------------------------------
__global__ __launch_bounds__(256) void softmaxC_kernel(
    float* __restrict__ S, const int* __restrict__ mask)
{
    const int b  = blockIdx.y;
    const int t0 = blockIdx.x * 8;
    const int tid = threadIdx.x;

    __shared__ float sM[TDEC], sI[TDEC];
    __shared__ int smk[8], srk[8];
    if (tid < 8) {
        smk[tid] = mask[b * TENC + t0 + tid];
        srk[tid] = g_rank[b * TENC + t0 + tid];
    }
    for (int i = tid; i < TDEC; i += 256) {
        sM[i] = g_Mx[b * TDEC + i];
        sI[i] = g_Iv[b * TDEC + i];
    }
    __syncthreads();

    #pragma unroll
    for (int slot = tid; slot < 1024; slot += 256) {
        int row = slot >> 7;
        int u4  = slot & 127;
        int u   = u4 * 4;
        size_t idx = ((size_t)b * TENC + t0 + row) * TDEC + u;
        if (smk[row]) {
            float4 v = *(float4*)&S[idx];
            v.x = __expf(v.x - sM[u + 0]) * sI[u + 0];
            v.y = __expf(v.y - sM[u + 1]) * sI[u + 1];
            v.z = __expf(v.z - sM[u + 2]) * sI[u + 2];
            v.w = __expf(v.w - sM[u + 3]) * sI[u + 3];
            *(float4*)&S[idx] = v;
            __half2 h01 = {__float2half(v.x), __float2half(v.y)};
            __half2 h23 = {__float2half(v.z), __float2half(v.w)};
            uint2 hv = {*(uint32_t*)&h01, *(uint32_t*)&h23};
            *(uint2*)&g_pc[((size_t)b * TENC + srk[row]) * TDEC + u] = hv;
        } else {
            float4 z = {0.f, 0.f, 0.f, 0.f};
            *(float4*)&S[idx] = z;
        }
    }
}

// ---------------------------------------------------------------------------
// GEMM2 (fp16 single pass, compact K, contiguous B): BM=128, BN=128, BK=32.
// K runs to cnt32 only. 4-deep ring, 2 CTAs/SM.
// ---------------------------------------------------------------------------
#define G2_BUF   8704             // 32 rows * 272 B
#define G2_STAGE (2 * G2_BUF)     // Pc, Ef
#define G2_DYN   (4 * G2_STAGE + 1024)

__global__ __launch_bounds__(256, 2) void gemm2_kernel(float* __restrict__ ctx)
{
    extern __shared__ __align__(16) uint8_t dynsm[];
    const uint32_t dynb = (smem_u32(dynsm) + 1023u) & ~1023u;

    const int b  = blockIdx.z;
    const int u0 = blockIdx.y * 128;
    const int d0 = blockIdx.x * 128;
    const int cnt = g_cnt[b];
    const int NST = (cnt + 31) >> 5;

    const __half* Pc = g_pc + (size_t)b * TENC * TDEC;
    const __half* Ef = g_ef + (size_t)b * TENC * DIM;
    float* C = ctx + (size_t)b * TDEC * DIM;

    const int tid  = threadIdx.x;
    const int lane = tid & 31;
    const int wid  = tid >> 5;
    const int m_off = (wid & 1) * 64;   // u
    const int n_off = (wid >> 1) * 32;  // d

    const int lrow = tid >> 4;   // 0..15 (+16)
    const int lc   = tid & 15;

    const uint32_t aBase = (uint32_t)(((lane & 7) + ((lane >> 4) << 3)) * 272
                                      + (m_off + ((lane >> 3) & 1) * 8) * 2);
    const uint32_t bBase = (uint32_t)(((lane & 7) + (((lane >> 3) & 1) << 3)) * 272
                                      + (n_off + (lane >> 4) * 8) * 2);

    float acc[4][4][4];
    #pragma unroll
    for (int i = 0; i < 4; i++)
        #pragma unroll
        for (int j = 0; j < 4; j++)
            #pragma unroll
            for (int k = 0; k < 4; k++) acc[i][j][k] = 0.f;

    auto load_stage = [&](int s) {
        const int k0 = s * 32;
        const uint32_t sb = dynb + (uint32_t)(s & 3) * G2_STAGE;
        #pragma unroll
        for (int j = 0; j < 2; j++) {
            int row = lrow + j * 16;
            uint32_t so = (uint32_t)(row * 272 + lc * 16);
            size_t goP = (size_t)(k0 + row) * TDEC + u0 + lc * 8;
            size_t goE = (size_t)(k0 + row) * DIM + d0 + lc * 8;
            cpa16(sb + so,          Pc + goP);
            cpa16(sb + G2_BUF + so, Ef + goE);
        }
        cpa_commit();
    };

    const int pre = NST < 3 ? NST : 3;
    for (int s = 0; s < pre; s++) load_stage(s);

    for (int s = 0; s < NST; s++) {
        int out = NST - s - 1; if (out > 2) out = 2;
        if (out == 2) cpa_wait2();
        else if (out == 1) cpa_wait1();
        else cpa_wait0();
        __syncthreads();

        const uint32_t bPh = dynb + (uint32_t)(s & 3) * G2_STAGE;
        const uint32_t bEf = bPh + G2_BUF;

        #pragma unroll
        for (int ks = 0; ks < 2; ks++) {
            uint32_t koff = (uint32_t)(ks * 16 * 272);
            uint32_t ah[4][4], bh[2][4];
            #pragma unroll
            for (int im = 0; im < 4; im++) ldsm4t(ah[im], bPh + aBase + im * 32 + koff);
            #pragma unroll
            for (int p = 0; p < 2; p++)   ldsm4t(bh[p], bEf + bBase + p * 32 + koff);
            #pragma unroll
            for (int im = 0; im < 4; im++)
                #pragma unroll
                for (int in = 0; in < 4; in++)
                    mma_fp16(acc[im][in], ah[im], bh[in >> 1][(in & 1) * 2], bh[in >> 1][(in & 1) * 2 + 1]);
        }
        if (s + 3 < NST) load_stage(s + 3);
    }

    #pragma unroll
    for (int im = 0; im < 4; im++) {
        int ur = u0 + m_off + im * 16 + (lane >> 2);
        #pragma unroll
        for (int in = 0; in < 4; in++) {
            int col = d0 + n_off + in * 8 + (lane & 3) * 2;
            float2 v0 = {acc[im][in][0], acc[im][in][1]};
            float2 v1 = {acc[im][in][2], acc[im][in][3]};
            *(float2*)&C[(size_t)ur * DIM + col]       = v0;
            *(float2*)&C[(size_t)(ur + 8) * DIM + col] = v1;
        }
    }
}

// ---------------------------------------------------------------------------
extern "C" void kernel_launch(void* const* d_in, const int* in_sizes, int n_in,
                              void* d_out, int out_size)
{
    const float* enc      = (const float*)d_in[0];
    const int*   enc_mask = (const int*)  d_in[1];
    const float* dec      = (const float*)d_in[2];

    float* ctx = (float*)d_out;                      // [B, TDEC, DIM]
    float* S   = ctx + (size_t)BATCH * TDEC * DIM;   // [B, TENC, TDEC]

    cudaFuncSetAttribute(gemm1_kernel, cudaFuncAttributeMaxDynamicSharedMemorySize, G1_DYN);
    cudaFuncSetAttribute(gemm2_kernel, cudaFuncAttributeMaxDynamicSharedMemorySize, G2_DYN);

    compact_kernel<<<BATCH, 1024>>>(enc_mask);
    split_kernel<<<1536, 256>>>(enc, dec, enc_mask);

    gemm1_kernel<<<dim3(TDEC / 128, TENC / 128, BATCH), 256, G1_DYN>>>(S);

    softmaxB_kernel<<<(BATCH * TDEC + 255) / 256, 256>>>();
    softmaxC_kernel<<<dim3(TENC / 8, BATCH), 256>>>(S, enc_mask);

    gemm2_kernel<<<dim3(DIM / 128, TDEC / 128, BATCH), 256, G2_DYN>>>(ctx);
}

// round 17
// speedup vs baseline: 2.1733x; 1.0288x over previous
#include <cuda_runtime.h>
#include <cuda_bf16.h>
#include <cuda_fp16.h>
#include <cstdint>
#include <cstddef>

#define BATCH 8
#define TENC 2048
#define TDEC 512
#define DIM  1024

// ---------------------------------------------------------------------------
// Scratch (static device arrays — no allocation allowed)
// All enc-derived tensors are stored in COMPACT row order (unmasked rows only).
// Splits are fp16 hi/lo (hi also serves as gemm2's B operand).
// ---------------------------------------------------------------------------
__device__ __half g_eh[(size_t)BATCH * TENC * DIM];   // enc hi fp16 [b][j][d] compact
__device__ __half g_el[(size_t)BATCH * TENC * DIM];   // enc lo fp16 compact
__device__ __half g_dh[(size_t)BATCH * TDEC * DIM];   // dec hi fp16 [b][u][d]
__device__ __half g_dl[(size_t)BATCH * TDEC * DIM];   // dec lo fp16
__device__ __half g_pc[(size_t)BATCH * TENC * TDEC];  // COMPACT scores fp16 [b][j][u]
// mask compaction
__device__ int g_idx[BATCH * TENC];    // compact j -> t  (0-padded past cnt)
__device__ int g_rank[BATCH * TENC];   // t -> compact j  (valid where mask=1)
__device__ int g_cnt[BATCH];
__device__ int g_ctr[BATCH * (TDEC / 128)];   // last-CTA fold counters
// softmax partials: 16 compact chunks of 128
__device__ float g_cm[BATCH * 16 * TDEC];
__device__ float g_cs[BATCH * 16 * TDEC];
__device__ float g_Mx[BATCH * TDEC];
__device__ float g_Iv[BATCH * TDEC];

// ---------------------------------------------------------------------------
// helpers
// ---------------------------------------------------------------------------
__device__ __forceinline__ uint32_t smem_u32(const void* p) {
    return (uint32_t)__cvta_generic_to_shared(p);
}
__device__ __forceinline__ void cpa16(uint32_t s, const void* g) {
    asm volatile("cp.async.cg.shared.global [%0], [%1], 16;\n" :: "r"(s), "l"(g));
}
__device__ __forceinline__ void cpa_commit() {
    asm volatile("cp.async.commit_group;\n");
}
__device__ __forceinline__ void cpa_wait2() { asm volatile("cp.async.wait_group 2;\n"); }
__device__ __forceinline__ void cpa_wait1() { asm volatile("cp.async.wait_group 1;\n"); }
__device__ __forceinline__ void cpa_wait0() { asm volatile("cp.async.wait_group 0;\n"); }
__device__ __forceinline__ void ldsm4(uint32_t* r, uint32_t a) {
    asm volatile("ldmatrix.sync.aligned.m8n8.x4.shared.b16 {%0,%1,%2,%3}, [%4];\n"
                 : "=r"(r[0]), "=r"(r[1]), "=r"(r[2]), "=r"(r[3]) : "r"(a));
}
__device__ __forceinline__ void ldsm4t(uint32_t* r, uint32_t a) {
    asm volatile("ldmatrix.sync.aligned.m8n8.x4.trans.shared.b16 {%0,%1,%2,%3}, [%4];\n"
                 : "=r"(r[0]), "=r"(r[1]), "=r"(r[2]), "=r"(r[3]) : "r"(a));
}
__device__ __forceinline__ void mma_fp16(float* c, const uint32_t* a, uint32_t b0, uint32_t b1) {
    asm volatile(
        "mma.sync.aligned.m16n8k16.row.col.f32.f16.f16.f32 "
        "{%0,%1,%2,%3},{%4,%5,%6,%7},{%8,%9},{%0,%1,%2,%3};\n"
        : "+f"(c[0]), "+f"(c[1]), "+f"(c[2]), "+f"(c[3])
        : "r"(a[0]), "r"(a[1]), "r"(a[2]), "r"(a[3]), "r"(b0), "r"(b1));
}

// ---------------------------------------------------------------------------
// compact: per batch, prefix-scan mask; init partials + counters; zero-pad pc
// ---------------------------------------------------------------------------
__global__ __launch_bounds__(1024) void compact_kernel(const int* __restrict__ mask)
{
    const int b   = blockIdx.x;
    const int tid = threadIdx.x;       // 1024
    const int lane = tid & 31, wid = tid >> 5;
    const int* m = mask + b * TENC;

    int v0 = m[2 * tid], v1 = m[2 * tid + 1];
    int s = v0 + v1;
    int x = s;
    #pragma unroll
    for (int o = 1; o < 32; o <<= 1) {
        int y = __shfl_up_sync(0xffffffffu, x, o);
        if (lane >= o) x += y;
    }
    __shared__ int wsum[32], wscan[32];
    if (lane == 31) wsum[wid] = x;
    __syncthreads();
    if (wid == 0) {
        int w = wsum[lane];
        #pragma unroll
        for (int o = 1; o < 32; o <<= 1) {
            int y = __shfl_up_sync(0xffffffffu, w, o);
            if (lane >= o) w += y;
        }
        wscan[lane] = w;
    }
    __syncthreads();
    int excl = x - s + (wid > 0 ? wscan[wid - 1] : 0);
    int p = excl;
    if (v0) { g_idx[b * TENC + p] = 2 * tid;     g_rank[b * TENC + 2 * tid]     = p; p++; }
    if (v1) { g_idx[b * TENC + p] = 2 * tid + 1; g_rank[b * TENC + 2 * tid + 1] = p; }
    const int total = wscan[31];
    if (tid == 0) g_cnt[b] = total;
    if (tid < TDEC / 128) g_ctr[b * (TDEC / 128) + tid] = 0;
    __syncthreads();

    for (int j = tid; j < TENC; j += 1024)
        if (j >= total) g_idx[b * TENC + j] = 0;
    for (int i = tid; i < 16 * TDEC; i += 1024) {
        g_cm[b * 16 * TDEC + i] = -3.4e38f;
        g_cs[b * 16 * TDEC + i] = 0.f;
    }
    const int cnt32 = (total + 31) & ~31;
    // zero-pad compact score rows [total, cnt32) (pc is gemm2's multiplier)
    {
        const int padn = (cnt32 - total) * TDEC;
        __half zh = __float2half(0.f);
        for (int i = tid; i < padn; i += 1024) {
            int r = total + i / TDEC, u = i % TDEC;
            g_pc[((size_t)b * TENC + r) * TDEC + u] = zh;
        }
    }
}

// ---------------------------------------------------------------------------
// merged split kernel (fp16 hi/lo):
//   blocks [0, 1024): enc -> compact eh/el (skip masked rows)
//   blocks [1024, 1536): dec -> dh/dl
// ---------------------------------------------------------------------------
__global__ __launch_bounds__(256) void split_kernel(
    const float* __restrict__ enc, const float* __restrict__ dec,
    const int* __restrict__ mask)
{
    if (blockIdx.x < 1024) {
        const int n4 = (int)((size_t)BATCH * TENC * DIM / 4);
        const int stride = 1024 * 256;
        for (int i = blockIdx.x * 256 + threadIdx.x; i < n4; i += stride) {
            const int trow = i >> 8;              // b*TENC + t  (DIM/4 = 256)
            if (!mask[trow]) continue;
            const int j = g_rank[trow];
            const size_t orow = (size_t)((trow & ~(TENC - 1)) + j);
            const int col4 = i & 255;
            float4 v = ((const float4*)enc)[i];
            __half h0 = __float2half(v.x), h1 = __float2half(v.y);
            __half h2 = __float2half(v.z), h3 = __float2half(v.w);
            __half l0 = __float2half(v.x - __half2float(h0));
            __half l1 = __float2half(v.y - __half2float(h1));
            __half l2 = __float2half(v.z - __half2float(h2));
            __half l3 = __float2half(v.w - __half2float(h3));
            __half2 hA = {h0, h1}, hB = {h2, h3}, lA = {l0, l1}, lB = {l2, l3};
            uint2 hv = {*(uint32_t*)&hA, *(uint32_t*)&hB};
            uint2 lv = {*(uint32_t*)&lA, *(uint32_t*)&lB};
            size_t o4 = orow * 256 + col4;
            ((uint2*)g_eh)[o4] = hv;
            ((uint2*)g_el)[o4] = lv;
        }
    } else {
        const int n4 = (int)((size_t)BATCH * TDEC * DIM / 4);
        const int stride = 512 * 256;
        for (int i = (blockIdx.x - 1024) * 256 + threadIdx.x; i < n4; i += stride) {
            float4 v = ((const float4*)dec)[i];
            __half h0 = __float2half(v.x), h1 = __float2half(v.y);
            __half h2 = __float2half(v.z), h3 = __float2half(v.w);
            __half l0 = __float2half(v.x - __half2float(h0));
            __half l1 = __float2half(v.y - __half2float(h1));
            __half l2 = __float2half(v.z - __half2float(h2));
            __half l3 = __float2half(v.w - __half2float(h3));
            __half2 hA = {h0, h1}, hB = {h2, h3}, lA = {l0, l1}, lB = {l2, l3};
            uint2 hv = {*(uint32_t*)&hA, *(uint32_t*)&hB};
            uint2 lv = {*(uint32_t*)&lA, *(uint32_t*)&lB};
            ((uint2*)g_dh)[i] = hv;
            ((uint2*)g_dl)[i] = lv;
        }
    }
}

// ---------------------------------------------------------------------------
// GEMM1 (fp16x3, compact rows) + fused softmax chunk partials
// + last-CTA fold of chunk partials into g_Mx/g_Iv (replaces softmaxB).
// 2-stage cp.async ring, 2 CTAs/SM.
// ---------------------------------------------------------------------------
#define G1_BUF   10240
#define G1_STAGE (4 * G1_BUF)
#define G1_DYN   (2 * G1_STAGE + 1024)

__global__ __launch_bounds__(256, 2) void gemm1_kernel(float* __restrict__ S)
{
    const int b  = blockIdx.z;
    const int m0 = blockIdx.y * 128;   // compact row tile
    const int n0 = blockIdx.x * 128;   // u
    const int cnt = g_cnt[b];
    if (m0 >= cnt) return;

    extern __shared__ __align__(16) uint8_t dynsm[];
    const uint32_t dynb = (smem_u32(dynsm) + 1023u) & ~1023u;
    __shared__ float smax[2][128];
    __shared__ float ssum[2][128];
    __shared__ int s_done;

    const int* idxp = g_idx + b * TENC;
    const __half* Ah = g_eh + (size_t)b * TENC * DIM;
    const __half* Al = g_el + (size_t)b * TENC * DIM;
    const __half* Bh = g_dh + (size_t)b * TDEC * DIM;
    const __half* Bl = g_dl + (size_t)b * TDEC * DIM;
    float* Sp = S + (size_t)b * TENC * TDEC;

    const int tid  = threadIdx.x;
    const int lane = tid & 31;
    const int wid  = tid >> 5;
    const int m_off = (wid & 1) * 64;
    const int n_off = (wid >> 1) * 32;

    const int lrow = tid >> 2;
    const int lc   = tid & 3;

    const uint32_t aBase = (uint32_t)((m_off + (lane & 15)) * 80 + (lane >> 4) * 16);
    const uint32_t bBase = (uint32_t)((n_off + (lane & 7) + ((lane >> 4) << 3)) * 80
                                      + ((lane >> 3) & 1) * 16);

    float acc[4][4][4];
    #pragma unroll
    for (int i = 0; i < 4; i++)
        #pragma unroll
        for (int j = 0; j < 4; j++)
            #pragma unroll
            for (int k = 0; k < 4; k++) acc[i][j][k] = 0.f;

    const int NST = DIM / 32;

    auto load_stage = [&](int s) {
        const int k0 = s * 32;
        const uint32_t sb = dynb + (uint32_t)(s & 1) * G1_STAGE;
        #pragma unroll
        for (int j = 0; j < 2; j++) {
            int row = lrow + j * 64;
            uint32_t so = (uint32_t)(row * 80 + lc * 16);
            size_t goA = (size_t)(m0 + row) * DIM + k0 + lc * 8;
            size_t goB = (size_t)(n0 + row) * DIM + k0 + lc * 8;
            cpa16(sb + so,              Ah + goA);
            cpa16(sb + G1_BUF + so,     Al + goA);
            cpa16(sb + 2 * G1_BUF + so, Bh + goB);
            cpa16(sb + 3 * G1_BUF + so, Bl + goB);
        }
        cpa_commit();
    };

    load_stage(0);
    load_stage(1);

    for (int s = 0; s < NST; s++) {
        if (s < NST - 1) cpa_wait1(); else cpa_wait0();
        __syncthreads();

        const uint32_t bAh = dynb + (uint32_t)(s & 1) * G1_STAGE;
        const uint32_t bAl = bAh + G1_BUF;
        const uint32_t bBh = bAh + 2 * G1_BUF;
        const uint32_t bBl = bAh + 3 * G1_BUF;

        #pragma unroll
        for (int ks = 0; ks < 2; ks++) {
            uint32_t koff = (uint32_t)(ks * 32);
            uint32_t ah[4][4], bh[2][4];
            #pragma unroll
            for (int im = 0; im < 4; im++) ldsm4(ah[im], bAh + aBase + im * 1280 + koff);
            #pragma unroll
            for (int p = 0; p < 2; p++)   ldsm4(bh[p], bBh + bBase + p * 1280 + koff);
            #pragma unroll
            for (int im = 0; im < 4; im++)
                #pragma unroll
                for (int in = 0; in < 4; in++)
                    mma_fp16(acc[im][in], ah[im], bh[in >> 1][(in & 1) * 2], bh[in >> 1][(in & 1) * 2 + 1]);

            uint32_t bl[2][4];
            #pragma unroll
            for (int p = 0; p < 2; p++) ldsm4(bl[p], bBl + bBase + p * 1280 + koff);
            #pragma unroll
            for (int im = 0; im < 4; im++)
                #pragma unroll
                for (int in = 0; in < 4; in++)
                    mma_fp16(acc[im][in], ah[im], bl[in >> 1][(in & 1) * 2], bl[in >> 1][(in & 1) * 2 + 1]);

            uint32_t al[4][4];
            #pragma unroll
            for (int im = 0; im < 4; im++) ldsm4(al[im], bAl + aBase + im * 1280 + koff);
            #pragma unroll
            for (int im = 0; im < 4; im++)
                #pragma unroll
                for (int in = 0; in < 4; in++)
                    mma_fp16(acc[im][in], al[im], bh[in >> 1][(in & 1) * 2], bh[in >> 1][(in & 1) * 2 + 1]);
        }
        __syncthreads();
        if (s + 2 < NST) load_stage(s + 2);
    }

    // ---- epilogue: scatter S rows (valid only) + softmax partials
    bool ok0[4], ok1[4];
    int to0[4], to1[4];
    #pragma unroll
    for (int im = 0; im < 4; im++) {
        int r0 = m0 + m_off + im * 16 + (lane >> 2);
        int r1 = r0 + 8;
        ok0[im] = r0 < cnt;
        ok1[im] = r1 < cnt;
        to0[im] = idxp[r0];
        to1[im] = idxp[r1];
    }
    #pragma unroll
    for (int im = 0; im < 4; im++) {
        #pragma unroll
        for (int in = 0; in < 4; in++) {
            int col = n0 + n_off + in * 8 + (lane & 3) * 2;
            if (ok0[im]) *(float2*)&Sp[(size_t)to0[im] * TDEC + col] = *(float2*)&acc[im][in][0];
            if (ok1[im]) *(float2*)&Sp[(size_t)to1[im] * TDEC + col] = *(float2*)&acc[im][in][2];
        }
    }
    float umax[8];
    #pragma unroll
    for (int q = 0; q < 8; q++) umax[q] = -3.4e38f;
    #pragma unroll
    for (int im = 0; im < 4; im++)
        #pragma unroll
        for (int in = 0; in < 4; in++)
            #pragma unroll
            for (int j = 0; j < 2; j++) {
                if (ok0[im]) umax[in * 2 + j] = fmaxf(umax[in * 2 + j], acc[im][in][j]);
                if (ok1[im]) umax[in * 2 + j] = fmaxf(umax[in * 2 + j], acc[im][in][2 + j]);
            }
    #pragma unroll
    for (int msk = 4; msk <= 16; msk <<= 1)
        #pragma unroll
        for (int q = 0; q < 8; q++)
            umax[q] = fmaxf(umax[q], __shfl_xor_sync(0xffffffffu, umax[q], msk));
    float usum[8];
    #pragma unroll
    for (int q = 0; q < 8; q++) usum[q] = 0.f;
    #pragma unroll
    for (int im = 0; im < 4; im++)
        #pragma unroll
        for (int in = 0; in < 4; in++)
            #pragma unroll
            for (int j = 0; j < 2; j++) {
                usum[in * 2 + j] += ok0[im] ? __expf(acc[im][in][j]     - umax[in * 2 + j]) : 0.f;
                usum[in * 2 + j] += ok1[im] ? __expf(acc[im][in][2 + j] - umax[in * 2 + j]) : 0.f;
            }
    #pragma unroll
    for (int msk = 4; msk <= 16; msk <<= 1)
        #pragma unroll
        for (int q = 0; q < 8; q++)
            usum[q] += __shfl_xor_sync(0xffffffffu, usum[q], msk);
    if (lane < 4) {
        #pragma unroll
        for (int in = 0; in < 4; in++)
            #pragma unroll
            for (int j = 0; j < 2; j++) {
                int u = n_off + in * 8 + lane * 2 + j;
                smax[wid & 1][u] = umax[in * 2 + j];
                ssum[wid & 1][u] = usum[in * 2 + j];
            }
    }
    __syncthreads();
    if (tid < 128) {
        float m0v = smax[0][tid], m1v = smax[1][tid];
        float M = fmaxf(m0v, m1v);
        float Ssum = (m0v > -3.4e38f ? ssum[0][tid] * __expf(m0v - M) : 0.f)
                   + (m1v > -3.4e38f ? ssum[1][tid] * __expf(m1v - M) : 0.f);
        int idx = (b * 16 + blockIdx.y) * TDEC + n0 + tid;
        g_cm[idx] = M;
        g_cs[idx] = Ssum;
    }

    // ---- last active CTA for (b, n0) folds 16 chunks -> g_Mx / g_Iv
    __syncthreads();
    if (tid == 0) {
        __threadfence();
        s_done = atomicAdd(&g_ctr[b * (TDEC / 128) + blockIdx.x], 1);
    }
    __syncthreads();
    const int nact = (cnt + 127) >> 7;
    if (s_done == nact - 1 && tid < 128) {
        const int u = n0 + tid;
        float M = -3.4e38f;
        #pragma unroll
        for (int c = 0; c < 16; c++) M = fmaxf(M, g_cm[(b * 16 + c) * TDEC + u]);
        float Ssum = 0.f;
        #pragma unroll
        for (int c = 0; c < 16; c++) {
            float cm = g_cm[(b * 16 + c) * TDEC + u];
            Ssum += (cm > -3.4e38f) ? g_cs[(b * 16 + c) * TDEC + u] * __expf(cm - M) : 0.f;
        }
        g_Mx[b * TDEC + u] = M;
        g_Iv[b * TDEC + u] = 1.0f / Ssum;
    }
}

// ---------------------------------------------------------------------------
// softmaxC (row-coalesced): 8 t-rows/block. Masked rows -> S=0 (exact).
// ---------------------------------------------------------------------------
__global__ __launch_bounds__(256) void softmaxC_kernel(
    float* __restrict__ S, const int* __restrict__ mask)
{
    const int b  = blockIdx.y;
    const int t0 = blockIdx.x * 8;
    const int tid = threadIdx.x;

    __shared__ float sM[TDEC], sI[TDEC];
    __shared__ int smk[8], srk[8];
    if (tid < 8) {
        smk[tid] = mask[b * TENC + t0 + tid];
        srk[tid] = g_rank[b * TENC + t0 + tid];
    }
    for (int i = tid; i < TDEC; i += 256) {
        sM[i] = g_Mx[b * TDEC + i];
        sI[i] = g_Iv[b * TDEC + i];
    }
    __syncthreads();

    #pragma unroll
    for (int slot = tid; slot < 1024; slot += 256) {
        int row = slot >> 7;
        int u4  = slot & 127;
        int u   = u4 * 4;
        size_t idx = ((size_t)b * TENC + t0 + row) * TDEC + u;
        if (smk[row]) {
            float4 v = *(float4*)&S[idx];
            v.x = __expf(v.x - sM[u + 0]) * sI[u + 0];
            v.y = __expf(v.y - sM[u + 1]) * sI[u + 1];
            v.z = __expf(v.z - sM[u + 2]) * sI[u + 2];
            v.w = __expf(v.w - sM[u + 3]) * sI[u + 3];
            *(float4*)&S[idx] = v;
            __half2 h01 = {__float2half(v.x), __float2half(v.y)};
            __half2 h23 = {__float2half(v.z), __float2half(v.w)};
            uint2 hv = {*(uint32_t*)&h01, *(uint32_t*)&h23};
            *(uint2*)&g_pc[((size_t)b * TENC + srk[row]) * TDEC + u] = hv;
        } else {
            float4 z = {0.f, 0.f, 0.f, 0.f};
            *(float4*)&S[idx] = z;
        }
    }
}

// ---------------------------------------------------------------------------
// GEMM2 (fp16 single pass, compact K, B = g_eh): BM=128, BN=128, BK=32.
// K runs to cnt32 only. 4-deep ring, 2 CTAs/SM.
// ---------------------------------------------------------------------------
#define G2_BUF   8704             // 32 rows * 272 B
#define G2_STAGE (2 * G2_BUF)     // Pc, Eh
#define G2_DYN   (4 * G2_STAGE + 1024)

__global__ __launch_bounds__(256, 2) void gemm2_kernel(float* __restrict__ ctx)
{
    extern __shared__ __align__(16) uint8_t dynsm[];
    const uint32_t dynb = (smem_u32(dynsm) + 1023u) & ~1023u;

    const int b  = blockIdx.z;
    const int u0 = blockIdx.y * 128;
    const int d0 = blockIdx.x * 128;
    const int cnt = g_cnt[b];
    const int NST = (cnt + 31) >> 5;

    const __half* Pc = g_pc + (size_t)b * TENC * TDEC;
    const __half* Ef = g_eh + (size_t)b * TENC * DIM;
    float* C = ctx + (size_t)b * TDEC * DIM;

    const int tid  = threadIdx.x;
    const int lane = tid & 31;
    const int wid  = tid >> 5;
    const int m_off = (wid & 1) * 64;   // u
    const int n_off = (wid >> 1) * 32;  // d

    const int lrow = tid >> 4;   // 0..15 (+16)
    const int lc   = tid & 15;

    const uint32_t aBase = (uint32_t)(((lane & 7) + ((lane >> 4) << 3)) * 272
                                      + (m_off + ((lane >> 3) & 1) * 8) * 2);
    const uint32_t bBase = (uint32_t)(((lane & 7) + (((lane >> 3) & 1) << 3)) * 272
                                      + (n_off + (lane >> 4) * 8) * 2);

    float acc[4][4][4];
    #pragma unroll
    for (int i = 0; i < 4; i++)
        #pragma unroll
        for (int j = 0; j < 4; j++)
            #pragma unroll
            for (int k = 0; k < 4; k++) acc[i][j][k] = 0.f;

    auto load_stage = [&](int s) {
        const int k0 = s * 32;
        const uint32_t sb = dynb + (uint32_t)(s & 3) * G2_STAGE;
        #pragma unroll
        for (int j = 0; j < 2; j++) {
            int row = lrow + j * 16;
            uint32_t so = (uint32_t)(row * 272 + lc * 16);
            size_t goP = (size_t)(k0 + row) * TDEC + u0 + lc * 8;
            size_t goE = (size_t)(k0 + row) * DIM + d0 + lc * 8;
            cpa16(sb + so,          Pc + goP);
            cpa16(sb + G2_BUF + so, Ef + goE);
        }
        cpa_commit();
    };

    const int pre = NST < 3 ? NST : 3;
    for (int s = 0; s < pre; s++) load_stage(s);

    for (int s = 0; s < NST; s++) {
        int out = NST - s - 1; if (out > 2) out = 2;
        if (out == 2) cpa_wait2();
        else if (out == 1) cpa_wait1();
        else cpa_wait0();
        __syncthreads();

        const uint32_t bPh = dynb + (uint32_t)(s & 3) * G2_STAGE;
        const uint32_t bEf = bPh + G2_BUF;

        #pragma unroll
        for (int ks = 0; ks < 2; ks++) {
            uint32_t koff = (uint32_t)(ks * 16 * 272);
            uint32_t ah[4][4], bh[2][4];
            #pragma unroll
            for (int im = 0; im < 4; im++) ldsm4t(ah[im], bPh + aBase + im * 32 + koff);
            #pragma unroll
            for (int p = 0; p < 2; p++)   ldsm4t(bh[p], bEf + bBase + p * 32 + koff);
            #pragma unroll
            for (int im = 0; im < 4; im++)
                #pragma unroll
                for (int in = 0; in < 4; in++)
                    mma_fp16(acc[im][in], ah[im], bh[in >> 1][(in & 1) * 2], bh[in >> 1][(in & 1) * 2 + 1]);
        }
        if (s + 3 < NST) load_stage(s + 3);
    }

    #pragma unroll
    for (int im = 0; im < 4; im++) {
        int ur = u0 + m_off + im * 16 + (lane >> 2);
        #pragma unroll
        for (int in = 0; in < 4; in++) {
            int col = d0 + n_off + in * 8 + (lane & 3) * 2;
            float2 v0 = {acc[im][in][0], acc[im][in][1]};
            float2 v1 = {acc[im][in][2], acc[im][in][3]};
            *(float2*)&C[(size_t)ur * DIM + col]       = v0;
            *(float2*)&C[(size_t)(ur + 8) * DIM + col] = v1;
        }
    }
}

// ---------------------------------------------------------------------------
extern "C" void kernel_launch(void* const* d_in, const int* in_sizes, int n_in,
                              void* d_out, int out_size)
{
    const float* enc      = (const float*)d_in[0];
    const int*   enc_mask = (const int*)  d_in[1];
    const float* dec      = (const float*)d_in[2];

    float* ctx = (float*)d_out;                      // [B, TDEC, DIM]
    float* S   = ctx + (size_t)BATCH * TDEC * DIM;   // [B, TENC, TDEC]

    cudaFuncSetAttribute(gemm1_kernel, cudaFuncAttributeMaxDynamicSharedMemorySize, G1_DYN);
    cudaFuncSetAttribute(gemm2_kernel, cudaFuncAttributeMaxDynamicSharedMemorySize, G2_DYN);

    compact_kernel<<<BATCH, 1024>>>(enc_mask);
    split_kernel<<<1536, 256>>>(enc, dec, enc_mask);

    gemm1_kernel<<<dim3(TDEC / 128, TENC / 128, BATCH), 256, G1_DYN>>>(S);

    softmaxC_kernel<<<dim3(TENC / 8, BATCH), 256>>>(S, enc_mask);

    gemm2_kernel<<<dim3(DIM / 128, TDEC / 128, BATCH), 256, G2_DYN>>>(ctx);
}